// round 7
// baseline (speedup 1.0000x reference)
#include <cuda_runtime.h>

#define BSZ 1024
#define NAG 64
#define NLK 32
#define NFE 16
#define HD  32
#define MD  32
#define AD  16
#define NPAIR (BSZ*NAG)   // 65536

typedef unsigned long long u64;

// Scratch (static device globals: allocation-free)
__device__ float g_msg[NPAIR*MD];        // per-pair messages
__device__ float g_mean[BSZ*MD];         // per-batch mean message
// Transposed weights (per-output-channel contiguous rows)
__device__ __align__(16) float g_ilwT[32*512];    // [chan][512]
__device__ __align__(16) float g_gwT [32*192];    // [chan][ihr ihz ihn hhr hhz hhn][32]
__device__ __align__(16) float g_mswT[32*32];     // [chan][32]
__device__ __align__(16) float g_mgwT[64*32*32];  // [agent][chan][32]

__device__ __forceinline__ float sigm(float x){ return 1.0f/(1.0f+__expf(-x)); }

// ---- packed f32x2 helpers (sm_103a FFMA2 path) ----
__device__ __forceinline__ u64 f2fma(u64 a, u64 b, u64 c){
    u64 d; asm("fma.rn.f32x2 %0, %1, %2, %3;" : "=l"(d) : "l"(a), "l"(b), "l"(c)); return d;
}
__device__ __forceinline__ u64 f2add(u64 a, u64 b){
    u64 d; asm("add.rn.f32x2 %0, %1, %2;" : "=l"(d) : "l"(a), "l"(b)); return d;
}
__device__ __forceinline__ u64 f2pack(float lo, float hi){
    u64 d; asm("mov.b64 %0, {%1, %2};" : "=l"(d) : "r"(__float_as_uint(lo)), "r"(__float_as_uint(hi)));
    return d;
}
__device__ __forceinline__ float2 f2unpack(u64 d){
    unsigned lo, hi; asm("mov.b64 {%0, %1}, %2;" : "=r"(lo), "=r"(hi) : "l"(d));
    return make_float2(__uint_as_float(lo), __uint_as_float(hi));
}
__device__ __forceinline__ float f2hsum(u64 d){ float2 u = f2unpack(d); return u.x + u.y; }

// ---------------------------------------------------------------------------
// Setup: transpose weights into per-channel contiguous rows (runs per launch,
// deterministic, ~2us).
// ---------------------------------------------------------------------------
__global__ void setup_kernel(const float* __restrict__ il_w,
                             const float* __restrict__ gwih,
                             const float* __restrict__ gwhh,
                             const float* __restrict__ ms_w,
                             const float* __restrict__ mg_w)
{
    const int i = blockIdx.x * 256 + threadIdx.x;   // 65536 threads
    { int a = i >> 10, r = i & 1023, c = r >> 5, k = r & 31;
      g_mgwT[i] = mg_w[a*1024 + k*32 + c]; }
    if (i < 16384){ int c = i >> 9, k = i & 511; g_ilwT[i] = il_w[k*32 + c]; }
    if (i < 6144){ int c = i / 192, r = i % 192, g = r >> 5, k = r & 31;
      g_gwT[i] = (g < 3) ? gwih[k*96 + g*32 + c] : gwhh[k*96 + (g-3)*32 + c]; }
    if (i < 1024){ int c = i >> 5, k = i & 31; g_mswT[i] = ms_w[k*32 + c]; }
}

// ---------------------------------------------------------------------------
// Kernel 1: 1 warp handles TWO pairs (p, p+32768; same agent).
// Broadcast-row projection (wavefront-minimal), FFMA2 everywhere, transposed
// weight rows via LDG.128, broadcast-LDS instead of shuffles in the tail.
// ---------------------------------------------------------------------------
__global__ __launch_bounds__(64) void k1_kernel(
    const float* __restrict__ states, const float* __restrict__ hprev,
    const float* __restrict__ ia_wq, const float* __restrict__ ia_bq,
    const float* __restrict__ ia_wkv, const float* __restrict__ ia_bkv,
    const float* __restrict__ ia_wo, const float* __restrict__ ia_bo,
    const float* __restrict__ ln1_g, const float* __restrict__ ln1_b,
    const float* __restrict__ il_b,
    const float* __restrict__ gbih, const float* __restrict__ gbhh,
    const float* __restrict__ ms_b, const float* __restrict__ mg_b,
    float* __restrict__ out_h)
{
    __shared__ __align__(16) float s_wo[512];
    __shared__ __align__(16) float s_cst[48];          // bo[16], g1[16], b1[16]
    __shared__ __align__(16) float Ss[2][2][32][20];   // [warp][pair][row][20]
    __shared__ __align__(16) float Qs[2][32][36];
    __shared__ __align__(16) float Ks[2][32][32];
    __shared__ __align__(16) float Vs[2][32][32];
    __shared__ __align__(16) float sX[2][4][32];       // enc/h/mb broadcast stash

    const int tid = threadIdx.x;
    for (int i = tid; i < 512; i += 64) s_wo[i] = ia_wo[i];
    if (tid < 16)      s_cst[tid] = ia_bo[tid];
    else if (tid < 32) s_cst[tid] = ln1_g[tid-16];
    else if (tid < 48) s_cst[tid] = ln1_b[tid-32];
    __syncthreads();

    const int w    = tid >> 5;
    const int lane = tid & 31;
    const int pA   = blockIdx.x * 2 + w;       // [0, 32768)
    const int pB   = pA + NPAIR/2;             // same agent
    const int a    = pA & (NAG - 1);

    // --- stage both pairs' states rows ---
    {
        const float4* sa = (const float4*)(states + ((size_t)pA*NLK + lane)*NFE);
        const float4* sb = (const float4*)(states + ((size_t)pB*NLK + lane)*NFE);
        float4* da = (float4*)Ss[w][0][lane];
        float4* db = (float4*)Ss[w][1][lane];
        #pragma unroll
        for (int t = 0; t < 4; t++){ da[t] = sa[t]; db[t] = sb[t]; }
    }

    // --- stationary weight columns, pre-packed f32x2 (lane = output channel) ---
    const float scale = 0.3535533905932738f;   // 1/sqrt(8)
    u64 wq2[8], wk2[8], wv2[8];
    #pragma unroll
    for (int j = 0; j < 8; j++){
        wq2[j] = f2pack(ia_wq [(2*j)*32 + lane]*scale, ia_wq [(2*j+1)*32 + lane]*scale);
        wk2[j] = f2pack(ia_wkv[(2*j)*64 + lane],       ia_wkv[(2*j+1)*64 + lane]);
        wv2[j] = f2pack(ia_wkv[(2*j)*64 + 32 + lane],  ia_wkv[(2*j+1)*64 + 32 + lane]);
    }
    const float bq = ia_bq[lane] * scale;
    const float bk = ia_bkv[lane];
    const float bv = ia_bkv[32 + lane];

    // ================= per-pair attention (sequential, shared buffers) =====
    #pragma unroll 1
    for (int pp = 0; pp < 2; pp++){
        __syncwarp();
        // --- projection: BROADCAST row reads (free), lane = output channel ---
        #pragma unroll 4
        for (int t = 0; t < 32; t++){
            const ulonglong2* rp = (const ulonglong2*)Ss[w][pp][t];   // broadcast
            ulonglong2 rA = rp[0], rB = rp[1], rC = rp[2], rD = rp[3];
            u64 q1 = f2fma(rA.x,wq2[0], f2fma(rA.y,wq2[1], f2fma(rB.x,wq2[2], f2fma(rB.y,wq2[3], 0ull))));
            u64 q2 = f2fma(rC.x,wq2[4], f2fma(rC.y,wq2[5], f2fma(rD.x,wq2[6], f2fma(rD.y,wq2[7], 0ull))));
            u64 k1 = f2fma(rA.x,wk2[0], f2fma(rA.y,wk2[1], f2fma(rB.x,wk2[2], f2fma(rB.y,wk2[3], 0ull))));
            u64 k2 = f2fma(rC.x,wk2[4], f2fma(rC.y,wk2[5], f2fma(rD.x,wk2[6], f2fma(rD.y,wk2[7], 0ull))));
            u64 v1 = f2fma(rA.x,wv2[0], f2fma(rA.y,wv2[1], f2fma(rB.x,wv2[2], f2fma(rB.y,wv2[3], 0ull))));
            u64 v2 = f2fma(rC.x,wv2[4], f2fma(rC.y,wv2[5], f2fma(rD.x,wv2[6], f2fma(rD.y,wv2[7], 0ull))));
            Qs[w][t][lane] = f2hsum(f2add(q1,q2)) + bq;
            Ks[w][t][lane] = f2hsum(f2add(k1,k2)) + bk;
            Vs[w][t][lane] = f2hsum(f2add(v1,v2)) + bv;
        }
        __syncwarp();

        // --- 4-head attention + fused out-projection, packed accumulators ---
        u64 aft2[8];
        {
            const u64* bo2 = (const u64*)s_cst;
            #pragma unroll
            for (int j = 0; j < 8; j++) aft2[j] = bo2[j];
        }

        #pragma unroll
        for (int n = 0; n < 4; n++){
            const ulonglong2* qp = (const ulonglong2*)&Qs[w][lane][n*8];
            ulonglong2 qA = qp[0], qB = qp[1];
            u64 o0=0ull, o1=0ull, o2=0ull, o3=0ull;
            float sum = 0.f;
            #pragma unroll 8
            for (int k = 0; k < 32; k++){
                const ulonglong2* kr = (const ulonglong2*)&Ks[w][k][n*8];   // broadcast
                ulonglong2 ka = kr[0], kb = kr[1];
                u64 s2 = f2fma(qA.x,ka.x, f2fma(qA.y,ka.y, f2fma(qB.x,kb.x, f2fma(qB.y,kb.y, 0ull))));
                float e = __expf(f2hsum(s2));  // no-max softmax: |score| << 1 here
                sum += e;
                u64 e2 = f2pack(e, e);
                const ulonglong2* vr = (const ulonglong2*)&Vs[w][k][n*8];   // broadcast
                ulonglong2 va = vr[0], vb = vr[1];
                o0 = f2fma(e2, va.x, o0); o1 = f2fma(e2, va.y, o1);
                o2 = f2fma(e2, vb.x, o2); o3 = f2fma(e2, vb.y, o3);
            }
            const float inv = 1.0f / sum;
            float2 p0 = f2unpack(o0), p1 = f2unpack(o1), p2 = f2unpack(o2), p3 = f2unpack(o3);
            float od[8] = {p0.x*inv, p0.y*inv, p1.x*inv, p1.y*inv,
                           p2.x*inv, p2.y*inv, p3.x*inv, p3.y*inv};
            #pragma unroll
            for (int d = 0; d < 8; d++){
                u64 od2 = f2pack(od[d], od[d]);
                const ulonglong2* wp = (const ulonglong2*)(s_wo + (n*8+d)*16);  // broadcast
                ulonglong2 wA = wp[0], wB = wp[1], wC = wp[2], wD = wp[3];
                aft2[0] = f2fma(od2, wA.x, aft2[0]); aft2[1] = f2fma(od2, wA.y, aft2[1]);
                aft2[2] = f2fma(od2, wB.x, aft2[2]); aft2[3] = f2fma(od2, wB.y, aft2[3]);
                aft2[4] = f2fma(od2, wC.x, aft2[4]); aft2[5] = f2fma(od2, wC.y, aft2[5]);
                aft2[6] = f2fma(od2, wD.x, aft2[6]); aft2[7] = f2fma(od2, wD.y, aft2[7]);
            }
        }

        // --- unpack, residual (re-read own states row), LayerNorm ---
        float aft[16];
        #pragma unroll
        for (int j = 0; j < 8; j++){
            float2 u = f2unpack(aft2[j]);
            aft[2*j] = u.x; aft[2*j+1] = u.y;
        }
        {
            const float4* srp = (const float4*)Ss[w][pp][lane];
            float4 s0 = srp[0], s1 = srp[1], s2 = srp[2], s3 = srp[3];
            aft[0]+=s0.x; aft[1]+=s0.y; aft[2]+=s0.z; aft[3]+=s0.w;
            aft[4]+=s1.x; aft[5]+=s1.y; aft[6]+=s1.z; aft[7]+=s1.w;
            aft[8]+=s2.x; aft[9]+=s2.y; aft[10]+=s2.z; aft[11]+=s2.w;
            aft[12]+=s3.x; aft[13]+=s3.y; aft[14]+=s3.z; aft[15]+=s3.w;
        }
        float mean = 0.f;
        #pragma unroll
        for (int f = 0; f < 16; f++) mean += aft[f];
        mean *= 0.0625f;
        float var = 0.f;
        #pragma unroll
        for (int f = 0; f < 16; f++){ float d = aft[f]-mean; var = fmaf(d,d,var); }
        var *= 0.0625f;
        float rstd = rsqrtf(var + 1e-5f);
        #pragma unroll
        for (int f = 0; f < 16; f++)
            aft[f] = (aft[f]-mean)*rstd*s_cst[16+f] + s_cst[32+f];

        __syncwarp();
        {
            float4* dst = (float4*)Ss[w][pp][lane];    // overwrite states with aft
            dst[0] = make_float4(aft[0],aft[1],aft[2],aft[3]);
            dst[1] = make_float4(aft[4],aft[5],aft[6],aft[7]);
            dst[2] = make_float4(aft[8],aft[9],aft[10],aft[11]);
            dst[3] = make_float4(aft[12],aft[13],aft[14],aft[15]);
        }
    }
    __syncwarp();

    // ================= joint tail (transposed weights, FFMA2) ==============
    // enc = aft_flat(512) . ilwT[lane][:]
    u64 eaccA0=0ull, eaccA1=0ull, eaccB0=0ull, eaccB1=0ull;
    {
        const ulonglong2* wrow = (const ulonglong2*)(g_ilwT + lane*512);
        #pragma unroll 4
        for (int l = 0; l < 32; l++){
            const ulonglong2* ap = (const ulonglong2*)Ss[w][0][l];   // broadcast
            const ulonglong2* bp = (const ulonglong2*)Ss[w][1][l];
            ulonglong2 a0=ap[0], a1=ap[1], a2=ap[2], a3=ap[3];
            ulonglong2 b0=bp[0], b1=bp[1], b2=bp[2], b3=bp[3];
            ulonglong2 w0=wrow[l*4+0], w1=wrow[l*4+1], w2=wrow[l*4+2], w3=wrow[l*4+3];
            eaccA0 = f2fma(a0.x,w0.x, f2fma(a0.y,w0.y, eaccA0));
            eaccA1 = f2fma(a1.x,w1.x, f2fma(a1.y,w1.y, eaccA1));
            eaccA0 = f2fma(a2.x,w2.x, f2fma(a2.y,w2.y, eaccA0));
            eaccA1 = f2fma(a3.x,w3.x, f2fma(a3.y,w3.y, eaccA1));
            eaccB0 = f2fma(b0.x,w0.x, f2fma(b0.y,w0.y, eaccB0));
            eaccB1 = f2fma(b1.x,w1.x, f2fma(b1.y,w1.y, eaccB1));
            eaccB0 = f2fma(b2.x,w2.x, f2fma(b2.y,w2.y, eaccB0));
            eaccB1 = f2fma(b3.x,w3.x, f2fma(b3.y,w3.y, eaccB1));
        }
    }
    float encA = f2hsum(f2add(eaccA0, eaccA1)) + il_b[lane];
    float encB = f2hsum(f2add(eaccB0, eaccB1)) + il_b[lane];

    // GRU: stash enc/h, broadcast-LDS + transposed packed weights
    float hpA = hprev[(size_t)pA*HD + lane];
    float hpB = hprev[(size_t)pB*HD + lane];
    __syncwarp();
    sX[w][0][lane] = encA;  sX[w][1][lane] = encB;
    sX[w][2][lane] = hpA;   sX[w][3][lane] = hpB;
    __syncwarp();

    u64 iRA=0ull,iZA=0ull,iNA=0ull,hRA=0ull,hZA=0ull,hNA=0ull;
    u64 iRB=0ull,iZB=0ull,iNB=0ull,hRB=0ull,hZB=0ull,hNB=0ull;
    {
        const ulonglong2* grow = (const ulonglong2*)(g_gwT + lane*192);
        const ulonglong2* pe0 = (const ulonglong2*)sX[w][0];
        const ulonglong2* pe1 = (const ulonglong2*)sX[w][1];
        const ulonglong2* ph0 = (const ulonglong2*)sX[w][2];
        const ulonglong2* ph1 = (const ulonglong2*)sX[w][3];
        #pragma unroll
        for (int c = 0; c < 8; c++){
            ulonglong2 eA = pe0[c], eB = pe1[c], hA = ph0[c], hB = ph1[c];  // broadcast
            ulonglong2 wir = grow[c],    wiz = grow[8+c],  win = grow[16+c];
            ulonglong2 whr = grow[24+c], whz = grow[32+c], whn = grow[40+c];
            iRA = f2fma(eA.x,wir.x, f2fma(eA.y,wir.y, iRA));
            iZA = f2fma(eA.x,wiz.x, f2fma(eA.y,wiz.y, iZA));
            iNA = f2fma(eA.x,win.x, f2fma(eA.y,win.y, iNA));
            hRA = f2fma(hA.x,whr.x, f2fma(hA.y,whr.y, hRA));
            hZA = f2fma(hA.x,whz.x, f2fma(hA.y,whz.y, hZA));
            hNA = f2fma(hA.x,whn.x, f2fma(hA.y,whn.y, hNA));
            iRB = f2fma(eB.x,wir.x, f2fma(eB.y,wir.y, iRB));
            iZB = f2fma(eB.x,wiz.x, f2fma(eB.y,wiz.y, iZB));
            iNB = f2fma(eB.x,win.x, f2fma(eB.y,win.y, iNB));
            hRB = f2fma(hB.x,whr.x, f2fma(hB.y,whr.y, hRB));
            hZB = f2fma(hB.x,whz.x, f2fma(hB.y,whz.y, hZB));
            hNB = f2fma(hB.x,whn.x, f2fma(hB.y,whn.y, hNB));
        }
    }
    float rA = sigm(f2hsum(iRA) + gbih[lane]      + f2hsum(hRA) + gbhh[lane]);
    float zA = sigm(f2hsum(iZA) + gbih[32+lane]   + f2hsum(hZA) + gbhh[32+lane]);
    float nAv= tanhf(f2hsum(iNA) + gbih[64+lane]  + rA*(f2hsum(hNA) + gbhh[64+lane]));
    float rB = sigm(f2hsum(iRB) + gbih[lane]      + f2hsum(hRB) + gbhh[lane]);
    float zB = sigm(f2hsum(iZB) + gbih[32+lane]   + f2hsum(hZB) + gbhh[32+lane]);
    float nBv= tanhf(f2hsum(iNB) + gbih[64+lane]  + rB*(f2hsum(hNB) + gbhh[64+lane]));
    float hnA = (1.0f - zA)*nAv + zA*hpA;
    float hnB = (1.0f - zB)*nBv + zB*hpB;
    out_h[(size_t)pA*HD + lane] = hnA;
    out_h[(size_t)pB*HD + lane] = hnB;

    // message embedding: stash h, transposed ms weights
    __syncwarp();
    sX[w][0][lane] = hnA; sX[w][1][lane] = hnB;
    __syncwarp();
    u64 mA2=0ull, mB2=0ull;
    {
        const ulonglong2* msr = (const ulonglong2*)(g_mswT + lane*32);
        const ulonglong2* pa = (const ulonglong2*)sX[w][0];
        const ulonglong2* pb = (const ulonglong2*)sX[w][1];
        #pragma unroll
        for (int c = 0; c < 8; c++){
            ulonglong2 hA = pa[c], hB = pb[c];     // broadcast
            ulonglong2 ww = msr[c];
            mA2 = f2fma(hA.x,ww.x, f2fma(hA.y,ww.y, mA2));
            mB2 = f2fma(hB.x,ww.x, f2fma(hB.y,ww.y, mB2));
        }
    }
    float mbA = fmaxf(f2hsum(mA2) + ms_b[lane], 0.f);
    float mbB = fmaxf(f2hsum(mB2) + ms_b[lane], 0.f);

    // per-agent message generator (same agent both pairs)
    __syncwarp();
    sX[w][2][lane] = mbA; sX[w][3][lane] = mbB;
    __syncwarp();
    u64 gA2=0ull, gB2=0ull;
    {
        const ulonglong2* mgr = (const ulonglong2*)(g_mgwT + (size_t)a*1024 + lane*32);
        const ulonglong2* pa = (const ulonglong2*)sX[w][2];
        const ulonglong2* pb = (const ulonglong2*)sX[w][3];
        #pragma unroll
        for (int c = 0; c < 8; c++){
            ulonglong2 mA = pa[c], mB = pb[c];     // broadcast
            ulonglong2 ww = mgr[c];
            gA2 = f2fma(mA.x,ww.x, f2fma(mA.y,ww.y, gA2));
            gB2 = f2fma(mB.x,ww.x, f2fma(mB.y,ww.y, gB2));
        }
    }
    g_msg[(size_t)pA*MD + lane] = f2hsum(gA2) + mg_b[a*32 + lane];
    g_msg[(size_t)pB*MD + lane] = f2hsum(gB2) + mg_b[a*32 + lane];
}

// ---------------------------------------------------------------------------
// Kernel 2: deterministic per-batch mean over agents; broadcast to out_mm.
// ---------------------------------------------------------------------------
__global__ void k2_kernel(float* __restrict__ out_mm)
{
    const int b = blockIdx.x;
    const int m = threadIdx.x;                    // 32 threads
    const float* base = g_msg + (size_t)b*NAG*MD + m;
    float sum = 0.f;
    #pragma unroll 8
    for (int a = 0; a < NAG; a++) sum += base[a*MD];
    float mean = sum * (1.0f/64.0f);
    g_mean[b*MD + m] = mean;
    float* ob = out_mm + (size_t)b*NAG*MD + m;
    #pragma unroll 8
    for (int a = 0; a < NAG; a++) ob[a*MD] = mean;
}

// ---------------------------------------------------------------------------
// Kernel 3: comm attention (seqlen-1 softmax == 1 -> only V path), LN2,
// q-head. 1 warp handles TWO pairs with the SAME agent (p, p+32768).
// ---------------------------------------------------------------------------
__global__ __launch_bounds__(128) void k3_kernel(
    const float* __restrict__ hbuf,
    const float* __restrict__ ma_wkv, const float* __restrict__ ma_bkv,
    const float* __restrict__ ma_wo,  const float* __restrict__ ma_bo,
    const float* __restrict__ ln2_g,  const float* __restrict__ ln2_b,
    const float* __restrict__ qs_w,   const float* __restrict__ qs_b,
    const float* __restrict__ ah_w,   const float* __restrict__ ah_b,
    float* __restrict__ out_q)
{
    const int tid  = threadIdx.x;
    const int w    = tid >> 5;
    const int lane = tid & 31;
    const int idx  = blockIdx.x * 4 + w;          // 0..32767
    const int p0   = idx;
    const int p1   = idx + NPAIR/2;               // same agent
    const int b0   = p0 >> 6;
    const int b1   = p1 >> 6;
    const int a    = p0 & (NAG - 1);

    float h0 = hbuf[(size_t)p0*HD + lane];
    float h1 = hbuf[(size_t)p1*HD + lane];
    float m0 = g_mean[b0*MD + lane];
    float m1 = g_mean[b1*MD + lane];

    // V = mean_msg @ ma_wkv[:,32:64] + ma_bkv[32:]
    float V0 = ma_bkv[32 + lane], V1 = V0;
    #pragma unroll 4
    for (int k = 0; k < 32; k++){
        float ww = ma_wkv[k*64 + 32 + lane];
        V0 = fmaf(__shfl_sync(0xffffffffu, m0, k), ww, V0);
        V1 = fmaf(__shfl_sync(0xffffffffu, m1, k), ww, V1);
    }
    // after = V @ ma_wo + ma_bo
    float af0 = ma_bo[lane], af1 = af0;
    #pragma unroll 4
    for (int k = 0; k < 32; k++){
        float ww = ma_wo[k*32 + lane];
        af0 = fmaf(__shfl_sync(0xffffffffu, V0, k), ww, af0);
        af1 = fmaf(__shfl_sync(0xffffffffu, V1, k), ww, af1);
    }
    // LN2(h + after), both pairs
    float g2 = ln2_g[lane], bb2 = ln2_b[lane];
    float x0 = h0 + af0, x1 = h1 + af1;
    float t0 = x0, t1 = x1;
    #pragma unroll
    for (int off = 16; off > 0; off >>= 1){
        t0 += __shfl_xor_sync(0xffffffffu, t0, off);
        t1 += __shfl_xor_sync(0xffffffffu, t1, off);
    }
    float mu0 = t0 * (1.0f/32.0f), mu1 = t1 * (1.0f/32.0f);
    float d0 = x0 - mu0, d1 = x1 - mu1;
    float v0 = d0*d0, v1 = d1*d1;
    #pragma unroll
    for (int off = 16; off > 0; off >>= 1){
        v0 += __shfl_xor_sync(0xffffffffu, v0, off);
        v1 += __shfl_xor_sync(0xffffffffu, v1, off);
    }
    float an0 = d0 * rsqrtf(v0*(1.0f/32.0f) + 1e-5f) * g2 + bb2;
    float an1 = d1 * rsqrtf(v1*(1.0f/32.0f) + 1e-5f) * g2 + bb2;

    // qemb = relu([h, after_ln] @ qs_w + qs_b)
    float qe0 = qs_b[lane], qe1 = qe0;
    #pragma unroll 4
    for (int k = 0; k < 32; k++){
        float w0 = qs_w[k*32 + lane];
        float w1 = qs_w[(32+k)*32 + lane];
        qe0 = fmaf(__shfl_sync(0xffffffffu, h0, k),  w0, qe0);
        qe0 = fmaf(__shfl_sync(0xffffffffu, an0, k), w1, qe0);
        qe1 = fmaf(__shfl_sync(0xffffffffu, h1, k),  w0, qe1);
        qe1 = fmaf(__shfl_sync(0xffffffffu, an1, k), w1, qe1);
    }
    qe0 = fmaxf(qe0, 0.f);
    qe1 = fmaxf(qe1, 0.f);

    // q = qemb @ ah_w[a] + ah_b[a]   (lanes 0..15 hold the 16 actions)
    float qa0 = 0.f, qa1 = 0.f;
    if (lane < 16){ qa0 = ah_b[a*16 + lane]; qa1 = qa0; }
    const float* aw = ah_w + (size_t)a*512;
    #pragma unroll 4
    for (int k = 0; k < 32; k++){
        float ww = (lane < 16) ? aw[k*16 + lane] : 0.f;
        qa0 = fmaf(__shfl_sync(0xffffffffu, qe0, k), ww, qa0);
        qa1 = fmaf(__shfl_sync(0xffffffffu, qe1, k), ww, qa1);
    }
    if (lane < 16){
        out_q[(size_t)p0*AD + lane] = qa0;
        out_q[(size_t)p1*AD + lane] = qa1;
    }
}

// ---------------------------------------------------------------------------
extern "C" void kernel_launch(void* const* d_in, const int* in_sizes, int n_in,
                              void* d_out, int out_size)
{
    const float* states = (const float*)d_in[0];
    const float* hidden = (const float*)d_in[1];
    const float* ia_wq  = (const float*)d_in[2];
    const float* ia_bq  = (const float*)d_in[3];
    const float* ia_wkv = (const float*)d_in[4];
    const float* ia_bkv = (const float*)d_in[5];
    const float* ia_wo  = (const float*)d_in[6];
    const float* ia_bo  = (const float*)d_in[7];
    const float* ln1_g  = (const float*)d_in[8];
    const float* ln1_b  = (const float*)d_in[9];
    const float* il_w   = (const float*)d_in[10];
    const float* il_b   = (const float*)d_in[11];
    const float* gwih   = (const float*)d_in[12];
    const float* gwhh   = (const float*)d_in[13];
    const float* gbih   = (const float*)d_in[14];
    const float* gbhh   = (const float*)d_in[15];
    const float* ms_w   = (const float*)d_in[16];
    const float* ms_b   = (const float*)d_in[17];
    const float* mg_w   = (const float*)d_in[18];
    const float* mg_b   = (const float*)d_in[19];
    // d_in[20] = ma_wq, d_in[21] = ma_bq: eliminated (seqlen-1 softmax == 1)
    const float* ma_wkv = (const float*)d_in[22];
    const float* ma_bkv = (const float*)d_in[23];
    const float* ma_wo  = (const float*)d_in[24];
    const float* ma_bo  = (const float*)d_in[25];
    const float* ln2_g  = (const float*)d_in[26];
    const float* ln2_b  = (const float*)d_in[27];
    const float* qs_w   = (const float*)d_in[28];
    const float* qs_b   = (const float*)d_in[29];
    const float* ah_w   = (const float*)d_in[30];
    const float* ah_b   = (const float*)d_in[31];

    float* out    = (float*)d_out;
    float* out_q  = out;                                        // [NPAIR,16]
    float* out_h  = out + (size_t)NPAIR*AD;                     // [NPAIR,32]
    float* out_mm = out + (size_t)NPAIR*AD + (size_t)NPAIR*HD;  // [NPAIR,32]

    setup_kernel<<<256, 256>>>(il_w, gwih, gwhh, ms_w, mg_w);
    k1_kernel<<<NPAIR/4, 64>>>(states, hidden, ia_wq, ia_bq, ia_wkv, ia_bkv,
                               ia_wo, ia_bo, ln1_g, ln1_b, il_b,
                               gbih, gbhh, ms_b, mg_b, out_h);
    k2_kernel<<<BSZ, 32>>>(out_mm);
    k3_kernel<<<NPAIR/8, 128>>>(out_h, ma_wkv, ma_bkv, ma_wo, ma_bo,
                                ln2_g, ln2_b, qs_w, qs_b, ah_w, ah_b, out_q);
}

// round 8
// speedup vs baseline: 1.7041x; 1.7041x over previous
#include <cuda_runtime.h>

#define BSZ 1024
#define NAG 64
#define NLK 32
#define NFE 16
#define HD  32
#define MD  32
#define AD  16
#define NPAIR (BSZ*NAG)   // 65536

typedef unsigned long long u64;

// Scratch (static device globals: allocation-free)
__device__ float g_msg[NPAIR*MD];   // per-pair messages
__device__ float g_mean[BSZ*MD];    // per-batch mean message

__device__ __forceinline__ float sigm(float x){ return 1.0f/(1.0f+__expf(-x)); }

// ---- packed f32x2 helpers (sm_103a FFMA2 path) ----
__device__ __forceinline__ u64 f2fma(u64 a, u64 b, u64 c){
    u64 d; asm("fma.rn.f32x2 %0, %1, %2, %3;" : "=l"(d) : "l"(a), "l"(b), "l"(c)); return d;
}
__device__ __forceinline__ u64 f2add(u64 a, u64 b){
    u64 d; asm("add.rn.f32x2 %0, %1, %2;" : "=l"(d) : "l"(a), "l"(b)); return d;
}
__device__ __forceinline__ u64 f2pack(float lo, float hi){
    u64 d; asm("mov.b64 %0, {%1, %2};" : "=l"(d) : "r"(__float_as_uint(lo)), "r"(__float_as_uint(hi)));
    return d;
}
__device__ __forceinline__ float2 f2unpack(u64 d){
    unsigned lo, hi; asm("mov.b64 {%0, %1}, %2;" : "=r"(lo), "=r"(hi) : "l"(d));
    return make_float2(__uint_as_float(lo), __uint_as_float(hi));
}
__device__ __forceinline__ float f2hsum(u64 d){ float2 u = f2unpack(d); return u.x + u.y; }

// ---------------------------------------------------------------------------
// Kernel 1: 1 warp handles TWO pairs (p, p+32768; same agent).
// Projection uses BROADCAST row reads (1 wavefront per LDS.128 vs 4 for
// distinct-address reads) with lane = output channel. Attention phases
// sequential (shared Q/K/V smem); tail joint with COALESCED scalar weight
// LDGs (32 lanes x 4B contiguous = 1 line per instruction).
// ---------------------------------------------------------------------------
__global__ __launch_bounds__(64, 6) void k1_kernel(
    const float* __restrict__ states, const float* __restrict__ hprev,
    const float* __restrict__ ia_wq, const float* __restrict__ ia_bq,
    const float* __restrict__ ia_wkv, const float* __restrict__ ia_bkv,
    const float* __restrict__ ia_wo, const float* __restrict__ ia_bo,
    const float* __restrict__ ln1_g, const float* __restrict__ ln1_b,
    const float* __restrict__ il_w, const float* __restrict__ il_b,
    const float* __restrict__ gwih, const float* __restrict__ gwhh,
    const float* __restrict__ gbih, const float* __restrict__ gbhh,
    const float* __restrict__ ms_w, const float* __restrict__ ms_b,
    const float* __restrict__ mg_w, const float* __restrict__ mg_b,
    float* __restrict__ out_h)
{
    __shared__ __align__(16) float s_wo[512];
    __shared__ __align__(16) float s_cst[48];          // bo[16], g1[16], b1[16]
    __shared__ __align__(16) float Ss[2][2][32][20];   // [warp][pair][row][20]
    __shared__ __align__(16) float Qs[2][32][36];
    __shared__ __align__(16) float Ks[2][32][32];
    __shared__ __align__(16) float Vs[2][32][32];

    const int tid = threadIdx.x;
    for (int i = tid; i < 512; i += 64) s_wo[i] = ia_wo[i];
    if (tid < 16)      s_cst[tid] = ia_bo[tid];
    else if (tid < 32) s_cst[tid] = ln1_g[tid-16];
    else if (tid < 48) s_cst[tid] = ln1_b[tid-32];
    __syncthreads();

    const int w    = tid >> 5;
    const int lane = tid & 31;
    const int pA   = blockIdx.x * 2 + w;       // [0, 32768)
    const int pB   = pA + NPAIR/2;             // same agent
    const int a    = pA & (NAG - 1);

    // --- stage both pairs' states rows ---
    {
        const float4* sa = (const float4*)(states + ((size_t)pA*NLK + lane)*NFE);
        const float4* sb = (const float4*)(states + ((size_t)pB*NLK + lane)*NFE);
        float4* da = (float4*)Ss[w][0][lane];
        float4* db = (float4*)Ss[w][1][lane];
        #pragma unroll
        for (int t = 0; t < 4; t++){ da[t] = sa[t]; db[t] = sb[t]; }
    }

    // --- stationary weight columns, pre-packed f32x2 (lane = output channel) ---
    const float scale = 0.3535533905932738f;   // 1/sqrt(8)
    u64 wq2[8], wk2[8], wv2[8];
    #pragma unroll
    for (int j = 0; j < 8; j++){
        wq2[j] = f2pack(ia_wq [(2*j)*32 + lane]*scale, ia_wq [(2*j+1)*32 + lane]*scale);
        wk2[j] = f2pack(ia_wkv[(2*j)*64 + lane],       ia_wkv[(2*j+1)*64 + lane]);
        wv2[j] = f2pack(ia_wkv[(2*j)*64 + 32 + lane],  ia_wkv[(2*j+1)*64 + 32 + lane]);
    }
    const float bq = ia_bq[lane] * scale;
    const float bk = ia_bkv[lane];
    const float bv = ia_bkv[32 + lane];

    // ================= per-pair attention (sequential, shared buffers) =====
    #pragma unroll 1
    for (int pp = 0; pp < 2; pp++){
        __syncwarp();
        // --- projection: BROADCAST row reads (1 wf each), lane = out channel ---
        #pragma unroll 4
        for (int t = 0; t < 32; t++){
            const ulonglong2* rp = (const ulonglong2*)Ss[w][pp][t];   // broadcast
            ulonglong2 rA = rp[0], rB = rp[1], rC = rp[2], rD = rp[3];
            u64 q1 = f2fma(rA.x,wq2[0], f2fma(rA.y,wq2[1], f2fma(rB.x,wq2[2], f2fma(rB.y,wq2[3], 0ull))));
            u64 q2 = f2fma(rC.x,wq2[4], f2fma(rC.y,wq2[5], f2fma(rD.x,wq2[6], f2fma(rD.y,wq2[7], 0ull))));
            u64 k1 = f2fma(rA.x,wk2[0], f2fma(rA.y,wk2[1], f2fma(rB.x,wk2[2], f2fma(rB.y,wk2[3], 0ull))));
            u64 k2 = f2fma(rC.x,wk2[4], f2fma(rC.y,wk2[5], f2fma(rD.x,wk2[6], f2fma(rD.y,wk2[7], 0ull))));
            u64 v1 = f2fma(rA.x,wv2[0], f2fma(rA.y,wv2[1], f2fma(rB.x,wv2[2], f2fma(rB.y,wv2[3], 0ull))));
            u64 v2 = f2fma(rC.x,wv2[4], f2fma(rC.y,wv2[5], f2fma(rD.x,wv2[6], f2fma(rD.y,wv2[7], 0ull))));
            Qs[w][t][lane] = f2hsum(f2add(q1,q2)) + bq;
            Ks[w][t][lane] = f2hsum(f2add(k1,k2)) + bk;
            Vs[w][t][lane] = f2hsum(f2add(v1,v2)) + bv;
        }
        __syncwarp();

        // --- 4-head attention + fused out-projection, packed accumulators ---
        u64 aft2[8];
        {
            const u64* bo2 = (const u64*)s_cst;
            #pragma unroll
            for (int j = 0; j < 8; j++) aft2[j] = bo2[j];
        }

        #pragma unroll
        for (int n = 0; n < 4; n++){
            const ulonglong2* qp = (const ulonglong2*)&Qs[w][lane][n*8];
            ulonglong2 qA = qp[0], qB = qp[1];
            u64 o0=0ull, o1=0ull, o2=0ull, o3=0ull;
            float sum = 0.f;
            #pragma unroll 8
            for (int k = 0; k < 32; k++){
                const ulonglong2* kr = (const ulonglong2*)&Ks[w][k][n*8];   // broadcast
                ulonglong2 ka = kr[0], kb = kr[1];
                u64 s2 = f2fma(qA.x,ka.x, f2fma(qA.y,ka.y, f2fma(qB.x,kb.x, f2fma(qB.y,kb.y, 0ull))));
                float e = __expf(f2hsum(s2));  // no-max softmax: |score| << 1 here
                sum += e;
                u64 e2 = f2pack(e, e);
                const ulonglong2* vr = (const ulonglong2*)&Vs[w][k][n*8];   // broadcast
                ulonglong2 va = vr[0], vb = vr[1];
                o0 = f2fma(e2, va.x, o0); o1 = f2fma(e2, va.y, o1);
                o2 = f2fma(e2, vb.x, o2); o3 = f2fma(e2, vb.y, o3);
            }
            const float inv = 1.0f / sum;
            float2 p0 = f2unpack(o0), p1 = f2unpack(o1), p2 = f2unpack(o2), p3 = f2unpack(o3);
            float od[8] = {p0.x*inv, p0.y*inv, p1.x*inv, p1.y*inv,
                           p2.x*inv, p2.y*inv, p3.x*inv, p3.y*inv};
            #pragma unroll
            for (int d = 0; d < 8; d++){
                u64 od2 = f2pack(od[d], od[d]);
                const ulonglong2* wp = (const ulonglong2*)(s_wo + (n*8+d)*16);  // broadcast
                ulonglong2 wA = wp[0], wB = wp[1], wC = wp[2], wD = wp[3];
                aft2[0] = f2fma(od2, wA.x, aft2[0]); aft2[1] = f2fma(od2, wA.y, aft2[1]);
                aft2[2] = f2fma(od2, wB.x, aft2[2]); aft2[3] = f2fma(od2, wB.y, aft2[3]);
                aft2[4] = f2fma(od2, wC.x, aft2[4]); aft2[5] = f2fma(od2, wC.y, aft2[5]);
                aft2[6] = f2fma(od2, wD.x, aft2[6]); aft2[7] = f2fma(od2, wD.y, aft2[7]);
            }
        }

        // --- unpack, residual (re-read own states row), LayerNorm ---
        float aft[16];
        #pragma unroll
        for (int j = 0; j < 8; j++){
            float2 u = f2unpack(aft2[j]);
            aft[2*j] = u.x; aft[2*j+1] = u.y;
        }
        {
            const float4* srp = (const float4*)Ss[w][pp][lane];
            float4 s0 = srp[0], s1 = srp[1], s2 = srp[2], s3 = srp[3];
            aft[0]+=s0.x; aft[1]+=s0.y; aft[2]+=s0.z; aft[3]+=s0.w;
            aft[4]+=s1.x; aft[5]+=s1.y; aft[6]+=s1.z; aft[7]+=s1.w;
            aft[8]+=s2.x; aft[9]+=s2.y; aft[10]+=s2.z; aft[11]+=s2.w;
            aft[12]+=s3.x; aft[13]+=s3.y; aft[14]+=s3.z; aft[15]+=s3.w;
        }
        float mean = 0.f;
        #pragma unroll
        for (int f = 0; f < 16; f++) mean += aft[f];
        mean *= 0.0625f;
        float var = 0.f;
        #pragma unroll
        for (int f = 0; f < 16; f++){ float d = aft[f]-mean; var = fmaf(d,d,var); }
        var *= 0.0625f;
        float rstd = rsqrtf(var + 1e-5f);
        #pragma unroll
        for (int f = 0; f < 16; f++)
            aft[f] = (aft[f]-mean)*rstd*s_cst[16+f] + s_cst[32+f];

        __syncwarp();
        {
            float4* dst = (float4*)Ss[w][pp][lane];    // overwrite states with aft
            dst[0] = make_float4(aft[0],aft[1],aft[2],aft[3]);
            dst[1] = make_float4(aft[4],aft[5],aft[6],aft[7]);
            dst[2] = make_float4(aft[8],aft[9],aft[10],aft[11]);
            dst[3] = make_float4(aft[12],aft[13],aft[14],aft[15]);
        }
    }
    __syncwarp();

    // ================= joint tail: coalesced weight LDG feeds BOTH pairs ===
    // enc = aft_flat(512) . il_w[:,lane]
    float encA = il_b[lane], encB = encA;
    #pragma unroll 4
    for (int l = 0; l < 32; l++){
        const float4* ap = (const float4*)Ss[w][0][l];   // broadcast
        const float4* bp = (const float4*)Ss[w][1][l];
        float4 a0=ap[0], a1=ap[1], a2=ap[2], a3=ap[3];
        float4 b0=bp[0], b1=bp[1], b2=bp[2], b3=bp[3];
        const float* wp = il_w + (size_t)(l*16)*32 + lane;
        float t;
        t=wp[0*32];  encA=fmaf(a0.x,t,encA); encB=fmaf(b0.x,t,encB);
        t=wp[1*32];  encA=fmaf(a0.y,t,encA); encB=fmaf(b0.y,t,encB);
        t=wp[2*32];  encA=fmaf(a0.z,t,encA); encB=fmaf(b0.z,t,encB);
        t=wp[3*32];  encA=fmaf(a0.w,t,encA); encB=fmaf(b0.w,t,encB);
        t=wp[4*32];  encA=fmaf(a1.x,t,encA); encB=fmaf(b1.x,t,encB);
        t=wp[5*32];  encA=fmaf(a1.y,t,encA); encB=fmaf(b1.y,t,encB);
        t=wp[6*32];  encA=fmaf(a1.z,t,encA); encB=fmaf(b1.z,t,encB);
        t=wp[7*32];  encA=fmaf(a1.w,t,encA); encB=fmaf(b1.w,t,encB);
        t=wp[8*32];  encA=fmaf(a2.x,t,encA); encB=fmaf(b2.x,t,encB);
        t=wp[9*32];  encA=fmaf(a2.y,t,encA); encB=fmaf(b2.y,t,encB);
        t=wp[10*32]; encA=fmaf(a2.z,t,encA); encB=fmaf(b2.z,t,encB);
        t=wp[11*32]; encA=fmaf(a2.w,t,encA); encB=fmaf(b2.w,t,encB);
        t=wp[12*32]; encA=fmaf(a3.x,t,encA); encB=fmaf(b3.x,t,encB);
        t=wp[13*32]; encA=fmaf(a3.y,t,encA); encB=fmaf(b3.y,t,encB);
        t=wp[14*32]; encA=fmaf(a3.z,t,encA); encB=fmaf(b3.z,t,encB);
        t=wp[15*32]; encA=fmaf(a3.w,t,encA); encB=fmaf(b3.w,t,encB);
    }

    // GRU (gate order r,z,n); lane owns output channel
    float hpA = hprev[(size_t)pA*HD + lane];
    float hpB = hprev[(size_t)pB*HD + lane];
    float giA0 = gbih[lane], giA1 = gbih[32+lane], giA2 = gbih[64+lane];
    float ghA0 = gbhh[lane], ghA1 = gbhh[32+lane], ghA2 = gbhh[64+lane];
    float giB0 = giA0, giB1 = giA1, giB2 = giA2;
    float ghB0 = ghA0, ghB1 = ghA1, ghB2 = ghA2;
    #pragma unroll 4
    for (int k = 0; k < 32; k++){
        float eA = __shfl_sync(0xffffffffu, encA, k);
        float eB = __shfl_sync(0xffffffffu, encB, k);
        float hA = __shfl_sync(0xffffffffu, hpA,  k);
        float hB = __shfl_sync(0xffffffffu, hpB,  k);
        const float* wi = gwih + k*96 + lane;
        const float* wh = gwhh + k*96 + lane;
        float wi0 = wi[0], wi1 = wi[32], wi2 = wi[64];
        float wh0 = wh[0], wh1 = wh[32], wh2 = wh[64];
        giA0=fmaf(eA,wi0,giA0); giB0=fmaf(eB,wi0,giB0);
        giA1=fmaf(eA,wi1,giA1); giB1=fmaf(eB,wi1,giB1);
        giA2=fmaf(eA,wi2,giA2); giB2=fmaf(eB,wi2,giB2);
        ghA0=fmaf(hA,wh0,ghA0); ghB0=fmaf(hB,wh0,ghB0);
        ghA1=fmaf(hA,wh1,ghA1); ghB1=fmaf(hB,wh1,ghB1);
        ghA2=fmaf(hA,wh2,ghA2); ghB2=fmaf(hB,wh2,ghB2);
    }
    float rA = sigm(giA0 + ghA0), rB = sigm(giB0 + ghB0);
    float zA = sigm(giA1 + ghA1), zB = sigm(giB1 + ghB1);
    float nA = tanhf(giA2 + rA*ghA2), nB = tanhf(giB2 + rB*ghB2);
    float hnA = (1.0f - zA)*nA + zA*hpA;
    float hnB = (1.0f - zB)*nB + zB*hpB;
    out_h[(size_t)pA*HD + lane] = hnA;
    out_h[(size_t)pB*HD + lane] = hnB;

    // message embedding (shared ms_w loads)
    float mbA = ms_b[lane], mbB = mbA;
    #pragma unroll 4
    for (int k = 0; k < 32; k++){
        float hA = __shfl_sync(0xffffffffu, hnA, k);
        float hB = __shfl_sync(0xffffffffu, hnB, k);
        float t = ms_w[k*32 + lane];
        mbA = fmaf(hA, t, mbA);
        mbB = fmaf(hB, t, mbB);
    }
    mbA = fmaxf(mbA, 0.f);
    mbB = fmaxf(mbB, 0.f);

    // per-agent message generator (same agent for both pairs -> shared loads)
    float mgA = mg_b[a*32 + lane], mgB = mgA;
    const float* mgw = mg_w + (size_t)a*1024 + lane;
    #pragma unroll 4
    for (int k = 0; k < 32; k++){
        float mA = __shfl_sync(0xffffffffu, mbA, k);
        float mB = __shfl_sync(0xffffffffu, mbB, k);
        float t = mgw[k*32];
        mgA = fmaf(mA, t, mgA);
        mgB = fmaf(mB, t, mgB);
    }
    g_msg[(size_t)pA*MD + lane] = mgA;
    g_msg[(size_t)pB*MD + lane] = mgB;
}

// ---------------------------------------------------------------------------
// Kernel 2: deterministic per-batch mean over agents; broadcast to out_mm.
// ---------------------------------------------------------------------------
__global__ void k2_kernel(float* __restrict__ out_mm)
{
    const int b = blockIdx.x;
    const int m = threadIdx.x;                    // 32 threads
    const float* base = g_msg + (size_t)b*NAG*MD + m;
    float sum = 0.f;
    #pragma unroll 8
    for (int a = 0; a < NAG; a++) sum += base[a*MD];
    float mean = sum * (1.0f/64.0f);
    g_mean[b*MD + m] = mean;
    float* ob = out_mm + (size_t)b*NAG*MD + m;
    #pragma unroll 8
    for (int a = 0; a < NAG; a++) ob[a*MD] = mean;
}

// ---------------------------------------------------------------------------
// Kernel 3: comm attention (seqlen-1 softmax == 1 -> only V path), LN2,
// q-head. 1 warp handles TWO pairs with the SAME agent (p, p+32768).
// ---------------------------------------------------------------------------
__global__ __launch_bounds__(128) void k3_kernel(
    const float* __restrict__ hbuf,
    const float* __restrict__ ma_wkv, const float* __restrict__ ma_bkv,
    const float* __restrict__ ma_wo,  const float* __restrict__ ma_bo,
    const float* __restrict__ ln2_g,  const float* __restrict__ ln2_b,
    const float* __restrict__ qs_w,   const float* __restrict__ qs_b,
    const float* __restrict__ ah_w,   const float* __restrict__ ah_b,
    float* __restrict__ out_q)
{
    const int tid  = threadIdx.x;
    const int w    = tid >> 5;
    const int lane = tid & 31;
    const int idx  = blockIdx.x * 4 + w;          // 0..32767
    const int p0   = idx;
    const int p1   = idx + NPAIR/2;               // same agent
    const int b0   = p0 >> 6;
    const int b1   = p1 >> 6;
    const int a    = p0 & (NAG - 1);

    float h0 = hbuf[(size_t)p0*HD + lane];
    float h1 = hbuf[(size_t)p1*HD + lane];
    float m0 = g_mean[b0*MD + lane];
    float m1 = g_mean[b1*MD + lane];

    // V = mean_msg @ ma_wkv[:,32:64] + ma_bkv[32:]
    float V0 = ma_bkv[32 + lane], V1 = V0;
    #pragma unroll 4
    for (int k = 0; k < 32; k++){
        float ww = ma_wkv[k*64 + 32 + lane];
        V0 = fmaf(__shfl_sync(0xffffffffu, m0, k), ww, V0);
        V1 = fmaf(__shfl_sync(0xffffffffu, m1, k), ww, V1);
    }
    // after = V @ ma_wo + ma_bo
    float af0 = ma_bo[lane], af1 = af0;
    #pragma unroll 4
    for (int k = 0; k < 32; k++){
        float ww = ma_wo[k*32 + lane];
        af0 = fmaf(__shfl_sync(0xffffffffu, V0, k), ww, af0);
        af1 = fmaf(__shfl_sync(0xffffffffu, V1, k), ww, af1);
    }
    // LN2(h + after), both pairs
    float g2 = ln2_g[lane], bb2 = ln2_b[lane];
    float x0 = h0 + af0, x1 = h1 + af1;
    float t0 = x0, t1 = x1;
    #pragma unroll
    for (int off = 16; off > 0; off >>= 1){
        t0 += __shfl_xor_sync(0xffffffffu, t0, off);
        t1 += __shfl_xor_sync(0xffffffffu, t1, off);
    }
    float mu0 = t0 * (1.0f/32.0f), mu1 = t1 * (1.0f/32.0f);
    float d0 = x0 - mu0, d1 = x1 - mu1;
    float v0 = d0*d0, v1 = d1*d1;
    #pragma unroll
    for (int off = 16; off > 0; off >>= 1){
        v0 += __shfl_xor_sync(0xffffffffu, v0, off);
        v1 += __shfl_xor_sync(0xffffffffu, v1, off);
    }
    float an0 = d0 * rsqrtf(v0*(1.0f/32.0f) + 1e-5f) * g2 + bb2;
    float an1 = d1 * rsqrtf(v1*(1.0f/32.0f) + 1e-5f) * g2 + bb2;

    // qemb = relu([h, after_ln] @ qs_w + qs_b)
    float qe0 = qs_b[lane], qe1 = qe0;
    #pragma unroll 4
    for (int k = 0; k < 32; k++){
        float w0 = qs_w[k*32 + lane];
        float w1 = qs_w[(32+k)*32 + lane];
        qe0 = fmaf(__shfl_sync(0xffffffffu, h0, k),  w0, qe0);
        qe0 = fmaf(__shfl_sync(0xffffffffu, an0, k), w1, qe0);
        qe1 = fmaf(__shfl_sync(0xffffffffu, h1, k),  w0, qe1);
        qe1 = fmaf(__shfl_sync(0xffffffffu, an1, k), w1, qe1);
    }
    qe0 = fmaxf(qe0, 0.f);
    qe1 = fmaxf(qe1, 0.f);

    // q = qemb @ ah_w[a] + ah_b[a]   (lanes 0..15 hold the 16 actions)
    float qa0 = 0.f, qa1 = 0.f;
    if (lane < 16){ qa0 = ah_b[a*16 + lane]; qa1 = qa0; }
    const float* aw = ah_w + (size_t)a*512;
    #pragma unroll 4
    for (int k = 0; k < 32; k++){
        float ww = (lane < 16) ? aw[k*16 + lane] : 0.f;
        qa0 = fmaf(__shfl_sync(0xffffffffu, qe0, k), ww, qa0);
        qa1 = fmaf(__shfl_sync(0xffffffffu, qe1, k), ww, qa1);
    }
    if (lane < 16){
        out_q[(size_t)p0*AD + lane] = qa0;
        out_q[(size_t)p1*AD + lane] = qa1;
    }
}

// ---------------------------------------------------------------------------
extern "C" void kernel_launch(void* const* d_in, const int* in_sizes, int n_in,
                              void* d_out, int out_size)
{
    const float* states = (const float*)d_in[0];
    const float* hidden = (const float*)d_in[1];
    const float* ia_wq  = (const float*)d_in[2];
    const float* ia_bq  = (const float*)d_in[3];
    const float* ia_wkv = (const float*)d_in[4];
    const float* ia_bkv = (const float*)d_in[5];
    const float* ia_wo  = (const float*)d_in[6];
    const float* ia_bo  = (const float*)d_in[7];
    const float* ln1_g  = (const float*)d_in[8];
    const float* ln1_b  = (const float*)d_in[9];
    const float* il_w   = (const float*)d_in[10];
    const float* il_b   = (const float*)d_in[11];
    const float* gwih   = (const float*)d_in[12];
    const float* gwhh   = (const float*)d_in[13];
    const float* gbih   = (const float*)d_in[14];
    const float* gbhh   = (const float*)d_in[15];
    const float* ms_w   = (const float*)d_in[16];
    const float* ms_b   = (const float*)d_in[17];
    const float* mg_w   = (const float*)d_in[18];
    const float* mg_b   = (const float*)d_in[19];
    // d_in[20] = ma_wq, d_in[21] = ma_bq: eliminated (seqlen-1 softmax == 1)
    const float* ma_wkv = (const float*)d_in[22];
    const float* ma_bkv = (const float*)d_in[23];
    const float* ma_wo  = (const float*)d_in[24];
    const float* ma_bo  = (const float*)d_in[25];
    const float* ln2_g  = (const float*)d_in[26];
    const float* ln2_b  = (const float*)d_in[27];
    const float* qs_w   = (const float*)d_in[28];
    const float* qs_b   = (const float*)d_in[29];
    const float* ah_w   = (const float*)d_in[30];
    const float* ah_b   = (const float*)d_in[31];

    float* out    = (float*)d_out;
    float* out_q  = out;                                        // [NPAIR,16]
    float* out_h  = out + (size_t)NPAIR*AD;                     // [NPAIR,32]
    float* out_mm = out + (size_t)NPAIR*AD + (size_t)NPAIR*HD;  // [NPAIR,32]

    k1_kernel<<<NPAIR/4, 64>>>(states, hidden, ia_wq, ia_bq, ia_wkv, ia_bkv,
                               ia_wo, ia_bo, ln1_g, ln1_b, il_w, il_b,
                               gwih, gwhh, gbih, gbhh, ms_b ? ms_w : ms_w, ms_b,
                               mg_w, mg_b, out_h);
    k2_kernel<<<BSZ, 32>>>(out_mm);
    k3_kernel<<<NPAIR/8, 128>>>(out_h, ma_wkv, ma_bkv, ma_wo, ma_bo,
                                ln2_g, ln2_b, qs_w, qs_b, ah_w, ah_b, out_q);
}

// round 9
// speedup vs baseline: 1.8852x; 1.1062x over previous
#include <cuda_runtime.h>
#include <cuda_fp16.h>

#define BSZ 1024
#define NAG 64
#define NLK 32
#define NFE 16
#define HD  32
#define MD  32
#define AD  16
#define NPAIR (BSZ*NAG)   // 65536

typedef unsigned long long u64;

// Scratch (static device globals: allocation-free)
__device__ float g_msg[NPAIR*MD];   // per-pair messages
__device__ float g_mean[BSZ*MD];    // per-batch mean message

__device__ __forceinline__ float sigm(float x){ return 1.0f/(1.0f+__expf(-x)); }

// ---- packed f32x2 helpers (sm_103a FFMA2 path) ----
__device__ __forceinline__ u64 f2fma(u64 a, u64 b, u64 c){
    u64 d; asm("fma.rn.f32x2 %0, %1, %2, %3;" : "=l"(d) : "l"(a), "l"(b), "l"(c)); return d;
}
__device__ __forceinline__ u64 f2add(u64 a, u64 b){
    u64 d; asm("add.rn.f32x2 %0, %1, %2;" : "=l"(d) : "l"(a), "l"(b)); return d;
}
__device__ __forceinline__ u64 f2pack(float lo, float hi){
    u64 d; asm("mov.b64 %0, {%1, %2};" : "=l"(d) : "r"(__float_as_uint(lo)), "r"(__float_as_uint(hi)));
    return d;
}
__device__ __forceinline__ float2 f2unpack(u64 d){
    unsigned lo, hi; asm("mov.b64 {%0, %1}, %2;" : "=r"(lo), "=r"(hi) : "l"(d));
    return make_float2(__uint_as_float(lo), __uint_as_float(hi));
}
__device__ __forceinline__ float f2hsum(u64 d){ float2 u = f2unpack(d); return u.x + u.y; }
__device__ __forceinline__ __half2 u2h(unsigned u){ return *reinterpret_cast<__half2*>(&u); }

// ---------------------------------------------------------------------------
// Kernel 1: 1 warp handles TWO pairs (p, p+32768; same agent).
// Projection: broadcast fp32 row reads, weight-stationary FFMA2, results
// converted to fp16 in shared (K/V/Q) -> attention broadcast wavefronts halve
// (one LDS.128 = one head's K or V per key). Scores via HFMA2, PV in half2.
// Tail joint with coalesced scalar weight LDGs.
// ---------------------------------------------------------------------------
__global__ __launch_bounds__(64, 6) void k1_kernel(
    const float* __restrict__ states, const float* __restrict__ hprev,
    const float* __restrict__ ia_wq, const float* __restrict__ ia_bq,
    const float* __restrict__ ia_wkv, const float* __restrict__ ia_bkv,
    const float* __restrict__ ia_wo, const float* __restrict__ ia_bo,
    const float* __restrict__ ln1_g, const float* __restrict__ ln1_b,
    const float* __restrict__ il_w, const float* __restrict__ il_b,
    const float* __restrict__ gwih, const float* __restrict__ gwhh,
    const float* __restrict__ gbih, const float* __restrict__ gbhh,
    const float* __restrict__ ms_w, const float* __restrict__ ms_b,
    const float* __restrict__ mg_w, const float* __restrict__ mg_b,
    float* __restrict__ out_h)
{
    __shared__ __align__(16) float s_wo[512];
    __shared__ __align__(16) float s_cst[48];          // bo[16], g1[16], b1[16]
    __shared__ __align__(16) float Ss[2][2][32][20];   // [warp][pair][row][20]
    __shared__ __align__(16) __half Qh[2][32][32];     // [warp][link][chan]
    __shared__ __align__(16) __half Kh[2][32][32];
    __shared__ __align__(16) __half Vh[2][32][32];

    const int tid = threadIdx.x;
    for (int i = tid; i < 512; i += 64) s_wo[i] = ia_wo[i];
    if (tid < 16)      s_cst[tid] = ia_bo[tid];
    else if (tid < 32) s_cst[tid] = ln1_g[tid-16];
    else if (tid < 48) s_cst[tid] = ln1_b[tid-32];
    __syncthreads();

    const int w    = tid >> 5;
    const int lane = tid & 31;
    const int pA   = blockIdx.x * 2 + w;       // [0, 32768)
    const int pB   = pA + NPAIR/2;             // same agent
    const int a    = pA & (NAG - 1);

    // --- stage both pairs' states rows ---
    {
        const float4* sa = (const float4*)(states + ((size_t)pA*NLK + lane)*NFE);
        const float4* sb = (const float4*)(states + ((size_t)pB*NLK + lane)*NFE);
        float4* da = (float4*)Ss[w][0][lane];
        float4* db = (float4*)Ss[w][1][lane];
        #pragma unroll
        for (int t = 0; t < 4; t++){ da[t] = sa[t]; db[t] = sb[t]; }
    }

    // --- stationary weight columns, pre-packed f32x2 (lane = output channel) ---
    const float scale = 0.3535533905932738f;   // 1/sqrt(8)
    u64 wq2[8], wk2[8], wv2[8];
    #pragma unroll
    for (int j = 0; j < 8; j++){
        wq2[j] = f2pack(ia_wq [(2*j)*32 + lane]*scale, ia_wq [(2*j+1)*32 + lane]*scale);
        wk2[j] = f2pack(ia_wkv[(2*j)*64 + lane],       ia_wkv[(2*j+1)*64 + lane]);
        wv2[j] = f2pack(ia_wkv[(2*j)*64 + 32 + lane],  ia_wkv[(2*j+1)*64 + 32 + lane]);
    }
    const float bq = ia_bq[lane] * scale;
    const float bk = ia_bkv[lane];
    const float bv = ia_bkv[32 + lane];

    // ================= per-pair attention (sequential, shared buffers) =====
    #pragma unroll 1
    for (int pp = 0; pp < 2; pp++){
        __syncwarp();
        // --- projection: BROADCAST row reads, lane = out channel, fp16 out ---
        #pragma unroll 4
        for (int t = 0; t < 32; t++){
            const ulonglong2* rp = (const ulonglong2*)Ss[w][pp][t];   // broadcast
            ulonglong2 rA = rp[0], rB = rp[1], rC = rp[2], rD = rp[3];
            u64 q1 = f2fma(rA.x,wq2[0], f2fma(rA.y,wq2[1], f2fma(rB.x,wq2[2], f2fma(rB.y,wq2[3], 0ull))));
            u64 q2 = f2fma(rC.x,wq2[4], f2fma(rC.y,wq2[5], f2fma(rD.x,wq2[6], f2fma(rD.y,wq2[7], 0ull))));
            u64 k1 = f2fma(rA.x,wk2[0], f2fma(rA.y,wk2[1], f2fma(rB.x,wk2[2], f2fma(rB.y,wk2[3], 0ull))));
            u64 k2 = f2fma(rC.x,wk2[4], f2fma(rC.y,wk2[5], f2fma(rD.x,wk2[6], f2fma(rD.y,wk2[7], 0ull))));
            u64 v1 = f2fma(rA.x,wv2[0], f2fma(rA.y,wv2[1], f2fma(rB.x,wv2[2], f2fma(rB.y,wv2[3], 0ull))));
            u64 v2 = f2fma(rC.x,wv2[4], f2fma(rC.y,wv2[5], f2fma(rD.x,wv2[6], f2fma(rD.y,wv2[7], 0ull))));
            Qh[w][t][lane] = __float2half_rn(f2hsum(f2add(q1,q2)) + bq);
            Kh[w][t][lane] = __float2half_rn(f2hsum(f2add(k1,k2)) + bk);
            Vh[w][t][lane] = __float2half_rn(f2hsum(f2add(v1,v2)) + bv);
        }
        __syncwarp();

        // --- 4-head attention (fp16 K/V/Q), fused fp32 out-projection ---
        u64 aft2[8];
        {
            const u64* bo2 = (const u64*)s_cst;
            #pragma unroll
            for (int j = 0; j < 8; j++) aft2[j] = bo2[j];
        }

        #pragma unroll
        for (int n = 0; n < 4; n++){
            const uint4* qp = (const uint4*)&Qh[w][lane][n*8];
            uint4 qu = qp[0];
            __half2 q0 = u2h(qu.x), q1 = u2h(qu.y), q2 = u2h(qu.z), q3 = u2h(qu.w);
            __half2 o0 = __float2half2_rn(0.f), o1 = o0, o2 = o0, o3 = o0;
            float sum = 0.f;
            #pragma unroll 8
            for (int k = 0; k < 32; k++){
                uint4 ku = *(const uint4*)&Kh[w][k][n*8];   // broadcast, 1 wf
                __half2 sh = __hmul2(q0, u2h(ku.x));
                sh = __hfma2(q1, u2h(ku.y), sh);
                sh = __hfma2(q2, u2h(ku.z), sh);
                sh = __hfma2(q3, u2h(ku.w), sh);
                float s = __low2float(sh) + __high2float(sh);
                float e = __expf(s);        // no-max softmax: |score| << 1 here
                sum += e;
                __half2 e2 = __float2half2_rn(e);
                uint4 vu = *(const uint4*)&Vh[w][k][n*8];   // broadcast, 1 wf
                o0 = __hfma2(e2, u2h(vu.x), o0);
                o1 = __hfma2(e2, u2h(vu.y), o1);
                o2 = __hfma2(e2, u2h(vu.z), o2);
                o3 = __hfma2(e2, u2h(vu.w), o3);
            }
            const float inv = 1.0f / sum;
            float2 p0 = __half22float2(o0), p1 = __half22float2(o1);
            float2 p2 = __half22float2(o2), p3 = __half22float2(o3);
            float od[8] = {p0.x*inv, p0.y*inv, p1.x*inv, p1.y*inv,
                           p2.x*inv, p2.y*inv, p3.x*inv, p3.y*inv};
            #pragma unroll
            for (int d = 0; d < 8; d++){
                u64 od2 = f2pack(od[d], od[d]);
                const ulonglong2* wp = (const ulonglong2*)(s_wo + (n*8+d)*16);  // broadcast
                ulonglong2 wA = wp[0], wB = wp[1], wC = wp[2], wD = wp[3];
                aft2[0] = f2fma(od2, wA.x, aft2[0]); aft2[1] = f2fma(od2, wA.y, aft2[1]);
                aft2[2] = f2fma(od2, wB.x, aft2[2]); aft2[3] = f2fma(od2, wB.y, aft2[3]);
                aft2[4] = f2fma(od2, wC.x, aft2[4]); aft2[5] = f2fma(od2, wC.y, aft2[5]);
                aft2[6] = f2fma(od2, wD.x, aft2[6]); aft2[7] = f2fma(od2, wD.y, aft2[7]);
            }
        }

        // --- unpack, residual (re-read own states row), LayerNorm ---
        float aft[16];
        #pragma unroll
        for (int j = 0; j < 8; j++){
            float2 u = f2unpack(aft2[j]);
            aft[2*j] = u.x; aft[2*j+1] = u.y;
        }
        {
            const float4* srp = (const float4*)Ss[w][pp][lane];
            float4 s0 = srp[0], s1 = srp[1], s2 = srp[2], s3 = srp[3];
            aft[0]+=s0.x; aft[1]+=s0.y; aft[2]+=s0.z; aft[3]+=s0.w;
            aft[4]+=s1.x; aft[5]+=s1.y; aft[6]+=s1.z; aft[7]+=s1.w;
            aft[8]+=s2.x; aft[9]+=s2.y; aft[10]+=s2.z; aft[11]+=s2.w;
            aft[12]+=s3.x; aft[13]+=s3.y; aft[14]+=s3.z; aft[15]+=s3.w;
        }
        float mean = 0.f;
        #pragma unroll
        for (int f = 0; f < 16; f++) mean += aft[f];
        mean *= 0.0625f;
        float var = 0.f;
        #pragma unroll
        for (int f = 0; f < 16; f++){ float d = aft[f]-mean; var = fmaf(d,d,var); }
        var *= 0.0625f;
        float rstd = rsqrtf(var + 1e-5f);
        #pragma unroll
        for (int f = 0; f < 16; f++)
            aft[f] = (aft[f]-mean)*rstd*s_cst[16+f] + s_cst[32+f];

        __syncwarp();
        {
            float4* dst = (float4*)Ss[w][pp][lane];    // overwrite states with aft
            dst[0] = make_float4(aft[0],aft[1],aft[2],aft[3]);
            dst[1] = make_float4(aft[4],aft[5],aft[6],aft[7]);
            dst[2] = make_float4(aft[8],aft[9],aft[10],aft[11]);
            dst[3] = make_float4(aft[12],aft[13],aft[14],aft[15]);
        }
    }
    __syncwarp();

    // ================= joint tail: coalesced weight LDG feeds BOTH pairs ===
    // enc = aft_flat(512) . il_w[:,lane]
    float encA = il_b[lane], encB = encA;
    #pragma unroll 4
    for (int l = 0; l < 32; l++){
        const float4* ap = (const float4*)Ss[w][0][l];   // broadcast
        const float4* bp = (const float4*)Ss[w][1][l];
        float4 a0=ap[0], a1=ap[1], a2=ap[2], a3=ap[3];
        float4 b0=bp[0], b1=bp[1], b2=bp[2], b3=bp[3];
        const float* wp = il_w + (size_t)(l*16)*32 + lane;
        float t;
        t=wp[0*32];  encA=fmaf(a0.x,t,encA); encB=fmaf(b0.x,t,encB);
        t=wp[1*32];  encA=fmaf(a0.y,t,encA); encB=fmaf(b0.y,t,encB);
        t=wp[2*32];  encA=fmaf(a0.z,t,encA); encB=fmaf(b0.z,t,encB);
        t=wp[3*32];  encA=fmaf(a0.w,t,encA); encB=fmaf(b0.w,t,encB);
        t=wp[4*32];  encA=fmaf(a1.x,t,encA); encB=fmaf(b1.x,t,encB);
        t=wp[5*32];  encA=fmaf(a1.y,t,encA); encB=fmaf(b1.y,t,encB);
        t=wp[6*32];  encA=fmaf(a1.z,t,encA); encB=fmaf(b1.z,t,encB);
        t=wp[7*32];  encA=fmaf(a1.w,t,encA); encB=fmaf(b1.w,t,encB);
        t=wp[8*32];  encA=fmaf(a2.x,t,encA); encB=fmaf(b2.x,t,encB);
        t=wp[9*32];  encA=fmaf(a2.y,t,encA); encB=fmaf(b2.y,t,encB);
        t=wp[10*32]; encA=fmaf(a2.z,t,encA); encB=fmaf(b2.z,t,encB);
        t=wp[11*32]; encA=fmaf(a2.w,t,encA); encB=fmaf(b2.w,t,encB);
        t=wp[12*32]; encA=fmaf(a3.x,t,encA); encB=fmaf(b3.x,t,encB);
        t=wp[13*32]; encA=fmaf(a3.y,t,encA); encB=fmaf(b3.y,t,encB);
        t=wp[14*32]; encA=fmaf(a3.z,t,encA); encB=fmaf(b3.z,t,encB);
        t=wp[15*32]; encA=fmaf(a3.w,t,encA); encB=fmaf(b3.w,t,encB);
    }

    // GRU (gate order r,z,n); lane owns output channel
    float hpA = hprev[(size_t)pA*HD + lane];
    float hpB = hprev[(size_t)pB*HD + lane];
    float giA0 = gbih[lane], giA1 = gbih[32+lane], giA2 = gbih[64+lane];
    float ghA0 = gbhh[lane], ghA1 = gbhh[32+lane], ghA2 = gbhh[64+lane];
    float giB0 = giA0, giB1 = giA1, giB2 = giA2;
    float ghB0 = ghA0, ghB1 = ghA1, ghB2 = ghA2;
    #pragma unroll 4
    for (int k = 0; k < 32; k++){
        float eA = __shfl_sync(0xffffffffu, encA, k);
        float eB = __shfl_sync(0xffffffffu, encB, k);
        float hA = __shfl_sync(0xffffffffu, hpA,  k);
        float hB = __shfl_sync(0xffffffffu, hpB,  k);
        const float* wi = gwih + k*96 + lane;
        const float* wh = gwhh + k*96 + lane;
        float wi0 = wi[0], wi1 = wi[32], wi2 = wi[64];
        float wh0 = wh[0], wh1 = wh[32], wh2 = wh[64];
        giA0=fmaf(eA,wi0,giA0); giB0=fmaf(eB,wi0,giB0);
        giA1=fmaf(eA,wi1,giA1); giB1=fmaf(eB,wi1,giB1);
        giA2=fmaf(eA,wi2,giA2); giB2=fmaf(eB,wi2,giB2);
        ghA0=fmaf(hA,wh0,ghA0); ghB0=fmaf(hB,wh0,ghB0);
        ghA1=fmaf(hA,wh1,ghA1); ghB1=fmaf(hB,wh1,ghB1);
        ghA2=fmaf(hA,wh2,ghA2); ghB2=fmaf(hB,wh2,ghB2);
    }
    float rA = sigm(giA0 + ghA0), rB = sigm(giB0 + ghB0);
    float zA = sigm(giA1 + ghA1), zB = sigm(giB1 + ghB1);
    float nA = tanhf(giA2 + rA*ghA2), nB = tanhf(giB2 + rB*ghB2);
    float hnA = (1.0f - zA)*nA + zA*hpA;
    float hnB = (1.0f - zB)*nB + zB*hpB;
    out_h[(size_t)pA*HD + lane] = hnA;
    out_h[(size_t)pB*HD + lane] = hnB;

    // message embedding (shared ms_w loads)
    float mbA = ms_b[lane], mbB = mbA;
    #pragma unroll 4
    for (int k = 0; k < 32; k++){
        float hA = __shfl_sync(0xffffffffu, hnA, k);
        float hB = __shfl_sync(0xffffffffu, hnB, k);
        float t = ms_w[k*32 + lane];
        mbA = fmaf(hA, t, mbA);
        mbB = fmaf(hB, t, mbB);
    }
    mbA = fmaxf(mbA, 0.f);
    mbB = fmaxf(mbB, 0.f);

    // per-agent message generator (same agent for both pairs -> shared loads)
    float mgA = mg_b[a*32 + lane], mgB = mgA;
    const float* mgw = mg_w + (size_t)a*1024 + lane;
    #pragma unroll 4
    for (int k = 0; k < 32; k++){
        float mA = __shfl_sync(0xffffffffu, mbA, k);
        float mB = __shfl_sync(0xffffffffu, mbB, k);
        float t = mgw[k*32];
        mgA = fmaf(mA, t, mgA);
        mgB = fmaf(mB, t, mgB);
    }
    g_msg[(size_t)pA*MD + lane] = mgA;
    g_msg[(size_t)pB*MD + lane] = mgB;
}

// ---------------------------------------------------------------------------
// Kernel 2: deterministic per-batch mean over agents; broadcast to out_mm.
// ---------------------------------------------------------------------------
__global__ void k2_kernel(float* __restrict__ out_mm)
{
    const int b = blockIdx.x;
    const int m = threadIdx.x;                    // 32 threads
    const float* base = g_msg + (size_t)b*NAG*MD + m;
    float sum = 0.f;
    #pragma unroll 8
    for (int a = 0; a < NAG; a++) sum += base[a*MD];
    float mean = sum * (1.0f/64.0f);
    g_mean[b*MD + m] = mean;
    float* ob = out_mm + (size_t)b*NAG*MD + m;
    #pragma unroll 8
    for (int a = 0; a < NAG; a++) ob[a*MD] = mean;
}

// ---------------------------------------------------------------------------
// Kernel 3: comm attention (seqlen-1 softmax == 1 -> only V path), LN2,
// q-head. 1 warp handles TWO pairs with the SAME agent (p, p+32768).
// ---------------------------------------------------------------------------
__global__ __launch_bounds__(128) void k3_kernel(
    const float* __restrict__ hbuf,
    const float* __restrict__ ma_wkv, const float* __restrict__ ma_bkv,
    const float* __restrict__ ma_wo,  const float* __restrict__ ma_bo,
    const float* __restrict__ ln2_g,  const float* __restrict__ ln2_b,
    const float* __restrict__ qs_w,   const float* __restrict__ qs_b,
    const float* __restrict__ ah_w,   const float* __restrict__ ah_b,
    float* __restrict__ out_q)
{
    const int tid  = threadIdx.x;
    const int w    = tid >> 5;
    const int lane = tid & 31;
    const int idx  = blockIdx.x * 4 + w;          // 0..32767
    const int p0   = idx;
    const int p1   = idx + NPAIR/2;               // same agent
    const int b0   = p0 >> 6;
    const int b1   = p1 >> 6;
    const int a    = p0 & (NAG - 1);

    float h0 = hbuf[(size_t)p0*HD + lane];
    float h1 = hbuf[(size_t)p1*HD + lane];
    float m0 = g_mean[b0*MD + lane];
    float m1 = g_mean[b1*MD + lane];

    // V = mean_msg @ ma_wkv[:,32:64] + ma_bkv[32:]
    float V0 = ma_bkv[32 + lane], V1 = V0;
    #pragma unroll 4
    for (int k = 0; k < 32; k++){
        float ww = ma_wkv[k*64 + 32 + lane];
        V0 = fmaf(__shfl_sync(0xffffffffu, m0, k), ww, V0);
        V1 = fmaf(__shfl_sync(0xffffffffu, m1, k), ww, V1);
    }
    // after = V @ ma_wo + ma_bo
    float af0 = ma_bo[lane], af1 = af0;
    #pragma unroll 4
    for (int k = 0; k < 32; k++){
        float ww = ma_wo[k*32 + lane];
        af0 = fmaf(__shfl_sync(0xffffffffu, V0, k), ww, af0);
        af1 = fmaf(__shfl_sync(0xffffffffu, V1, k), ww, af1);
    }
    // LN2(h + after), both pairs
    float g2 = ln2_g[lane], bb2 = ln2_b[lane];
    float x0 = h0 + af0, x1 = h1 + af1;
    float t0 = x0, t1 = x1;
    #pragma unroll
    for (int off = 16; off > 0; off >>= 1){
        t0 += __shfl_xor_sync(0xffffffffu, t0, off);
        t1 += __shfl_xor_sync(0xffffffffu, t1, off);
    }
    float mu0 = t0 * (1.0f/32.0f), mu1 = t1 * (1.0f/32.0f);
    float d0 = x0 - mu0, d1 = x1 - mu1;
    float v0 = d0*d0, v1 = d1*d1;
    #pragma unroll
    for (int off = 16; off > 0; off >>= 1){
        v0 += __shfl_xor_sync(0xffffffffu, v0, off);
        v1 += __shfl_xor_sync(0xffffffffu, v1, off);
    }
    float an0 = d0 * rsqrtf(v0*(1.0f/32.0f) + 1e-5f) * g2 + bb2;
    float an1 = d1 * rsqrtf(v1*(1.0f/32.0f) + 1e-5f) * g2 + bb2;

    // qemb = relu([h, after_ln] @ qs_w + qs_b)
    float qe0 = qs_b[lane], qe1 = qe0;
    #pragma unroll 4
    for (int k = 0; k < 32; k++){
        float w0 = qs_w[k*32 + lane];
        float w1 = qs_w[(32+k)*32 + lane];
        qe0 = fmaf(__shfl_sync(0xffffffffu, h0, k),  w0, qe0);
        qe0 = fmaf(__shfl_sync(0xffffffffu, an0, k), w1, qe0);
        qe1 = fmaf(__shfl_sync(0xffffffffu, h1, k),  w0, qe1);
        qe1 = fmaf(__shfl_sync(0xffffffffu, an1, k), w1, qe1);
    }
    qe0 = fmaxf(qe0, 0.f);
    qe1 = fmaxf(qe1, 0.f);

    // q = qemb @ ah_w[a] + ah_b[a]   (lanes 0..15 hold the 16 actions)
    float qa0 = 0.f, qa1 = 0.f;
    if (lane < 16){ qa0 = ah_b[a*16 + lane]; qa1 = qa0; }
    const float* aw = ah_w + (size_t)a*512;
    #pragma unroll 4
    for (int k = 0; k < 32; k++){
        float ww = (lane < 16) ? aw[k*16 + lane] : 0.f;
        qa0 = fmaf(__shfl_sync(0xffffffffu, qe0, k), ww, qa0);
        qa1 = fmaf(__shfl_sync(0xffffffffu, qe1, k), ww, qa1);
    }
    if (lane < 16){
        out_q[(size_t)p0*AD + lane] = qa0;
        out_q[(size_t)p1*AD + lane] = qa1;
    }
}

// ---------------------------------------------------------------------------
extern "C" void kernel_launch(void* const* d_in, const int* in_sizes, int n_in,
                              void* d_out, int out_size)
{
    const float* states = (const float*)d_in[0];
    const float* hidden = (const float*)d_in[1];
    const float* ia_wq  = (const float*)d_in[2];
    const float* ia_bq  = (const float*)d_in[3];
    const float* ia_wkv = (const float*)d_in[4];
    const float* ia_bkv = (const float*)d_in[5];
    const float* ia_wo  = (const float*)d_in[6];
    const float* ia_bo  = (const float*)d_in[7];
    const float* ln1_g  = (const float*)d_in[8];
    const float* ln1_b  = (const float*)d_in[9];
    const float* il_w   = (const float*)d_in[10];
    const float* il_b   = (const float*)d_in[11];
    const float* gwih   = (const float*)d_in[12];
    const float* gwhh   = (const float*)d_in[13];
    const float* gbih   = (const float*)d_in[14];
    const float* gbhh   = (const float*)d_in[15];
    const float* ms_w   = (const float*)d_in[16];
    const float* ms_b   = (const float*)d_in[17];
    const float* mg_w   = (const float*)d_in[18];
    const float* mg_b   = (const float*)d_in[19];
    // d_in[20] = ma_wq, d_in[21] = ma_bq: eliminated (seqlen-1 softmax == 1)
    const float* ma_wkv = (const float*)d_in[22];
    const float* ma_bkv = (const float*)d_in[23];
    const float* ma_wo  = (const float*)d_in[24];
    const float* ma_bo  = (const float*)d_in[25];
    const float* ln2_g  = (const float*)d_in[26];
    const float* ln2_b  = (const float*)d_in[27];
    const float* qs_w   = (const float*)d_in[28];
    const float* qs_b   = (const float*)d_in[29];
    const float* ah_w   = (const float*)d_in[30];
    const float* ah_b   = (const float*)d_in[31];

    float* out    = (float*)d_out;
    float* out_q  = out;                                        // [NPAIR,16]
    float* out_h  = out + (size_t)NPAIR*AD;                     // [NPAIR,32]
    float* out_mm = out + (size_t)NPAIR*AD + (size_t)NPAIR*HD;  // [NPAIR,32]

    k1_kernel<<<NPAIR/4, 64>>>(states, hidden, ia_wq, ia_bq, ia_wkv, ia_bkv,
                               ia_wo, ia_bo, ln1_g, ln1_b, il_w, il_b,
                               gwih, gwhh, gbih, gbhh, ms_w, ms_b,
                               mg_w, mg_b, out_h);
    k2_kernel<<<BSZ, 32>>>(out_mm);
    k3_kernel<<<NPAIR/8, 128>>>(out_h, ma_wkv, ma_bkv, ma_wo, ma_bo,
                                ln2_g, ln2_b, qs_w, qs_b, ah_w, ah_b, out_q);
}

// round 12
// speedup vs baseline: 2.1088x; 1.1186x over previous
#include <cuda_runtime.h>
#include <cuda_fp16.h>

#define BSZ 1024
#define NAG 64
#define NLK 32
#define NFE 16
#define HD  32
#define MD  32
#define AD  16
#define NPAIR (BSZ*NAG)   // 65536

typedef unsigned long long u64;

// Scratch (static device globals: allocation-free)
__device__ float g_msg[NPAIR*MD];   // per-pair messages
__device__ float g_mean[BSZ*MD];    // per-batch mean message

__device__ __forceinline__ float sigm(float x){ return 1.0f/(1.0f+__expf(-x)); }

// ---- packed f32x2 helpers (sm_103a FFMA2 path) ----
__device__ __forceinline__ u64 f2fma(u64 a, u64 b, u64 c){
    u64 d; asm("fma.rn.f32x2 %0, %1, %2, %3;" : "=l"(d) : "l"(a), "l"(b), "l"(c)); return d;
}
__device__ __forceinline__ u64 f2add(u64 a, u64 b){
    u64 d; asm("add.rn.f32x2 %0, %1, %2;" : "=l"(d) : "l"(a), "l"(b)); return d;
}
__device__ __forceinline__ u64 f2pack(float lo, float hi){
    u64 d; asm("mov.b64 %0, {%1, %2};" : "=l"(d) : "r"(__float_as_uint(lo)), "r"(__float_as_uint(hi)));
    return d;
}
__device__ __forceinline__ float2 f2unpack(u64 d){
    unsigned lo, hi; asm("mov.b64 {%0, %1}, %2;" : "=r"(lo), "=r"(hi) : "l"(d));
    return make_float2(__uint_as_float(lo), __uint_as_float(hi));
}
__device__ __forceinline__ float f2hsum(u64 d){ float2 u = f2unpack(d); return u.x + u.y; }
__device__ __forceinline__ __half2 u2h(unsigned u){ return *reinterpret_cast<__half2*>(&u); }

// ---------------------------------------------------------------------------
// Kernel 1: 1 warp handles TWO pairs (p, p+32768; same agent).
// fp16 Q/K/V in shared (1 LDS.128 = one head row), HFMA2 scores + half2 PV,
// fp16 wo + half2 out-projection accumulation (2 LDS.128 per (n,d)).
// Tail joint with coalesced scalar weight LDGs.
// ---------------------------------------------------------------------------
__global__ __launch_bounds__(64, 6) void k1_kernel(
    const float* __restrict__ states, const float* __restrict__ hprev,
    const float* __restrict__ ia_wq, const float* __restrict__ ia_bq,
    const float* __restrict__ ia_wkv, const float* __restrict__ ia_bkv,
    const float* __restrict__ ia_wo, const float* __restrict__ ia_bo,
    const float* __restrict__ ln1_g, const float* __restrict__ ln1_b,
    const float* __restrict__ il_w, const float* __restrict__ il_b,
    const float* __restrict__ gwih, const float* __restrict__ gwhh,
    const float* __restrict__ gbih, const float* __restrict__ gbhh,
    const float* __restrict__ ms_w, const float* __restrict__ ms_b,
    const float* __restrict__ mg_w, const float* __restrict__ mg_b,
    float* __restrict__ out_h)
{
    __shared__ __align__(16) __half s_woh[512];        // wo in fp16
    __shared__ __align__(16) float s_cst[48];          // bo[16], g1[16], b1[16]
    __shared__ __align__(16) float Ss[2][2][32][20];   // [warp][pair][row][20]
    __shared__ __align__(16) __half Qh[2][32][32];     // [warp][link][chan]
    __shared__ __align__(16) __half Kh[2][32][32];
    __shared__ __align__(16) __half Vh[2][32][32];

    const int tid = threadIdx.x;
    for (int i = tid; i < 512; i += 64) s_woh[i] = __float2half_rn(ia_wo[i]);
    if (tid < 16)      s_cst[tid] = ia_bo[tid];
    else if (tid < 32) s_cst[tid] = ln1_g[tid-16];
    else if (tid < 48) s_cst[tid] = ln1_b[tid-32];
    __syncthreads();

    const int w    = tid >> 5;
    const int lane = tid & 31;
    const int pA   = blockIdx.x * 2 + w;       // [0, 32768)
    const int pB   = pA + NPAIR/2;             // same agent
    const int a    = pA & (NAG - 1);

    // --- stage both pairs' states rows ---
    {
        const float4* sa = (const float4*)(states + ((size_t)pA*NLK + lane)*NFE);
        const float4* sb = (const float4*)(states + ((size_t)pB*NLK + lane)*NFE);
        float4* da = (float4*)Ss[w][0][lane];
        float4* db = (float4*)Ss[w][1][lane];
        #pragma unroll
        for (int t = 0; t < 4; t++){ da[t] = sa[t]; db[t] = sb[t]; }
    }

    // --- stationary weight columns, pre-packed f32x2 (lane = output channel) ---
    const float scale = 0.3535533905932738f;   // 1/sqrt(8)
    u64 wq2[8], wk2[8], wv2[8];
    #pragma unroll
    for (int j = 0; j < 8; j++){
        wq2[j] = f2pack(ia_wq [(2*j)*32 + lane]*scale, ia_wq [(2*j+1)*32 + lane]*scale);
        wk2[j] = f2pack(ia_wkv[(2*j)*64 + lane],       ia_wkv[(2*j+1)*64 + lane]);
        wv2[j] = f2pack(ia_wkv[(2*j)*64 + 32 + lane],  ia_wkv[(2*j+1)*64 + 32 + lane]);
    }
    const float bq = ia_bq[lane] * scale;
    const float bk = ia_bkv[lane];
    const float bv = ia_bkv[32 + lane];

    // ================= per-pair attention (sequential, shared buffers) =====
    #pragma unroll 1
    for (int pp = 0; pp < 2; pp++){
        __syncwarp();
        // --- projection: BROADCAST row reads, lane = out channel, fp16 out ---
        #pragma unroll 4
        for (int t = 0; t < 32; t++){
            const ulonglong2* rp = (const ulonglong2*)Ss[w][pp][t];   // broadcast
            ulonglong2 rA = rp[0], rB = rp[1], rC = rp[2], rD = rp[3];
            u64 q1 = f2fma(rA.x,wq2[0], f2fma(rA.y,wq2[1], f2fma(rB.x,wq2[2], f2fma(rB.y,wq2[3], 0ull))));
            u64 q2 = f2fma(rC.x,wq2[4], f2fma(rC.y,wq2[5], f2fma(rD.x,wq2[6], f2fma(rD.y,wq2[7], 0ull))));
            u64 k1 = f2fma(rA.x,wk2[0], f2fma(rA.y,wk2[1], f2fma(rB.x,wk2[2], f2fma(rB.y,wk2[3], 0ull))));
            u64 k2 = f2fma(rC.x,wk2[4], f2fma(rC.y,wk2[5], f2fma(rD.x,wk2[6], f2fma(rD.y,wk2[7], 0ull))));
            u64 v1 = f2fma(rA.x,wv2[0], f2fma(rA.y,wv2[1], f2fma(rB.x,wv2[2], f2fma(rB.y,wv2[3], 0ull))));
            u64 v2 = f2fma(rC.x,wv2[4], f2fma(rC.y,wv2[5], f2fma(rD.x,wv2[6], f2fma(rD.y,wv2[7], 0ull))));
            Qh[w][t][lane] = __float2half_rn(f2hsum(f2add(q1,q2)) + bq);
            Kh[w][t][lane] = __float2half_rn(f2hsum(f2add(k1,k2)) + bk);
            Vh[w][t][lane] = __float2half_rn(f2hsum(f2add(v1,v2)) + bv);
        }
        __syncwarp();

        // --- 4-head attention (fp16 K/V/Q), fp16 wo, half2 accumulation ---
        __half2 afth[8];
        #pragma unroll
        for (int j = 0; j < 8; j++) afth[j] = __float2half2_rn(0.f);

        #pragma unroll
        for (int n = 0; n < 4; n++){
            const uint4* qp = (const uint4*)&Qh[w][lane][n*8];
            uint4 qu = qp[0];
            __half2 q0 = u2h(qu.x), q1 = u2h(qu.y), q2 = u2h(qu.z), q3 = u2h(qu.w);
            __half2 o0 = __float2half2_rn(0.f), o1 = o0, o2 = o0, o3 = o0;
            float sum = 0.f;
            #pragma unroll 8
            for (int k = 0; k < 32; k++){
                uint4 ku = *(const uint4*)&Kh[w][k][n*8];   // broadcast, 1 wf
                __half2 sh = __hmul2(q0, u2h(ku.x));
                sh = __hfma2(q1, u2h(ku.y), sh);
                sh = __hfma2(q2, u2h(ku.z), sh);
                sh = __hfma2(q3, u2h(ku.w), sh);
                float s = __low2float(sh) + __high2float(sh);
                float e = __expf(s);        // no-max softmax: |score| << 1 here
                sum += e;
                __half2 e2 = __float2half2_rn(e);
                uint4 vu = *(const uint4*)&Vh[w][k][n*8];   // broadcast, 1 wf
                o0 = __hfma2(e2, u2h(vu.x), o0);
                o1 = __hfma2(e2, u2h(vu.y), o1);
                o2 = __hfma2(e2, u2h(vu.z), o2);
                o3 = __hfma2(e2, u2h(vu.w), o3);
            }
            const float inv = 1.0f / sum;
            float2 p0 = __half22float2(o0), p1 = __half22float2(o1);
            float2 p2 = __half22float2(o2), p3 = __half22float2(o3);
            float od[8] = {p0.x*inv, p0.y*inv, p1.x*inv, p1.y*inv,
                           p2.x*inv, p2.y*inv, p3.x*inv, p3.y*inv};
            #pragma unroll
            for (int d = 0; d < 8; d++){
                __half2 od2 = __float2half2_rn(od[d]);
                const uint4* wp = (const uint4*)(s_woh + (n*8+d)*16);  // 2 LDS.128
                uint4 wA = wp[0], wB = wp[1];
                afth[0] = __hfma2(od2, u2h(wA.x), afth[0]);
                afth[1] = __hfma2(od2, u2h(wA.y), afth[1]);
                afth[2] = __hfma2(od2, u2h(wA.z), afth[2]);
                afth[3] = __hfma2(od2, u2h(wA.w), afth[3]);
                afth[4] = __hfma2(od2, u2h(wB.x), afth[4]);
                afth[5] = __hfma2(od2, u2h(wB.y), afth[5]);
                afth[6] = __hfma2(od2, u2h(wB.z), afth[6]);
                afth[7] = __hfma2(od2, u2h(wB.w), afth[7]);
            }
        }

        // --- unpack (+fp32 bias), residual, LayerNorm ---
        float aft[16];
        #pragma unroll
        for (int j = 0; j < 8; j++){
            float2 u = __half22float2(afth[j]);
            aft[2*j]   = u.x + s_cst[2*j];
            aft[2*j+1] = u.y + s_cst[2*j+1];
        }
        {
            const float4* srp = (const float4*)Ss[w][pp][lane];
            float4 s0 = srp[0], s1 = srp[1], s2 = srp[2], s3 = srp[3];
            aft[0]+=s0.x; aft[1]+=s0.y; aft[2]+=s0.z; aft[3]+=s0.w;
            aft[4]+=s1.x; aft[5]+=s1.y; aft[6]+=s1.z; aft[7]+=s1.w;
            aft[8]+=s2.x; aft[9]+=s2.y; aft[10]+=s2.z; aft[11]+=s2.w;
            aft[12]+=s3.x; aft[13]+=s3.y; aft[14]+=s3.z; aft[15]+=s3.w;
        }
        float mean = 0.f;
        #pragma unroll
        for (int f = 0; f < 16; f++) mean += aft[f];
        mean *= 0.0625f;
        float var = 0.f;
        #pragma unroll
        for (int f = 0; f < 16; f++){ float d = aft[f]-mean; var = fmaf(d,d,var); }
        var *= 0.0625f;
        float rstd = rsqrtf(var + 1e-5f);
        #pragma unroll
        for (int f = 0; f < 16; f++)
            aft[f] = (aft[f]-mean)*rstd*s_cst[16+f] + s_cst[32+f];

        __syncwarp();
        {
            float4* dst = (float4*)Ss[w][pp][lane];    // overwrite states with aft
            dst[0] = make_float4(aft[0],aft[1],aft[2],aft[3]);
            dst[1] = make_float4(aft[4],aft[5],aft[6],aft[7]);
            dst[2] = make_float4(aft[8],aft[9],aft[10],aft[11]);
            dst[3] = make_float4(aft[12],aft[13],aft[14],aft[15]);
        }
    }
    __syncwarp();

    // ================= joint tail: coalesced weight LDG feeds BOTH pairs ===
    // enc = aft_flat(512) . il_w[:,lane]
    float encA = il_b[lane], encB = encA;
    #pragma unroll 4
    for (int l = 0; l < 32; l++){
        const float4* ap = (const float4*)Ss[w][0][l];   // broadcast
        const float4* bp = (const float4*)Ss[w][1][l];
        float4 a0=ap[0], a1=ap[1], a2=ap[2], a3=ap[3];
        float4 b0=bp[0], b1=bp[1], b2=bp[2], b3=bp[3];
        const float* wp = il_w + (size_t)(l*16)*32 + lane;
        float t;
        t=wp[0*32];  encA=fmaf(a0.x,t,encA); encB=fmaf(b0.x,t,encB);
        t=wp[1*32];  encA=fmaf(a0.y,t,encA); encB=fmaf(b0.y,t,encB);
        t=wp[2*32];  encA=fmaf(a0.z,t,encA); encB=fmaf(b0.z,t,encB);
        t=wp[3*32];  encA=fmaf(a0.w,t,encA); encB=fmaf(b0.w,t,encB);
        t=wp[4*32];  encA=fmaf(a1.x,t,encA); encB=fmaf(b1.x,t,encB);
        t=wp[5*32];  encA=fmaf(a1.y,t,encA); encB=fmaf(b1.y,t,encB);
        t=wp[6*32];  encA=fmaf(a1.z,t,encA); encB=fmaf(b1.z,t,encB);
        t=wp[7*32];  encA=fmaf(a1.w,t,encA); encB=fmaf(b1.w,t,encB);
        t=wp[8*32];  encA=fmaf(a2.x,t,encA); encB=fmaf(b2.x,t,encB);
        t=wp[9*32];  encA=fmaf(a2.y,t,encA); encB=fmaf(b2.y,t,encB);
        t=wp[10*32]; encA=fmaf(a2.z,t,encA); encB=fmaf(b2.z,t,encB);
        t=wp[11*32]; encA=fmaf(a2.w,t,encA); encB=fmaf(b2.w,t,encB);
        t=wp[12*32]; encA=fmaf(a3.x,t,encA); encB=fmaf(b3.x,t,encB);
        t=wp[13*32]; encA=fmaf(a3.y,t,encA); encB=fmaf(b3.y,t,encB);
        t=wp[14*32]; encA=fmaf(a3.z,t,encA); encB=fmaf(b3.z,t,encB);
        t=wp[15*32]; encA=fmaf(a3.w,t,encA); encB=fmaf(b3.w,t,encB);
    }

    // GRU (gate order r,z,n); lane owns output channel
    float hpA = hprev[(size_t)pA*HD + lane];
    float hpB = hprev[(size_t)pB*HD + lane];
    float giA0 = gbih[lane], giA1 = gbih[32+lane], giA2 = gbih[64+lane];
    float ghA0 = gbhh[lane], ghA1 = gbhh[32+lane], ghA2 = gbhh[64+lane];
    float giB0 = giA0, giB1 = giA1, giB2 = giA2;
    float ghB0 = ghA0, ghB1 = ghA1, ghB2 = ghA2;
    #pragma unroll 4
    for (int k = 0; k < 32; k++){
        float eA = __shfl_sync(0xffffffffu, encA, k);
        float eB = __shfl_sync(0xffffffffu, encB, k);
        float hA = __shfl_sync(0xffffffffu, hpA,  k);
        float hB = __shfl_sync(0xffffffffu, hpB,  k);
        const float* wi = gwih + k*96 + lane;
        const float* wh = gwhh + k*96 + lane;
        float wi0 = wi[0], wi1 = wi[32], wi2 = wi[64];
        float wh0 = wh[0], wh1 = wh[32], wh2 = wh[64];
        giA0=fmaf(eA,wi0,giA0); giB0=fmaf(eB,wi0,giB0);
        giA1=fmaf(eA,wi1,giA1); giB1=fmaf(eB,wi1,giB1);
        giA2=fmaf(eA,wi2,giA2); giB2=fmaf(eB,wi2,giB2);
        ghA0=fmaf(hA,wh0,ghA0); ghB0=fmaf(hB,wh0,ghB0);
        ghA1=fmaf(hA,wh1,ghA1); ghB1=fmaf(hB,wh1,ghB1);
        ghA2=fmaf(hA,wh2,ghA2); ghB2=fmaf(hB,wh2,ghB2);
    }
    float rA = sigm(giA0 + ghA0), rB = sigm(giB0 + ghB0);
    float zA = sigm(giA1 + ghA1), zB = sigm(giB1 + ghB1);
    float nA = tanhf(giA2 + rA*ghA2), nB = tanhf(giB2 + rB*ghB2);
    float hnA = (1.0f - zA)*nA + zA*hpA;
    float hnB = (1.0f - zB)*nB + zB*hpB;
    out_h[(size_t)pA*HD + lane] = hnA;
    out_h[(size_t)pB*HD + lane] = hnB;

    // message embedding (shared ms_w loads)
    float mbA = ms_b[lane], mbB = mbA;
    #pragma unroll 4
    for (int k = 0; k < 32; k++){
        float hA = __shfl_sync(0xffffffffu, hnA, k);
        float hB = __shfl_sync(0xffffffffu, hnB, k);
        float t = ms_w[k*32 + lane];
        mbA = fmaf(hA, t, mbA);
        mbB = fmaf(hB, t, mbB);
    }
    mbA = fmaxf(mbA, 0.f);
    mbB = fmaxf(mbB, 0.f);

    // per-agent message generator (same agent for both pairs -> shared loads)
    float mgA = mg_b[a*32 + lane], mgB = mgA;
    const float* mgw = mg_w + (size_t)a*1024 + lane;
    #pragma unroll 4
    for (int k = 0; k < 32; k++){
        float mA = __shfl_sync(0xffffffffu, mbA, k);
        float mB = __shfl_sync(0xffffffffu, mbB, k);
        float t = mgw[k*32];
        mgA = fmaf(mA, t, mgA);
        mgB = fmaf(mB, t, mgB);
    }
    g_msg[(size_t)pA*MD + lane] = mgA;
    g_msg[(size_t)pB*MD + lane] = mgB;
}

// ---------------------------------------------------------------------------
// Kernel 2: deterministic per-batch mean over agents; broadcast to out_mm.
// ---------------------------------------------------------------------------
__global__ void k2_kernel(float* __restrict__ out_mm)
{
    const int b = blockIdx.x;
    const int m = threadIdx.x;                    // 32 threads
    const float* base = g_msg + (size_t)b*NAG*MD + m;
    float sum = 0.f;
    #pragma unroll 8
    for (int a = 0; a < NAG; a++) sum += base[a*MD];
    float mean = sum * (1.0f/64.0f);
    g_mean[b*MD + m] = mean;
    float* ob = out_mm + (size_t)b*NAG*MD + m;
    #pragma unroll 8
    for (int a = 0; a < NAG; a++) ob[a*MD] = mean;
}

// ---------------------------------------------------------------------------
// Kernel 3: comm attention (seqlen-1 softmax == 1 -> only V path), LN2,
// q-head. 1 warp handles TWO pairs (p, p+32768; same agent). Shuffle loops
// replaced by smem-stash + packed broadcast ulonglong2 + f2fma.
// ---------------------------------------------------------------------------
__global__ __launch_bounds__(128) void k3_kernel(
    const float* __restrict__ hbuf,
    const float* __restrict__ ma_wkv, const float* __restrict__ ma_bkv,
    const float* __restrict__ ma_wo,  const float* __restrict__ ma_bo,
    const float* __restrict__ ln2_g,  const float* __restrict__ ln2_b,
    const float* __restrict__ qs_w,   const float* __restrict__ qs_b,
    const float* __restrict__ ah_w,   const float* __restrict__ ah_b,
    float* __restrict__ out_q)
{
    __shared__ __align__(16) float sB[4][4][32];   // per-warp stash rows

    const int tid  = threadIdx.x;
    const int w    = tid >> 5;
    const int lane = tid & 31;
    const int idx  = blockIdx.x * 4 + w;          // 0..32767
    const int p0   = idx;
    const int p1   = idx + NPAIR/2;               // same agent
    const int b0   = p0 >> 6;
    const int b1   = p1 >> 6;
    const int a    = p0 & (NAG - 1);

    float h0 = hbuf[(size_t)p0*HD + lane];
    float h1 = hbuf[(size_t)p1*HD + lane];
    float m0 = g_mean[b0*MD + lane];
    float m1 = g_mean[b1*MD + lane];

    // stash mean messages
    sB[w][0][lane] = m0;  sB[w][1][lane] = m1;
    __syncwarp();

    // V = mean_msg @ ma_wkv[:,32:64] + ma_bkv[32:]  (packed broadcast + f2fma)
    u64 V0a = 0ull, V1a = 0ull;
    {
        const ulonglong2* pm0 = (const ulonglong2*)sB[w][0];
        const ulonglong2* pm1 = (const ulonglong2*)sB[w][1];
        #pragma unroll
        for (int c = 0; c < 8; c++){
            ulonglong2 mm0 = pm0[c], mm1 = pm1[c];   // broadcast, 1 wf each
            const int k = 4*c;
            float w0 = ma_wkv[(k+0)*64 + 32 + lane];
            float w1 = ma_wkv[(k+1)*64 + 32 + lane];
            float w2 = ma_wkv[(k+2)*64 + 32 + lane];
            float w3 = ma_wkv[(k+3)*64 + 32 + lane];
            u64 wp0 = f2pack(w0,w1), wp1 = f2pack(w2,w3);
            V0a = f2fma(mm0.x, wp0, f2fma(mm0.y, wp1, V0a));
            V1a = f2fma(mm1.x, wp0, f2fma(mm1.y, wp1, V1a));
        }
    }
    float V0 = f2hsum(V0a) + ma_bkv[32 + lane];
    float V1 = f2hsum(V1a) + ma_bkv[32 + lane];

    __syncwarp();
    sB[w][0][lane] = V0;  sB[w][1][lane] = V1;
    __syncwarp();

    // after = V @ ma_wo + ma_bo
    u64 A0a = 0ull, A1a = 0ull;
    {
        const ulonglong2* pv0 = (const ulonglong2*)sB[w][0];
        const ulonglong2* pv1 = (const ulonglong2*)sB[w][1];
        #pragma unroll
        for (int c = 0; c < 8; c++){
            ulonglong2 vv0 = pv0[c], vv1 = pv1[c];
            const int k = 4*c;
            float w0 = ma_wo[(k+0)*32 + lane];
            float w1 = ma_wo[(k+1)*32 + lane];
            float w2 = ma_wo[(k+2)*32 + lane];
            float w3 = ma_wo[(k+3)*32 + lane];
            u64 wp0 = f2pack(w0,w1), wp1 = f2pack(w2,w3);
            A0a = f2fma(vv0.x, wp0, f2fma(vv0.y, wp1, A0a));
            A1a = f2fma(vv1.x, wp0, f2fma(vv1.y, wp1, A1a));
        }
    }
    float af0 = f2hsum(A0a) + ma_bo[lane];
    float af1 = f2hsum(A1a) + ma_bo[lane];

    // LN2(h + after), both pairs (butterflies)
    float g2 = ln2_g[lane], bb2 = ln2_b[lane];
    float x0 = h0 + af0, x1 = h1 + af1;
    float t0 = x0, t1 = x1;
    #pragma unroll
    for (int off = 16; off > 0; off >>= 1){
        t0 += __shfl_xor_sync(0xffffffffu, t0, off);
        t1 += __shfl_xor_sync(0xffffffffu, t1, off);
    }
    float mu0 = t0 * (1.0f/32.0f), mu1 = t1 * (1.0f/32.0f);
    float d0 = x0 - mu0, d1 = x1 - mu1;
    float v0 = d0*d0, v1 = d1*d1;
    #pragma unroll
    for (int off = 16; off > 0; off >>= 1){
        v0 += __shfl_xor_sync(0xffffffffu, v0, off);
        v1 += __shfl_xor_sync(0xffffffffu, v1, off);
    }
    float an0 = d0 * rsqrtf(v0*(1.0f/32.0f) + 1e-5f) * g2 + bb2;
    float an1 = d1 * rsqrtf(v1*(1.0f/32.0f) + 1e-5f) * g2 + bb2;

    __syncwarp();
    sB[w][0][lane] = h0;  sB[w][1][lane] = an0;
    sB[w][2][lane] = h1;  sB[w][3][lane] = an1;
    __syncwarp();

    // qemb = relu([h, after_ln] @ qs_w + qs_b)
    u64 qe0a = 0ull, qe1a = 0ull;
    {
        const ulonglong2* ph0 = (const ulonglong2*)sB[w][0];
        const ulonglong2* pa0 = (const ulonglong2*)sB[w][1];
        const ulonglong2* ph1 = (const ulonglong2*)sB[w][2];
        const ulonglong2* pa1 = (const ulonglong2*)sB[w][3];
        #pragma unroll
        for (int c = 0; c < 8; c++){
            ulonglong2 hh0 = ph0[c], aa0 = pa0[c], hh1 = ph1[c], aa1 = pa1[c];
            const int k = 4*c;
            float wh0v = qs_w[(k+0)*32 + lane], wh1v = qs_w[(k+1)*32 + lane];
            float wh2v = qs_w[(k+2)*32 + lane], wh3v = qs_w[(k+3)*32 + lane];
            float wa0v = qs_w[(32+k+0)*32 + lane], wa1v = qs_w[(32+k+1)*32 + lane];
            float wa2v = qs_w[(32+k+2)*32 + lane], wa3v = qs_w[(32+k+3)*32 + lane];
            u64 wh01 = f2pack(wh0v,wh1v), wh23 = f2pack(wh2v,wh3v);
            u64 wa01 = f2pack(wa0v,wa1v), wa23 = f2pack(wa2v,wa3v);
            qe0a = f2fma(hh0.x, wh01, f2fma(hh0.y, wh23,
                    f2fma(aa0.x, wa01, f2fma(aa0.y, wa23, qe0a))));
            qe1a = f2fma(hh1.x, wh01, f2fma(hh1.y, wh23,
                    f2fma(aa1.x, wa01, f2fma(aa1.y, wa23, qe1a))));
        }
    }
    float qe0 = fmaxf(f2hsum(qe0a) + qs_b[lane], 0.f);
    float qe1 = fmaxf(f2hsum(qe1a) + qs_b[lane], 0.f);

    __syncwarp();
    sB[w][0][lane] = qe0;  sB[w][1][lane] = qe1;
    __syncwarp();

    // q = qemb @ ah_w[a] + ah_b[a]   (lanes 0..15 hold the 16 actions)
    u64 qa0a = 0ull, qa1a = 0ull;
    {
        const float* aw = ah_w + (size_t)a*512;
        const ulonglong2* pq0 = (const ulonglong2*)sB[w][0];
        const ulonglong2* pq1 = (const ulonglong2*)sB[w][1];
        #pragma unroll
        for (int c = 0; c < 8; c++){
            ulonglong2 qq0 = pq0[c], qq1 = pq1[c];
            const int k = 4*c;
            float w0 = (lane < 16) ? aw[(k+0)*16 + lane] : 0.f;
            float w1 = (lane < 16) ? aw[(k+1)*16 + lane] : 0.f;
            float w2 = (lane < 16) ? aw[(k+2)*16 + lane] : 0.f;
            float w3 = (lane < 16) ? aw[(k+3)*16 + lane] : 0.f;
            u64 wp0 = f2pack(w0,w1), wp1 = f2pack(w2,w3);
            qa0a = f2fma(qq0.x, wp0, f2fma(qq0.y, wp1, qa0a));
            qa1a = f2fma(qq1.x, wp0, f2fma(qq1.y, wp1, qa1a));
        }
    }
    if (lane < 16){
        out_q[(size_t)p0*AD + lane] = f2hsum(qa0a) + ah_b[a*16 + lane];
        out_q[(size_t)p1*AD + lane] = f2hsum(qa1a) + ah_b[a*16 + lane];
    }
}

// ---------------------------------------------------------------------------
extern "C" void kernel_launch(void* const* d_in, const int* in_sizes, int n_in,
                              void* d_out, int out_size)
{
    const float* states = (const float*)d_in[0];
    const float* hidden = (const float*)d_in[1];
    const float* ia_wq  = (const float*)d_in[2];
    const float* ia_bq  = (const float*)d_in[3];
    const float* ia_wkv = (const float*)d_in[4];
    const float* ia_bkv = (const float*)d_in[5];
    const float* ia_wo  = (const float*)d_in[6];
    const float* ia_bo  = (const float*)d_in[7];
    const float* ln1_g  = (const float*)d_in[8];
    const float* ln1_b  = (const float*)d_in[9];
    const float* il_w   = (const float*)d_in[10];
    const float* il_b   = (const float*)d_in[11];
    const float* gwih   = (const float*)d_in[12];
    const float* gwhh   = (const float*)d_in[13];
    const float* gbih   = (const float*)d_in[14];
    const float* gbhh   = (const float*)d_in[15];
    const float* ms_w   = (const float*)d_in[16];
    const float* ms_b   = (const float*)d_in[17];
    const float* mg_w   = (const float*)d_in[18];
    const float* mg_b   = (const float*)d_in[19];
    // d_in[20] = ma_wq, d_in[21] = ma_bq: eliminated (seqlen-1 softmax == 1)
    const float* ma_wkv = (const float*)d_in[22];
    const float* ma_bkv = (const float*)d_in[23];
    const float* ma_wo  = (const float*)d_in[24];
    const float* ma_bo  = (const float*)d_in[25];
    const float* ln2_g  = (const float*)d_in[26];
    const float* ln2_b  = (const float*)d_in[27];
    const float* qs_w   = (const float*)d_in[28];
    const float* qs_b   = (const float*)d_in[29];
    const float* ah_w   = (const float*)d_in[30];
    const float* ah_b   = (const float*)d_in[31];

    float* out    = (float*)d_out;
    float* out_q  = out;                                        // [NPAIR,16]
    float* out_h  = out + (size_t)NPAIR*AD;                     // [NPAIR,32]
    float* out_mm = out + (size_t)NPAIR*AD + (size_t)NPAIR*HD;  // [NPAIR,32]

    k1_kernel<<<NPAIR/4, 64>>>(states, hidden, ia_wq, ia_bq, ia_wkv, ia_bkv,
                               ia_wo, ia_bo, ln1_g, ln1_b, il_w, il_b,
                               gwih, gwhh, gbih, gbhh, ms_w, ms_b,
                               mg_w, mg_b, out_h);
    k2_kernel<<<BSZ, 32>>>(out_mm);
    k3_kernel<<<NPAIR/8, 128>>>(out_h, ma_wkv, ma_bkv, ma_wo, ma_bo,
                                ln2_g, ln2_b, qs_w, qs_b, ah_w, ah_b, out_q);
}

// round 13
// speedup vs baseline: 2.1301x; 1.0101x over previous
#include <cuda_runtime.h>
#include <cuda_fp16.h>

#define BSZ 1024
#define NAG 64
#define NLK 32
#define NFE 16
#define HD  32
#define MD  32
#define AD  16
#define NPAIR (BSZ*NAG)   // 65536

typedef unsigned long long u64;

// Scratch (static device globals: allocation-free)
__device__ float g_msg[NPAIR*MD];   // per-pair messages
__device__ float g_mean[BSZ*MD];    // per-batch mean message
// Quad-packed weights, LANE-MAJOR (lanes adjacent -> coalesced LDG.128):
// entry[q][lane] = float4(W[4q+0..4q+3][lane])
__device__ __align__(16) float4 g_ilw4[128*32];    // il_w  [512,32] -> [fq][j]
__device__ __align__(16) float4 g_gw4 [8*6*32];    // GRU   [kq][gate(ir,iz,in,hr,hz,hn)][j]
__device__ __align__(16) float4 g_msw4[8*32];      // ms_w  [kq][j]
__device__ __align__(16) float4 g_mgw4[64*8*32];   // mg_w  [agent][kq][j]

__device__ __forceinline__ float sigm(float x){ return 1.0f/(1.0f+__expf(-x)); }

// ---- packed f32x2 helpers (sm_103a FFMA2 path) ----
__device__ __forceinline__ u64 f2fma(u64 a, u64 b, u64 c){
    u64 d; asm("fma.rn.f32x2 %0, %1, %2, %3;" : "=l"(d) : "l"(a), "l"(b), "l"(c)); return d;
}
__device__ __forceinline__ u64 f2add(u64 a, u64 b){
    u64 d; asm("add.rn.f32x2 %0, %1, %2;" : "=l"(d) : "l"(a), "l"(b)); return d;
}
__device__ __forceinline__ u64 f2pack(float lo, float hi){
    u64 d; asm("mov.b64 %0, {%1, %2};" : "=l"(d) : "r"(__float_as_uint(lo)), "r"(__float_as_uint(hi)));
    return d;
}
__device__ __forceinline__ float2 f2unpack(u64 d){
    unsigned lo, hi; asm("mov.b64 {%0, %1}, %2;" : "=r"(lo), "=r"(hi) : "l"(d));
    return make_float2(__uint_as_float(lo), __uint_as_float(hi));
}
__device__ __forceinline__ float f2hsum(u64 d){ float2 u = f2unpack(d); return u.x + u.y; }
__device__ __forceinline__ __half2 u2h(unsigned u){ return *reinterpret_cast<__half2*>(&u); }

// ---------------------------------------------------------------------------
// Setup: quad-pack weights lane-major (coalesced gather and scatter). ~3us.
// ---------------------------------------------------------------------------
__global__ void setup_kernel(const float* __restrict__ il_w,
                             const float* __restrict__ gwih,
                             const float* __restrict__ gwhh,
                             const float* __restrict__ ms_w,
                             const float* __restrict__ mg_w)
{
    const int i = blockIdx.x * 256 + threadIdx.x;   // 0..16383
    {   // mg_w: all 16384 entries  [a][kq][j]
        int a = i >> 8, c = (i >> 5) & 7, j = i & 31;
        const float* s = mg_w + a*1024 + (4*c)*32 + j;
        g_mgw4[i] = make_float4(s[0], s[32], s[64], s[96]);
    }
    if (i < 4096){   // il_w: [fq][j]
        int fq = i >> 5, j = i & 31;
        const float* s = il_w + (4*fq)*32 + j;
        g_ilw4[i] = make_float4(s[0], s[32], s[64], s[96]);
    }
    if (i < 1536){   // GRU: [(c*6+g)*32 + j]
        int c = i / 192, r = i % 192, g = r >> 5, j = r & 31;
        const float* W = (g < 3) ? gwih : gwhh;
        const float* s = W + (4*c)*96 + (g % 3)*32 + j;
        g_gw4[i] = make_float4(s[0], s[96], s[192], s[288]);
    }
    if (i < 256){    // ms_w: [c][j]
        int c = i >> 5, j = i & 31;
        const float* s = ms_w + (4*c)*32 + j;
        g_msw4[i] = make_float4(s[0], s[32], s[64], s[96]);
    }
}

// ---------------------------------------------------------------------------
// Kernel 1: 1 warp handles TWO pairs (p, p+32768; same agent).
// fp16 Q/K/V attention (information-floor broadcast reads), FFMA2 projection,
// quad-packed coalesced weight LDG.128 + f2fma tail, stash+broadcast GRU.
// ---------------------------------------------------------------------------
__global__ __launch_bounds__(64, 6) void k1_kernel(
    const float* __restrict__ states, const float* __restrict__ hprev,
    const float* __restrict__ ia_wq, const float* __restrict__ ia_bq,
    const float* __restrict__ ia_wkv, const float* __restrict__ ia_bkv,
    const float* __restrict__ ia_wo, const float* __restrict__ ia_bo,
    const float* __restrict__ ln1_g, const float* __restrict__ ln1_b,
    const float* __restrict__ il_b,
    const float* __restrict__ gbih, const float* __restrict__ gbhh,
    const float* __restrict__ ms_b, const float* __restrict__ mg_b,
    float* __restrict__ out_h)
{
    __shared__ __align__(16) __half s_woh[512];        // wo in fp16
    __shared__ __align__(16) float s_cst[48];          // bo[16], g1[16], b1[16]
    __shared__ __align__(16) float Ss[2][2][32][20];   // [warp][pair][row][20]
    __shared__ __align__(16) __half Qh[2][32][32];     // [warp][link][chan]
    __shared__ __align__(16) __half Kh[2][32][32];
    __shared__ __align__(16) __half Vh[2][32][32];

    const int tid = threadIdx.x;
    for (int i = tid; i < 512; i += 64) s_woh[i] = __float2half_rn(ia_wo[i]);
    if (tid < 16)      s_cst[tid] = ia_bo[tid];
    else if (tid < 32) s_cst[tid] = ln1_g[tid-16];
    else if (tid < 48) s_cst[tid] = ln1_b[tid-32];
    __syncthreads();

    const int w    = tid >> 5;
    const int lane = tid & 31;
    const int pA   = blockIdx.x * 2 + w;       // [0, 32768)
    const int pB   = pA + NPAIR/2;             // same agent
    const int a    = pA & (NAG - 1);

    // --- stage both pairs' states rows ---
    {
        const float4* sa = (const float4*)(states + ((size_t)pA*NLK + lane)*NFE);
        const float4* sb = (const float4*)(states + ((size_t)pB*NLK + lane)*NFE);
        float4* da = (float4*)Ss[w][0][lane];
        float4* db = (float4*)Ss[w][1][lane];
        #pragma unroll
        for (int t = 0; t < 4; t++){ da[t] = sa[t]; db[t] = sb[t]; }
    }

    // --- stationary weight columns, pre-packed f32x2 (lane = output channel) ---
    const float scale = 0.3535533905932738f;   // 1/sqrt(8)
    u64 wq2[8], wk2[8], wv2[8];
    #pragma unroll
    for (int j = 0; j < 8; j++){
        wq2[j] = f2pack(ia_wq [(2*j)*32 + lane]*scale, ia_wq [(2*j+1)*32 + lane]*scale);
        wk2[j] = f2pack(ia_wkv[(2*j)*64 + lane],       ia_wkv[(2*j+1)*64 + lane]);
        wv2[j] = f2pack(ia_wkv[(2*j)*64 + 32 + lane],  ia_wkv[(2*j+1)*64 + 32 + lane]);
    }
    const float bq = ia_bq[lane] * scale;
    const float bk = ia_bkv[lane];
    const float bv = ia_bkv[32 + lane];

    // ================= per-pair attention (sequential, shared buffers) =====
    #pragma unroll 1
    for (int pp = 0; pp < 2; pp++){
        __syncwarp();
        // --- projection: BROADCAST row reads, lane = out channel, fp16 out ---
        #pragma unroll 4
        for (int t = 0; t < 32; t++){
            const ulonglong2* rp = (const ulonglong2*)Ss[w][pp][t];   // broadcast
            ulonglong2 rA = rp[0], rB = rp[1], rC = rp[2], rD = rp[3];
            u64 q1 = f2fma(rA.x,wq2[0], f2fma(rA.y,wq2[1], f2fma(rB.x,wq2[2], f2fma(rB.y,wq2[3], 0ull))));
            u64 q2 = f2fma(rC.x,wq2[4], f2fma(rC.y,wq2[5], f2fma(rD.x,wq2[6], f2fma(rD.y,wq2[7], 0ull))));
            u64 k1 = f2fma(rA.x,wk2[0], f2fma(rA.y,wk2[1], f2fma(rB.x,wk2[2], f2fma(rB.y,wk2[3], 0ull))));
            u64 k2 = f2fma(rC.x,wk2[4], f2fma(rC.y,wk2[5], f2fma(rD.x,wk2[6], f2fma(rD.y,wk2[7], 0ull))));
            u64 v1 = f2fma(rA.x,wv2[0], f2fma(rA.y,wv2[1], f2fma(rB.x,wv2[2], f2fma(rB.y,wv2[3], 0ull))));
            u64 v2 = f2fma(rC.x,wv2[4], f2fma(rC.y,wv2[5], f2fma(rD.x,wv2[6], f2fma(rD.y,wv2[7], 0ull))));
            Qh[w][t][lane] = __float2half_rn(f2hsum(f2add(q1,q2)) + bq);
            Kh[w][t][lane] = __float2half_rn(f2hsum(f2add(k1,k2)) + bk);
            Vh[w][t][lane] = __float2half_rn(f2hsum(f2add(v1,v2)) + bv);
        }
        __syncwarp();

        // --- 4-head attention (fp16 K/V/Q), fp16 wo, half2 accumulation ---
        __half2 afth[8];
        #pragma unroll
        for (int j = 0; j < 8; j++) afth[j] = __float2half2_rn(0.f);

        #pragma unroll
        for (int n = 0; n < 4; n++){
            const uint4* qp = (const uint4*)&Qh[w][lane][n*8];
            uint4 qu = qp[0];
            __half2 q0 = u2h(qu.x), q1 = u2h(qu.y), q2 = u2h(qu.z), q3 = u2h(qu.w);
            __half2 o0 = __float2half2_rn(0.f), o1 = o0, o2 = o0, o3 = o0;
            float sum = 0.f;
            #pragma unroll 8
            for (int k = 0; k < 32; k++){
                uint4 ku = *(const uint4*)&Kh[w][k][n*8];   // broadcast, 1 wf
                __half2 sh = __hmul2(q0, u2h(ku.x));
                sh = __hfma2(q1, u2h(ku.y), sh);
                sh = __hfma2(q2, u2h(ku.z), sh);
                sh = __hfma2(q3, u2h(ku.w), sh);
                float s = __low2float(sh) + __high2float(sh);
                float e = __expf(s);        // no-max softmax: |score| << 1 here
                sum += e;
                __half2 e2 = __float2half2_rn(e);
                uint4 vu = *(const uint4*)&Vh[w][k][n*8];   // broadcast, 1 wf
                o0 = __hfma2(e2, u2h(vu.x), o0);
                o1 = __hfma2(e2, u2h(vu.y), o1);
                o2 = __hfma2(e2, u2h(vu.z), o2);
                o3 = __hfma2(e2, u2h(vu.w), o3);
            }
            const float inv = 1.0f / sum;
            float2 p0 = __half22float2(o0), p1 = __half22float2(o1);
            float2 p2 = __half22float2(o2), p3 = __half22float2(o3);
            float od[8] = {p0.x*inv, p0.y*inv, p1.x*inv, p1.y*inv,
                           p2.x*inv, p2.y*inv, p3.x*inv, p3.y*inv};
            #pragma unroll
            for (int d = 0; d < 8; d++){
                __half2 od2 = __float2half2_rn(od[d]);
                const uint4* wp = (const uint4*)(s_woh + (n*8+d)*16);  // 2 LDS.128
                uint4 wA = wp[0], wB = wp[1];
                afth[0] = __hfma2(od2, u2h(wA.x), afth[0]);
                afth[1] = __hfma2(od2, u2h(wA.y), afth[1]);
                afth[2] = __hfma2(od2, u2h(wA.z), afth[2]);
                afth[3] = __hfma2(od2, u2h(wA.w), afth[3]);
                afth[4] = __hfma2(od2, u2h(wB.x), afth[4]);
                afth[5] = __hfma2(od2, u2h(wB.y), afth[5]);
                afth[6] = __hfma2(od2, u2h(wB.z), afth[6]);
                afth[7] = __hfma2(od2, u2h(wB.w), afth[7]);
            }
        }

        // --- unpack (+fp32 bias), residual, LayerNorm ---
        float aft[16];
        #pragma unroll
        for (int j = 0; j < 8; j++){
            float2 u = __half22float2(afth[j]);
            aft[2*j]   = u.x + s_cst[2*j];
            aft[2*j+1] = u.y + s_cst[2*j+1];
        }
        {
            const float4* srp = (const float4*)Ss[w][pp][lane];
            float4 s0 = srp[0], s1 = srp[1], s2 = srp[2], s3 = srp[3];
            aft[0]+=s0.x; aft[1]+=s0.y; aft[2]+=s0.z; aft[3]+=s0.w;
            aft[4]+=s1.x; aft[5]+=s1.y; aft[6]+=s1.z; aft[7]+=s1.w;
            aft[8]+=s2.x; aft[9]+=s2.y; aft[10]+=s2.z; aft[11]+=s2.w;
            aft[12]+=s3.x; aft[13]+=s3.y; aft[14]+=s3.z; aft[15]+=s3.w;
        }
        float mean = 0.f;
        #pragma unroll
        for (int f = 0; f < 16; f++) mean += aft[f];
        mean *= 0.0625f;
        float var = 0.f;
        #pragma unroll
        for (int f = 0; f < 16; f++){ float d = aft[f]-mean; var = fmaf(d,d,var); }
        var *= 0.0625f;
        float rstd = rsqrtf(var + 1e-5f);
        #pragma unroll
        for (int f = 0; f < 16; f++)
            aft[f] = (aft[f]-mean)*rstd*s_cst[16+f] + s_cst[32+f];

        __syncwarp();
        {
            float4* dst = (float4*)Ss[w][pp][lane];    // overwrite states with aft
            dst[0] = make_float4(aft[0],aft[1],aft[2],aft[3]);
            dst[1] = make_float4(aft[4],aft[5],aft[6],aft[7]);
            dst[2] = make_float4(aft[8],aft[9],aft[10],aft[11]);
            dst[3] = make_float4(aft[12],aft[13],aft[14],aft[15]);
        }
    }
    __syncwarp();

    // ================= joint tail: quad-packed coalesced weights, f2fma ====
    // enc = aft_flat(512) . il_w[:,lane]
    u64 cA0=0ull, cA1=0ull, cB0=0ull, cB1=0ull;
    {
        const ulonglong2* iw = (const ulonglong2*)g_ilw4;
        #pragma unroll 4
        for (int l = 0; l < 32; l++){
            const ulonglong2* ap = (const ulonglong2*)Ss[w][0][l];   // broadcast
            const ulonglong2* bp = (const ulonglong2*)Ss[w][1][l];
            ulonglong2 a0=ap[0], a1=ap[1], a2=ap[2], a3=ap[3];
            ulonglong2 b0=bp[0], b1=bp[1], b2=bp[2], b3=bp[3];
            const ulonglong2* wr = iw + (l*4)*32 + lane;             // coalesced LDG.128
            ulonglong2 w0 = wr[0], w1 = wr[32], w2 = wr[64], w3 = wr[96];
            cA0 = f2fma(a0.x,w0.x, f2fma(a0.y,w0.y, cA0));
            cA1 = f2fma(a1.x,w1.x, f2fma(a1.y,w1.y, cA1));
            cA0 = f2fma(a2.x,w2.x, f2fma(a2.y,w2.y, cA0));
            cA1 = f2fma(a3.x,w3.x, f2fma(a3.y,w3.y, cA1));
            cB0 = f2fma(b0.x,w0.x, f2fma(b0.y,w0.y, cB0));
            cB1 = f2fma(b1.x,w1.x, f2fma(b1.y,w1.y, cB1));
            cB0 = f2fma(b2.x,w2.x, f2fma(b2.y,w2.y, cB0));
            cB1 = f2fma(b3.x,w3.x, f2fma(b3.y,w3.y, cB1));
        }
    }
    float encA = f2hsum(f2add(cA0,cA1)) + il_b[lane];
    float encB = f2hsum(f2add(cB0,cB1)) + il_b[lane];

    // GRU via stash + broadcast + quad weights (Kh is dead -> reuse as stash)
    float hpA = hprev[(size_t)pA*HD + lane];
    float hpB = hprev[(size_t)pB*HD + lane];
    float* st = (float*)Kh[w];                 // 512 floats available
    __syncwarp();
    st[lane] = encA;  st[32+lane] = encB;  st[64+lane] = hpA;  st[96+lane] = hpB;
    __syncwarp();

    u64 irA=0ull,izA=0ull,inA=0ull,hrA=0ull,hzA=0ull,hnA2=0ull;
    u64 irB=0ull,izB=0ull,inB=0ull,hrB=0ull,hzB=0ull,hnB2=0ull;
    {
        const ulonglong2* pE0 = (const ulonglong2*)st;
        const ulonglong2* pE1 = (const ulonglong2*)(st+32);
        const ulonglong2* pH0 = (const ulonglong2*)(st+64);
        const ulonglong2* pH1 = (const ulonglong2*)(st+96);
        const ulonglong2* gw  = (const ulonglong2*)g_gw4;
        #pragma unroll
        for (int c = 0; c < 8; c++){
            ulonglong2 eA = pE0[c], eB = pE1[c], hA = pH0[c], hB = pH1[c];  // broadcast
            const ulonglong2* gbase = gw + (c*6)*32 + lane;
            ulonglong2 wir = gbase[0],    wiz = gbase[32],  win = gbase[64];
            ulonglong2 whr = gbase[96],   whz = gbase[128], whn = gbase[160];
            irA = f2fma(eA.x,wir.x, f2fma(eA.y,wir.y, irA));
            izA = f2fma(eA.x,wiz.x, f2fma(eA.y,wiz.y, izA));
            inA = f2fma(eA.x,win.x, f2fma(eA.y,win.y, inA));
            hrA = f2fma(hA.x,whr.x, f2fma(hA.y,whr.y, hrA));
            hzA = f2fma(hA.x,whz.x, f2fma(hA.y,whz.y, hzA));
            hnA2= f2fma(hA.x,whn.x, f2fma(hA.y,whn.y, hnA2));
            irB = f2fma(eB.x,wir.x, f2fma(eB.y,wir.y, irB));
            izB = f2fma(eB.x,wiz.x, f2fma(eB.y,wiz.y, izB));
            inB = f2fma(eB.x,win.x, f2fma(eB.y,win.y, inB));
            hrB = f2fma(hB.x,whr.x, f2fma(hB.y,whr.y, hrB));
            hzB = f2fma(hB.x,whz.x, f2fma(hB.y,whz.y, hzB));
            hnB2= f2fma(hB.x,whn.x, f2fma(hB.y,whn.y, hnB2));
        }
    }
    float rA = sigm(f2hsum(irA) + gbih[lane]    + f2hsum(hrA) + gbhh[lane]);
    float zA = sigm(f2hsum(izA) + gbih[32+lane] + f2hsum(hzA) + gbhh[32+lane]);
    float nA = tanhf(f2hsum(inA) + gbih[64+lane] + rA*(f2hsum(hnA2) + gbhh[64+lane]));
    float rB = sigm(f2hsum(irB) + gbih[lane]    + f2hsum(hrB) + gbhh[lane]);
    float zB = sigm(f2hsum(izB) + gbih[32+lane] + f2hsum(hzB) + gbhh[32+lane]);
    float nB = tanhf(f2hsum(inB) + gbih[64+lane] + rB*(f2hsum(hnB2) + gbhh[64+lane]));
    float hnA = (1.0f - zA)*nA + zA*hpA;
    float hnB = (1.0f - zB)*nB + zB*hpB;
    out_h[(size_t)pA*HD + lane] = hnA;
    out_h[(size_t)pB*HD + lane] = hnB;

    // message embedding (quad ms weights)
    __syncwarp();
    st[lane] = hnA;  st[32+lane] = hnB;
    __syncwarp();
    u64 mA=0ull, mB=0ull;
    {
        const ulonglong2* p0 = (const ulonglong2*)st;
        const ulonglong2* p1 = (const ulonglong2*)(st+32);
        const ulonglong2* wm = (const ulonglong2*)g_msw4;
        #pragma unroll
        for (int c = 0; c < 8; c++){
            ulonglong2 hA = p0[c], hB = p1[c];       // broadcast
            ulonglong2 ww = wm[c*32 + lane];
            mA = f2fma(hA.x,ww.x, f2fma(hA.y,ww.y, mA));
            mB = f2fma(hB.x,ww.x, f2fma(hB.y,ww.y, mB));
        }
    }
    float mbA = fmaxf(f2hsum(mA) + ms_b[lane], 0.f);
    float mbB = fmaxf(f2hsum(mB) + ms_b[lane], 0.f);

    // per-agent message generator (quad mg weights; same agent both pairs)
    __syncwarp();
    st[lane] = mbA;  st[32+lane] = mbB;
    __syncwarp();
    u64 gA=0ull, gB=0ull;
    {
        const ulonglong2* p0 = (const ulonglong2*)st;
        const ulonglong2* p1 = (const ulonglong2*)(st+32);
        const ulonglong2* wg = (const ulonglong2*)g_mgw4 + (size_t)a*8*32 + lane;
        #pragma unroll
        for (int c = 0; c < 8; c++){
            ulonglong2 mAx = p0[c], mBx = p1[c];     // broadcast
            ulonglong2 ww = wg[c*32];
            gA = f2fma(mAx.x,ww.x, f2fma(mAx.y,ww.y, gA));
            gB = f2fma(mBx.x,ww.x, f2fma(mBx.y,ww.y, gB));
        }
    }
    g_msg[(size_t)pA*MD + lane] = f2hsum(gA) + mg_b[a*32 + lane];
    g_msg[(size_t)pB*MD + lane] = f2hsum(gB) + mg_b[a*32 + lane];
}

// ---------------------------------------------------------------------------
// Kernel 2: deterministic per-batch mean over agents; broadcast to out_mm.
// ---------------------------------------------------------------------------
__global__ void k2_kernel(float* __restrict__ out_mm)
{
    const int b = blockIdx.x;
    const int m = threadIdx.x;                    // 32 threads
    const float* base = g_msg + (size_t)b*NAG*MD + m;
    float sum = 0.f;
    #pragma unroll 8
    for (int a = 0; a < NAG; a++) sum += base[a*MD];
    float mean = sum * (1.0f/64.0f);
    g_mean[b*MD + m] = mean;
    float* ob = out_mm + (size_t)b*NAG*MD + m;
    #pragma unroll 8
    for (int a = 0; a < NAG; a++) ob[a*MD] = mean;
}

// ---------------------------------------------------------------------------
// Kernel 3: comm attention (seqlen-1 softmax == 1 -> only V path), LN2,
// q-head. 1 warp handles TWO pairs (p, p+32768; same agent). Stash +
// packed broadcast ulonglong2 + f2fma.
// ---------------------------------------------------------------------------
__global__ __launch_bounds__(128) void k3_kernel(
    const float* __restrict__ hbuf,
    const float* __restrict__ ma_wkv, const float* __restrict__ ma_bkv,
    const float* __restrict__ ma_wo,  const float* __restrict__ ma_bo,
    const float* __restrict__ ln2_g,  const float* __restrict__ ln2_b,
    const float* __restrict__ qs_w,   const float* __restrict__ qs_b,
    const float* __restrict__ ah_w,   const float* __restrict__ ah_b,
    float* __restrict__ out_q)
{
    __shared__ __align__(16) float sB[4][4][32];   // per-warp stash rows

    const int tid  = threadIdx.x;
    const int w    = tid >> 5;
    const int lane = tid & 31;
    const int idx  = blockIdx.x * 4 + w;          // 0..32767
    const int p0   = idx;
    const int p1   = idx + NPAIR/2;               // same agent
    const int b0   = p0 >> 6;
    const int b1   = p1 >> 6;
    const int a    = p0 & (NAG - 1);

    float h0 = hbuf[(size_t)p0*HD + lane];
    float h1 = hbuf[(size_t)p1*HD + lane];
    float m0 = g_mean[b0*MD + lane];
    float m1 = g_mean[b1*MD + lane];

    // stash mean messages
    sB[w][0][lane] = m0;  sB[w][1][lane] = m1;
    __syncwarp();

    // V = mean_msg @ ma_wkv[:,32:64] + ma_bkv[32:]  (packed broadcast + f2fma)
    u64 V0a = 0ull, V1a = 0ull;
    {
        const ulonglong2* pm0 = (const ulonglong2*)sB[w][0];
        const ulonglong2* pm1 = (const ulonglong2*)sB[w][1];
        #pragma unroll
        for (int c = 0; c < 8; c++){
            ulonglong2 mm0 = pm0[c], mm1 = pm1[c];   // broadcast, 1 wf each
            const int k = 4*c;
            float w0 = ma_wkv[(k+0)*64 + 32 + lane];
            float w1 = ma_wkv[(k+1)*64 + 32 + lane];
            float w2 = ma_wkv[(k+2)*64 + 32 + lane];
            float w3 = ma_wkv[(k+3)*64 + 32 + lane];
            u64 wp0 = f2pack(w0,w1), wp1 = f2pack(w2,w3);
            V0a = f2fma(mm0.x, wp0, f2fma(mm0.y, wp1, V0a));
            V1a = f2fma(mm1.x, wp0, f2fma(mm1.y, wp1, V1a));
        }
    }
    float V0 = f2hsum(V0a) + ma_bkv[32 + lane];
    float V1 = f2hsum(V1a) + ma_bkv[32 + lane];

    __syncwarp();
    sB[w][0][lane] = V0;  sB[w][1][lane] = V1;
    __syncwarp();

    // after = V @ ma_wo + ma_bo
    u64 A0a = 0ull, A1a = 0ull;
    {
        const ulonglong2* pv0 = (const ulonglong2*)sB[w][0];
        const ulonglong2* pv1 = (const ulonglong2*)sB[w][1];
        #pragma unroll
        for (int c = 0; c < 8; c++){
            ulonglong2 vv0 = pv0[c], vv1 = pv1[c];
            const int k = 4*c;
            float w0 = ma_wo[(k+0)*32 + lane];
            float w1 = ma_wo[(k+1)*32 + lane];
            float w2 = ma_wo[(k+2)*32 + lane];
            float w3 = ma_wo[(k+3)*32 + lane];
            u64 wp0 = f2pack(w0,w1), wp1 = f2pack(w2,w3);
            A0a = f2fma(vv0.x, wp0, f2fma(vv0.y, wp1, A0a));
            A1a = f2fma(vv1.x, wp0, f2fma(vv1.y, wp1, A1a));
        }
    }
    float af0 = f2hsum(A0a) + ma_bo[lane];
    float af1 = f2hsum(A1a) + ma_bo[lane];

    // LN2(h + after), both pairs (butterflies)
    float g2 = ln2_g[lane], bb2 = ln2_b[lane];
    float x0 = h0 + af0, x1 = h1 + af1;
    float t0 = x0, t1 = x1;
    #pragma unroll
    for (int off = 16; off > 0; off >>= 1){
        t0 += __shfl_xor_sync(0xffffffffu, t0, off);
        t1 += __shfl_xor_sync(0xffffffffu, t1, off);
    }
    float mu0 = t0 * (1.0f/32.0f), mu1 = t1 * (1.0f/32.0f);
    float d0 = x0 - mu0, d1 = x1 - mu1;
    float v0 = d0*d0, v1 = d1*d1;
    #pragma unroll
    for (int off = 16; off > 0; off >>= 1){
        v0 += __shfl_xor_sync(0xffffffffu, v0, off);
        v1 += __shfl_xor_sync(0xffffffffu, v1, off);
    }
    float an0 = d0 * rsqrtf(v0*(1.0f/32.0f) + 1e-5f) * g2 + bb2;
    float an1 = d1 * rsqrtf(v1*(1.0f/32.0f) + 1e-5f) * g2 + bb2;

    __syncwarp();
    sB[w][0][lane] = h0;  sB[w][1][lane] = an0;
    sB[w][2][lane] = h1;  sB[w][3][lane] = an1;
    __syncwarp();

    // qemb = relu([h, after_ln] @ qs_w + qs_b)
    u64 qe0a = 0ull, qe1a = 0ull;
    {
        const ulonglong2* ph0 = (const ulonglong2*)sB[w][0];
        const ulonglong2* pa0 = (const ulonglong2*)sB[w][1];
        const ulonglong2* ph1 = (const ulonglong2*)sB[w][2];
        const ulonglong2* pa1 = (const ulonglong2*)sB[w][3];
        #pragma unroll
        for (int c = 0; c < 8; c++){
            ulonglong2 hh0 = ph0[c], aa0 = pa0[c], hh1 = ph1[c], aa1 = pa1[c];
            const int k = 4*c;
            float wh0v = qs_w[(k+0)*32 + lane], wh1v = qs_w[(k+1)*32 + lane];
            float wh2v = qs_w[(k+2)*32 + lane], wh3v = qs_w[(k+3)*32 + lane];
            float wa0v = qs_w[(32+k+0)*32 + lane], wa1v = qs_w[(32+k+1)*32 + lane];
            float wa2v = qs_w[(32+k+2)*32 + lane], wa3v = qs_w[(32+k+3)*32 + lane];
            u64 wh01 = f2pack(wh0v,wh1v), wh23 = f2pack(wh2v,wh3v);
            u64 wa01 = f2pack(wa0v,wa1v), wa23 = f2pack(wa2v,wa3v);
            qe0a = f2fma(hh0.x, wh01, f2fma(hh0.y, wh23,
                    f2fma(aa0.x, wa01, f2fma(aa0.y, wa23, qe0a))));
            qe1a = f2fma(hh1.x, wh01, f2fma(hh1.y, wh23,
                    f2fma(aa1.x, wa01, f2fma(aa1.y, wa23, qe1a))));
        }
    }
    float qe0 = fmaxf(f2hsum(qe0a) + qs_b[lane], 0.f);
    float qe1 = fmaxf(f2hsum(qe1a) + qs_b[lane], 0.f);

    __syncwarp();
    sB[w][0][lane] = qe0;  sB[w][1][lane] = qe1;
    __syncwarp();

    // q = qemb @ ah_w[a] + ah_b[a]   (lanes 0..15 hold the 16 actions)
    u64 qa0a = 0ull, qa1a = 0ull;
    {
        const float* aw = ah_w + (size_t)a*512;
        const ulonglong2* pq0 = (const ulonglong2*)sB[w][0];
        const ulonglong2* pq1 = (const ulonglong2*)sB[w][1];
        #pragma unroll
        for (int c = 0; c < 8; c++){
            ulonglong2 qq0 = pq0[c], qq1 = pq1[c];
            const int k = 4*c;
            float w0 = (lane < 16) ? aw[(k+0)*16 + lane] : 0.f;
            float w1 = (lane < 16) ? aw[(k+1)*16 + lane] : 0.f;
            float w2 = (lane < 16) ? aw[(k+2)*16 + lane] : 0.f;
            float w3 = (lane < 16) ? aw[(k+3)*16 + lane] : 0.f;
            u64 wp0 = f2pack(w0,w1), wp1 = f2pack(w2,w3);
            qa0a = f2fma(qq0.x, wp0, f2fma(qq0.y, wp1, qa0a));
            qa1a = f2fma(qq1.x, wp0, f2fma(qq1.y, wp1, qa1a));
        }
    }
    if (lane < 16){
        out_q[(size_t)p0*AD + lane] = f2hsum(qa0a) + ah_b[a*16 + lane];
        out_q[(size_t)p1*AD + lane] = f2hsum(qa1a) + ah_b[a*16 + lane];
    }
}

// ---------------------------------------------------------------------------
extern "C" void kernel_launch(void* const* d_in, const int* in_sizes, int n_in,
                              void* d_out, int out_size)
{
    const float* states = (const float*)d_in[0];
    const float* hidden = (const float*)d_in[1];
    const float* ia_wq  = (const float*)d_in[2];
    const float* ia_bq  = (const float*)d_in[3];
    const float* ia_wkv = (const float*)d_in[4];
    const float* ia_bkv = (const float*)d_in[5];
    const float* ia_wo  = (const float*)d_in[6];
    const float* ia_bo  = (const float*)d_in[7];
    const float* ln1_g  = (const float*)d_in[8];
    const float* ln1_b  = (const float*)d_in[9];
    const float* il_w   = (const float*)d_in[10];
    const float* il_b   = (const float*)d_in[11];
    const float* gwih   = (const float*)d_in[12];
    const float* gwhh   = (const float*)d_in[13];
    const float* gbih   = (const float*)d_in[14];
    const float* gbhh   = (const float*)d_in[15];
    const float* ms_w   = (const float*)d_in[16];
    const float* ms_b   = (const float*)d_in[17];
    const float* mg_w   = (const float*)d_in[18];
    const float* mg_b   = (const float*)d_in[19];
    // d_in[20] = ma_wq, d_in[21] = ma_bq: eliminated (seqlen-1 softmax == 1)
    const float* ma_wkv = (const float*)d_in[22];
    const float* ma_bkv = (const float*)d_in[23];
    const float* ma_wo  = (const float*)d_in[24];
    const float* ma_bo  = (const float*)d_in[25];
    const float* ln2_g  = (const float*)d_in[26];
    const float* ln2_b  = (const float*)d_in[27];
    const float* qs_w   = (const float*)d_in[28];
    const float* qs_b   = (const float*)d_in[29];
    const float* ah_w   = (const float*)d_in[30];
    const float* ah_b   = (const float*)d_in[31];

    float* out    = (float*)d_out;
    float* out_q  = out;                                        // [NPAIR,16]
    float* out_h  = out + (size_t)NPAIR*AD;                     // [NPAIR,32]
    float* out_mm = out + (size_t)NPAIR*AD + (size_t)NPAIR*HD;  // [NPAIR,32]

    setup_kernel<<<64, 256>>>(il_w, gwih, gwhh, ms_w, mg_w);
    k1_kernel<<<NPAIR/4, 64>>>(states, hidden, ia_wq, ia_bq, ia_wkv, ia_bkv,
                               ia_wo, ia_bo, ln1_g, ln1_b, il_b,
                               gbih, gbhh, ms_b, mg_b, out_h);
    k2_kernel<<<BSZ, 32>>>(out_mm);
    k3_kernel<<<NPAIR/8, 128>>>(out_h, ma_wkv, ma_bkv, ma_wo, ma_bo,
                                ln2_g, ln2_b, qs_w, qs_b, ah_w, ah_b, out_q);
}

// round 15
// speedup vs baseline: 2.1817x; 1.0242x over previous
#include <cuda_runtime.h>
#include <cuda_fp16.h>

#define BSZ 1024
#define NAG 64
#define NLK 32
#define NFE 16
#define HD  32
#define MD  32
#define AD  16
#define NPAIR (BSZ*NAG)   // 65536

typedef unsigned long long u64;

// Scratch (static device globals: allocation-free)
__device__ float g_msg[NPAIR*MD];   // per-pair messages
__device__ float g_mean[BSZ*MD];    // per-batch mean message
// Quad-packed weights, LANE-MAJOR: entry[q][lane] = float4(W[4q..4q+3][lane])
__device__ __align__(16) float4 g_ilw4[128*32];    // il_w  [512,32]
__device__ __align__(16) float4 g_gw4 [8*6*32];    // GRU   [kq][gate ir,iz,in,hr,hz,hn][j]
__device__ __align__(16) float4 g_msw4[8*32];      // ms_w
__device__ __align__(16) float4 g_mgw4[64*8*32];   // mg_w  [agent][kq][j]
__device__ __align__(16) float4 g_qsw4[16*32];     // qs_w  [64,32]
__device__ __align__(16) float4 g_mav4[8*32];      // ma_wkv V half [32,32]
__device__ __align__(16) float4 g_mao4[8*32];      // ma_wo [32,32]
__device__ __align__(16) float4 g_ahw4[64*8*16];   // ah_w  [agent][kq][j<16]

__device__ __forceinline__ float sigm(float x){ return 1.0f/(1.0f+__expf(-x)); }

// ---- packed f32x2 helpers (sm_103a FFMA2 path) ----
__device__ __forceinline__ u64 f2fma(u64 a, u64 b, u64 c){
    u64 d; asm("fma.rn.f32x2 %0, %1, %2, %3;" : "=l"(d) : "l"(a), "l"(b), "l"(c)); return d;
}
__device__ __forceinline__ u64 f2add(u64 a, u64 b){
    u64 d; asm("add.rn.f32x2 %0, %1, %2;" : "=l"(d) : "l"(a), "l"(b)); return d;
}
__device__ __forceinline__ u64 f2pack(float lo, float hi){
    u64 d; asm("mov.b64 %0, {%1, %2};" : "=l"(d) : "r"(__float_as_uint(lo)), "r"(__float_as_uint(hi)));
    return d;
}
__device__ __forceinline__ float2 f2unpack(u64 d){
    unsigned lo, hi; asm("mov.b64 {%0, %1}, %2;" : "=r"(lo), "=r"(hi) : "l"(d));
    return make_float2(__uint_as_float(lo), __uint_as_float(hi));
}
__device__ __forceinline__ float f2hsum(u64 d){ float2 u = f2unpack(d); return u.x + u.y; }
__device__ __forceinline__ __half2 u2h(unsigned u){ return *reinterpret_cast<__half2*>(&u); }
__device__ __forceinline__ unsigned h2u(__half2 h){ return *reinterpret_cast<unsigned*>(&h); }

// ---------------------------------------------------------------------------
// Setup: quad-pack weights lane-major (coalesced). ~4us.
// ---------------------------------------------------------------------------
__global__ void setup_kernel(const float* __restrict__ il_w,
                             const float* __restrict__ gwih,
                             const float* __restrict__ gwhh,
                             const float* __restrict__ ms_w,
                             const float* __restrict__ mg_w,
                             const float* __restrict__ qs_w,
                             const float* __restrict__ ma_wkv,
                             const float* __restrict__ ma_wo,
                             const float* __restrict__ ah_w)
{
    const int i = blockIdx.x * 256 + threadIdx.x;   // 0..16383
    {   // mg_w: all 16384 entries  [a][kq][j]
        int a = i >> 8, c = (i >> 5) & 7, j = i & 31;
        const float* s = mg_w + a*1024 + (4*c)*32 + j;
        g_mgw4[i] = make_float4(s[0], s[32], s[64], s[96]);
    }
    if (i < 8192){   // ah_w: [a][c][j<16]
        int a = i >> 7, c = (i >> 4) & 7, j = i & 15;
        const float* s = ah_w + a*512 + (4*c)*16 + j;
        g_ahw4[i] = make_float4(s[0], s[16], s[32], s[48]);
    }
    if (i < 4096){   // il_w: [fq][j]
        int fq = i >> 5, j = i & 31;
        const float* s = il_w + (4*fq)*32 + j;
        g_ilw4[i] = make_float4(s[0], s[32], s[64], s[96]);
    }
    if (i < 1536){   // GRU: [(c*6+g)*32 + j]
        int c = i / 192, r = i % 192, g = r >> 5, j = r & 31;
        const float* W = (g < 3) ? gwih : gwhh;
        const float* s = W + (4*c)*96 + (g % 3)*32 + j;
        g_gw4[i] = make_float4(s[0], s[96], s[192], s[288]);
    }
    if (i < 512){    // qs_w: [kq][j], kq 0..15
        int kq = i >> 5, j = i & 31;
        const float* s = qs_w + (4*kq)*32 + j;
        g_qsw4[i] = make_float4(s[0], s[32], s[64], s[96]);
    }
    if (i < 256){    // ms_w
        int c = i >> 5, j = i & 31;
        const float* s = ms_w + (4*c)*32 + j;
        g_msw4[i] = make_float4(s[0], s[32], s[64], s[96]);
    }
    if (i < 256){    // ma_wkv V half: col 32+j, stride 64
        int c = i >> 5, j = i & 31;
        const float* s = ma_wkv + (4*c)*64 + 32 + j;
        g_mav4[i] = make_float4(s[0], s[64], s[128], s[192]);
    }
    if (i < 256){    // ma_wo
        int c = i >> 5, j = i & 31;
        const float* s = ma_wo + (4*c)*32 + j;
        g_mao4[i] = make_float4(s[0], s[32], s[64], s[96]);
    }
}

// ---------------------------------------------------------------------------
// Kernel 1: 1 warp handles TWO pairs (p, p+32768; same agent).
// fp16 states staging (2 broadcast LDS.128/row), all-HFMA2 projection with
// half2 stationary weights, register-resident fp32 residual, fp16 attention,
// fp32 aft/LN, quad-packed coalesced tail.
// ---------------------------------------------------------------------------
__global__ __launch_bounds__(64, 6) void k1_kernel(
    const float* __restrict__ states, const float* __restrict__ hprev,
    const float* __restrict__ ia_wq, const float* __restrict__ ia_bq,
    const float* __restrict__ ia_wkv, const float* __restrict__ ia_bkv,
    const float* __restrict__ ia_wo, const float* __restrict__ ia_bo,
    const float* __restrict__ ln1_g, const float* __restrict__ ln1_b,
    const float* __restrict__ il_b,
    const float* __restrict__ gbih, const float* __restrict__ gbhh,
    const float* __restrict__ ms_b, const float* __restrict__ mg_b,
    float* __restrict__ out_h)
{
    __shared__ __align__(16) __half s_woh[512];        // wo fp16 (1KB)
    __shared__ __align__(16) float  s_cst[48];         // bo[16], g1[16], b1[16]
    __shared__ __align__(16) __half SsH[2][2][32][16]; // states fp16 (4KB)
    __shared__ __align__(16) float  Sa[2][2][32][20];  // aft fp32 (10.25KB)
    __shared__ __align__(16) __half Qh[2][32][32];
    __shared__ __align__(16) __half Kh[2][32][32];
    __shared__ __align__(16) __half Vh[2][32][32];

    const int tid = threadIdx.x;
    for (int i = tid; i < 512; i += 64) s_woh[i] = __float2half_rn(ia_wo[i]);
    if (tid < 16)      s_cst[tid] = ia_bo[tid];
    else if (tid < 32) s_cst[tid] = ln1_g[tid-16];
    else if (tid < 48) s_cst[tid] = ln1_b[tid-32];
    __syncthreads();

    const int w    = tid >> 5;
    const int lane = tid & 31;
    const int pA   = blockIdx.x * 2 + w;       // [0, 32768)
    const int pB   = pA + NPAIR/2;             // same agent
    const int a    = pA & (NAG - 1);

    // --- stage both pairs' rows: fp32 in regs (residual), fp16 to shared ---
    float sA[16], sB[16];
    {
        const float4* sa = (const float4*)(states + ((size_t)pA*NLK + lane)*NFE);
        const float4* sb = (const float4*)(states + ((size_t)pB*NLK + lane)*NFE);
        uint4* dA = (uint4*)SsH[w][0][lane];
        uint4* dB = (uint4*)SsH[w][1][lane];
        #pragma unroll
        for (int t = 0; t < 2; t++){
            float4 va0 = sa[2*t], va1 = sa[2*t+1];
            float4 vb0 = sb[2*t], vb1 = sb[2*t+1];
            sA[8*t+0]=va0.x; sA[8*t+1]=va0.y; sA[8*t+2]=va0.z; sA[8*t+3]=va0.w;
            sA[8*t+4]=va1.x; sA[8*t+5]=va1.y; sA[8*t+6]=va1.z; sA[8*t+7]=va1.w;
            sB[8*t+0]=vb0.x; sB[8*t+1]=vb0.y; sB[8*t+2]=vb0.z; sB[8*t+3]=vb0.w;
            sB[8*t+4]=vb1.x; sB[8*t+5]=vb1.y; sB[8*t+6]=vb1.z; sB[8*t+7]=vb1.w;
            dA[t] = make_uint4(h2u(__floats2half2_rn(va0.x,va0.y)),
                               h2u(__floats2half2_rn(va0.z,va0.w)),
                               h2u(__floats2half2_rn(va1.x,va1.y)),
                               h2u(__floats2half2_rn(va1.z,va1.w)));
            dB[t] = make_uint4(h2u(__floats2half2_rn(vb0.x,vb0.y)),
                               h2u(__floats2half2_rn(vb0.z,vb0.w)),
                               h2u(__floats2half2_rn(vb1.x,vb1.y)),
                               h2u(__floats2half2_rn(vb1.z,vb1.w)));
        }
    }

    // --- stationary half2 weight columns (lane = output channel) ---
    const float scale = 0.3535533905932738f;   // 1/sqrt(8)
    __half2 wqh[8], wkh[8], wvh[8];
    #pragma unroll
    for (int c = 0; c < 8; c++){
        wqh[c] = __floats2half2_rn(ia_wq [(2*c)*32 + lane]*scale, ia_wq [(2*c+1)*32 + lane]*scale);
        wkh[c] = __floats2half2_rn(ia_wkv[(2*c)*64 + lane],       ia_wkv[(2*c+1)*64 + lane]);
        wvh[c] = __floats2half2_rn(ia_wkv[(2*c)*64 + 32 + lane],  ia_wkv[(2*c+1)*64 + 32 + lane]);
    }
    const float bq = ia_bq[lane] * scale;
    const float bk = ia_bkv[lane];
    const float bv = ia_bkv[32 + lane];

    // ================= per-pair attention (full unroll: residual in regs) ==
    #pragma unroll
    for (int pp = 0; pp < 2; pp++){
        __syncwarp();
        // --- projection: 2 broadcast LDS.128/row, all HFMA2 ---
        #pragma unroll 4
        for (int t = 0; t < 32; t++){
            const uint4* rp = (const uint4*)SsH[w][pp][t];   // broadcast
            uint4 r0 = rp[0], r1 = rp[1];
            __half2 x0=u2h(r0.x), x1=u2h(r0.y), x2=u2h(r0.z), x3=u2h(r0.w);
            __half2 x4=u2h(r1.x), x5=u2h(r1.y), x6=u2h(r1.z), x7=u2h(r1.w);
            __half2 qa = __hmul2(x0,wqh[0]);
            qa=__hfma2(x1,wqh[1],qa); qa=__hfma2(x2,wqh[2],qa); qa=__hfma2(x3,wqh[3],qa);
            qa=__hfma2(x4,wqh[4],qa); qa=__hfma2(x5,wqh[5],qa); qa=__hfma2(x6,wqh[6],qa);
            qa=__hfma2(x7,wqh[7],qa);
            __half2 ka = __hmul2(x0,wkh[0]);
            ka=__hfma2(x1,wkh[1],ka); ka=__hfma2(x2,wkh[2],ka); ka=__hfma2(x3,wkh[3],ka);
            ka=__hfma2(x4,wkh[4],ka); ka=__hfma2(x5,wkh[5],ka); ka=__hfma2(x6,wkh[6],ka);
            ka=__hfma2(x7,wkh[7],ka);
            __half2 va = __hmul2(x0,wvh[0]);
            va=__hfma2(x1,wvh[1],va); va=__hfma2(x2,wvh[2],va); va=__hfma2(x3,wvh[3],va);
            va=__hfma2(x4,wvh[4],va); va=__hfma2(x5,wvh[5],va); va=__hfma2(x6,wvh[6],va);
            va=__hfma2(x7,wvh[7],va);
            Qh[w][t][lane] = __float2half_rn(__low2float(qa)+__high2float(qa)+bq);
            Kh[w][t][lane] = __float2half_rn(__low2float(ka)+__high2float(ka)+bk);
            Vh[w][t][lane] = __float2half_rn(__low2float(va)+__high2float(va)+bv);
        }
        __syncwarp();

        // --- 4-head attention (fp16), fp16 wo, half2 accumulation ---
        __half2 afth[8];
        #pragma unroll
        for (int j = 0; j < 8; j++) afth[j] = __float2half2_rn(0.f);

        #pragma unroll
        for (int n = 0; n < 4; n++){
            const uint4* qp = (const uint4*)&Qh[w][lane][n*8];
            uint4 qu = qp[0];
            __half2 q0 = u2h(qu.x), q1 = u2h(qu.y), q2 = u2h(qu.z), q3 = u2h(qu.w);
            __half2 o0 = __float2half2_rn(0.f), o1 = o0, o2 = o0, o3 = o0;
            float sum = 0.f;
            #pragma unroll 8
            for (int k = 0; k < 32; k++){
                uint4 ku = *(const uint4*)&Kh[w][k][n*8];   // broadcast, 1 wf
                __half2 sh = __hmul2(q0, u2h(ku.x));
                sh = __hfma2(q1, u2h(ku.y), sh);
                sh = __hfma2(q2, u2h(ku.z), sh);
                sh = __hfma2(q3, u2h(ku.w), sh);
                float s = __low2float(sh) + __high2float(sh);
                float e = __expf(s);        // no-max softmax: |score| << 1 here
                sum += e;
                __half2 e2 = __float2half2_rn(e);
                uint4 vu = *(const uint4*)&Vh[w][k][n*8];   // broadcast, 1 wf
                o0 = __hfma2(e2, u2h(vu.x), o0);
                o1 = __hfma2(e2, u2h(vu.y), o1);
                o2 = __hfma2(e2, u2h(vu.z), o2);
                o3 = __hfma2(e2, u2h(vu.w), o3);
            }
            const float inv = 1.0f / sum;
            float2 p0 = __half22float2(o0), p1 = __half22float2(o1);
            float2 p2 = __half22float2(o2), p3 = __half22float2(o3);
            float od[8] = {p0.x*inv, p0.y*inv, p1.x*inv, p1.y*inv,
                           p2.x*inv, p2.y*inv, p3.x*inv, p3.y*inv};
            #pragma unroll
            for (int d = 0; d < 8; d++){
                __half2 od2 = __float2half2_rn(od[d]);
                const uint4* wp = (const uint4*)(s_woh + (n*8+d)*16);  // 2 LDS.128
                uint4 wA = wp[0], wB = wp[1];
                afth[0] = __hfma2(od2, u2h(wA.x), afth[0]);
                afth[1] = __hfma2(od2, u2h(wA.y), afth[1]);
                afth[2] = __hfma2(od2, u2h(wA.z), afth[2]);
                afth[3] = __hfma2(od2, u2h(wA.w), afth[3]);
                afth[4] = __hfma2(od2, u2h(wB.x), afth[4]);
                afth[5] = __hfma2(od2, u2h(wB.y), afth[5]);
                afth[6] = __hfma2(od2, u2h(wB.z), afth[6]);
                afth[7] = __hfma2(od2, u2h(wB.w), afth[7]);
            }
        }

        // --- unpack (+bias), register-resident fp32 residual, LayerNorm ---
        float aft[16];
        #pragma unroll
        for (int j = 0; j < 8; j++){
            float2 u = __half22float2(afth[j]);
            aft[2*j]   = u.x + s_cst[2*j];
            aft[2*j+1] = u.y + s_cst[2*j+1];
        }
        #pragma unroll
        for (int f = 0; f < 16; f++) aft[f] += (pp ? sB[f] : sA[f]);

        float mean = 0.f;
        #pragma unroll
        for (int f = 0; f < 16; f++) mean += aft[f];
        mean *= 0.0625f;
        float var = 0.f;
        #pragma unroll
        for (int f = 0; f < 16; f++){ float d = aft[f]-mean; var = fmaf(d,d,var); }
        var *= 0.0625f;
        float rstd = rsqrtf(var + 1e-5f);
        #pragma unroll
        for (int f = 0; f < 16; f++)
            aft[f] = (aft[f]-mean)*rstd*s_cst[16+f] + s_cst[32+f];

        {
            float4* dst = (float4*)Sa[w][pp][lane];
            dst[0] = make_float4(aft[0],aft[1],aft[2],aft[3]);
            dst[1] = make_float4(aft[4],aft[5],aft[6],aft[7]);
            dst[2] = make_float4(aft[8],aft[9],aft[10],aft[11]);
            dst[3] = make_float4(aft[12],aft[13],aft[14],aft[15]);
        }
    }
    __syncwarp();

    // ================= joint tail: quad-packed coalesced weights, f2fma ====
    // enc = aft_flat(512) . il_w[:,lane]
    u64 cA0=0ull, cA1=0ull, cB0=0ull, cB1=0ull;
    {
        const ulonglong2* iw = (const ulonglong2*)g_ilw4;
        #pragma unroll 4
        for (int l = 0; l < 32; l++){
            const ulonglong2* ap = (const ulonglong2*)Sa[w][0][l];   // broadcast
            const ulonglong2* bp = (const ulonglong2*)Sa[w][1][l];
            ulonglong2 a0=ap[0], a1=ap[1], a2=ap[2], a3=ap[3];
            ulonglong2 b0=bp[0], b1=bp[1], b2=bp[2], b3=bp[3];
            const ulonglong2* wr = iw + (l*4)*32 + lane;             // coalesced LDG.128
            ulonglong2 w0 = wr[0], w1 = wr[32], w2 = wr[64], w3 = wr[96];
            cA0 = f2fma(a0.x,w0.x, f2fma(a0.y,w0.y, cA0));
            cA1 = f2fma(a1.x,w1.x, f2fma(a1.y,w1.y, cA1));
            cA0 = f2fma(a2.x,w2.x, f2fma(a2.y,w2.y, cA0));
            cA1 = f2fma(a3.x,w3.x, f2fma(a3.y,w3.y, cA1));
            cB0 = f2fma(b0.x,w0.x, f2fma(b0.y,w0.y, cB0));
            cB1 = f2fma(b1.x,w1.x, f2fma(b1.y,w1.y, cB1));
            cB0 = f2fma(b2.x,w2.x, f2fma(b2.y,w2.y, cB0));
            cB1 = f2fma(b3.x,w3.x, f2fma(b3.y,w3.y, cB1));
        }
    }
    float encA = f2hsum(f2add(cA0,cA1)) + il_b[lane];
    float encB = f2hsum(f2add(cB0,cB1)) + il_b[lane];

    // GRU via stash + broadcast + quad weights (Kh dead -> reuse as stash)
    float hpA = hprev[(size_t)pA*HD + lane];
    float hpB = hprev[(size_t)pB*HD + lane];
    float* st = (float*)Kh[w];                 // 512 floats available
    __syncwarp();
    st[lane] = encA;  st[32+lane] = encB;  st[64+lane] = hpA;  st[96+lane] = hpB;
    __syncwarp();

    u64 irA=0ull,izA=0ull,inA=0ull,hrA=0ull,hzA=0ull,hnA2=0ull;
    u64 irB=0ull,izB=0ull,inB=0ull,hrB=0ull,hzB=0ull,hnB2=0ull;
    {
        const ulonglong2* pE0 = (const ulonglong2*)st;
        const ulonglong2* pE1 = (const ulonglong2*)(st+32);
        const ulonglong2* pH0 = (const ulonglong2*)(st+64);
        const ulonglong2* pH1 = (const ulonglong2*)(st+96);
        const ulonglong2* gw  = (const ulonglong2*)g_gw4;
        #pragma unroll
        for (int c = 0; c < 8; c++){
            ulonglong2 eA = pE0[c], eB = pE1[c], hA = pH0[c], hB = pH1[c];  // broadcast
            const ulonglong2* gbase = gw + (c*6)*32 + lane;
            ulonglong2 wir = gbase[0],    wiz = gbase[32],  win = gbase[64];
            ulonglong2 whr = gbase[96],   whz = gbase[128], whn = gbase[160];
            irA = f2fma(eA.x,wir.x, f2fma(eA.y,wir.y, irA));
            izA = f2fma(eA.x,wiz.x, f2fma(eA.y,wiz.y, izA));
            inA = f2fma(eA.x,win.x, f2fma(eA.y,win.y, inA));
            hrA = f2fma(hA.x,whr.x, f2fma(hA.y,whr.y, hrA));
            hzA = f2fma(hA.x,whz.x, f2fma(hA.y,whz.y, hzA));
            hnA2= f2fma(hA.x,whn.x, f2fma(hA.y,whn.y, hnA2));
            irB = f2fma(eB.x,wir.x, f2fma(eB.y,wir.y, irB));
            izB = f2fma(eB.x,wiz.x, f2fma(eB.y,wiz.y, izB));
            inB = f2fma(eB.x,win.x, f2fma(eB.y,win.y, inB));
            hrB = f2fma(hB.x,whr.x, f2fma(hB.y,whr.y, hrB));
            hzB = f2fma(hB.x,whz.x, f2fma(hB.y,whz.y, hzB));
            hnB2= f2fma(hB.x,whn.x, f2fma(hB.y,whn.y, hnB2));
        }
    }
    float rA = sigm(f2hsum(irA) + gbih[lane]    + f2hsum(hrA) + gbhh[lane]);
    float zA = sigm(f2hsum(izA) + gbih[32+lane] + f2hsum(hzA) + gbhh[32+lane]);
    float nA = tanhf(f2hsum(inA) + gbih[64+lane] + rA*(f2hsum(hnA2) + gbhh[64+lane]));
    float rB = sigm(f2hsum(irB) + gbih[lane]    + f2hsum(hrB) + gbhh[lane]);
    float zB = sigm(f2hsum(izB) + gbih[32+lane] + f2hsum(hzB) + gbhh[32+lane]);
    float nB = tanhf(f2hsum(inB) + gbih[64+lane] + rB*(f2hsum(hnB2) + gbhh[64+lane]));
    float hnA = (1.0f - zA)*nA + zA*hpA;
    float hnB = (1.0f - zB)*nB + zB*hpB;
    out_h[(size_t)pA*HD + lane] = hnA;
    out_h[(size_t)pB*HD + lane] = hnB;

    // message embedding (quad ms weights)
    __syncwarp();
    st[lane] = hnA;  st[32+lane] = hnB;
    __syncwarp();
    u64 mA=0ull, mB=0ull;
    {
        const ulonglong2* p0 = (const ulonglong2*)st;
        const ulonglong2* p1 = (const ulonglong2*)(st+32);
        const ulonglong2* wm = (const ulonglong2*)g_msw4;
        #pragma unroll
        for (int c = 0; c < 8; c++){
            ulonglong2 hA = p0[c], hB = p1[c];       // broadcast
            ulonglong2 ww = wm[c*32 + lane];
            mA = f2fma(hA.x,ww.x, f2fma(hA.y,ww.y, mA));
            mB = f2fma(hB.x,ww.x, f2fma(hB.y,ww.y, mB));
        }
    }
    float mbA = fmaxf(f2hsum(mA) + ms_b[lane], 0.f);
    float mbB = fmaxf(f2hsum(mB) + ms_b[lane], 0.f);

    // per-agent message generator (quad mg weights; same agent both pairs)
    __syncwarp();
    st[lane] = mbA;  st[32+lane] = mbB;
    __syncwarp();
    u64 gA=0ull, gB=0ull;
    {
        const ulonglong2* p0 = (const ulonglong2*)st;
        const ulonglong2* p1 = (const ulonglong2*)(st+32);
        const ulonglong2* wg = (const ulonglong2*)g_mgw4 + (size_t)a*8*32 + lane;
        #pragma unroll
        for (int c = 0; c < 8; c++){
            ulonglong2 mAx = p0[c], mBx = p1[c];     // broadcast
            ulonglong2 ww = wg[c*32];
            gA = f2fma(mAx.x,ww.x, f2fma(mAx.y,ww.y, gA));
            gB = f2fma(mBx.x,ww.x, f2fma(mBx.y,ww.y, gB));
        }
    }
    g_msg[(size_t)pA*MD + lane] = f2hsum(gA) + mg_b[a*32 + lane];
    g_msg[(size_t)pB*MD + lane] = f2hsum(gB) + mg_b[a*32 + lane];
}

// ---------------------------------------------------------------------------
// Kernel 2: deterministic per-batch mean over agents; broadcast to out_mm.
// ---------------------------------------------------------------------------
__global__ void k2_kernel(float* __restrict__ out_mm)
{
    const int b = blockIdx.x;
    const int m = threadIdx.x;                    // 32 threads
    const float* base = g_msg + (size_t)b*NAG*MD + m;
    float sum = 0.f;
    #pragma unroll 8
    for (int a = 0; a < NAG; a++) sum += base[a*MD];
    float mean = sum * (1.0f/64.0f);
    g_mean[b*MD + m] = mean;
    float* ob = out_mm + (size_t)b*NAG*MD + m;
    #pragma unroll 8
    for (int a = 0; a < NAG; a++) ob[a*MD] = mean;
}

// ---------------------------------------------------------------------------
// Kernel 3: comm attention (seqlen-1 softmax == 1 -> only V path), LN2,
// q-head. 1 warp per TWO pairs (p, p+32768; same agent). Quad-packed
// weight LDG.128 + stash + packed broadcast f2fma.
// ---------------------------------------------------------------------------
__global__ __launch_bounds__(128) void k3_kernel(
    const float* __restrict__ hbuf,
    const float* __restrict__ ma_bkv, const float* __restrict__ ma_bo,
    const float* __restrict__ ln2_g,  const float* __restrict__ ln2_b,
    const float* __restrict__ qs_b,   const float* __restrict__ ah_b,
    float* __restrict__ out_q)
{
    __shared__ __align__(16) float sB[4][4][32];   // per-warp stash rows

    const int tid  = threadIdx.x;
    const int w    = tid >> 5;
    const int lane = tid & 31;
    const int idx  = blockIdx.x * 4 + w;          // 0..32767
    const int p0   = idx;
    const int p1   = idx + NPAIR/2;               // same agent
    const int b0   = p0 >> 6;
    const int b1   = p1 >> 6;
    const int a    = p0 & (NAG - 1);

    float h0 = hbuf[(size_t)p0*HD + lane];
    float h1 = hbuf[(size_t)p1*HD + lane];
    float m0 = g_mean[b0*MD + lane];
    float m1 = g_mean[b1*MD + lane];

    sB[w][0][lane] = m0;  sB[w][1][lane] = m1;
    __syncwarp();

    // V = mean_msg @ ma_wkv[:,32:64] + ma_bkv[32:]   (quad weights)
    u64 V0a = 0ull, V1a = 0ull;
    {
        const ulonglong2* pm0 = (const ulonglong2*)sB[w][0];
        const ulonglong2* pm1 = (const ulonglong2*)sB[w][1];
        const ulonglong2* wv  = (const ulonglong2*)g_mav4 + lane;
        #pragma unroll
        for (int c = 0; c < 8; c++){
            ulonglong2 mm0 = pm0[c], mm1 = pm1[c];   // broadcast
            ulonglong2 ww  = wv[c*32];               // coalesced LDG.128
            V0a = f2fma(mm0.x, ww.x, f2fma(mm0.y, ww.y, V0a));
            V1a = f2fma(mm1.x, ww.x, f2fma(mm1.y, ww.y, V1a));
        }
    }
    float V0 = f2hsum(V0a) + ma_bkv[32 + lane];
    float V1 = f2hsum(V1a) + ma_bkv[32 + lane];

    __syncwarp();
    sB[w][0][lane] = V0;  sB[w][1][lane] = V1;
    __syncwarp();

    // after = V @ ma_wo + ma_bo   (quad weights)
    u64 A0a = 0ull, A1a = 0ull;
    {
        const ulonglong2* pv0 = (const ulonglong2*)sB[w][0];
        const ulonglong2* pv1 = (const ulonglong2*)sB[w][1];
        const ulonglong2* wo  = (const ulonglong2*)g_mao4 + lane;
        #pragma unroll
        for (int c = 0; c < 8; c++){
            ulonglong2 vv0 = pv0[c], vv1 = pv1[c];
            ulonglong2 ww  = wo[c*32];
            A0a = f2fma(vv0.x, ww.x, f2fma(vv0.y, ww.y, A0a));
            A1a = f2fma(vv1.x, ww.x, f2fma(vv1.y, ww.y, A1a));
        }
    }
    float af0 = f2hsum(A0a) + ma_bo[lane];
    float af1 = f2hsum(A1a) + ma_bo[lane];

    // LN2(h + after), both pairs (butterflies)
    float g2 = ln2_g[lane], bb2 = ln2_b[lane];
    float x0 = h0 + af0, x1 = h1 + af1;
    float t0 = x0, t1 = x1;
    #pragma unroll
    for (int off = 16; off > 0; off >>= 1){
        t0 += __shfl_xor_sync(0xffffffffu, t0, off);
        t1 += __shfl_xor_sync(0xffffffffu, t1, off);
    }
    float mu0 = t0 * (1.0f/32.0f), mu1 = t1 * (1.0f/32.0f);
    float d0 = x0 - mu0, d1 = x1 - mu1;
    float v0 = d0*d0, v1 = d1*d1;
    #pragma unroll
    for (int off = 16; off > 0; off >>= 1){
        v0 += __shfl_xor_sync(0xffffffffu, v0, off);
        v1 += __shfl_xor_sync(0xffffffffu, v1, off);
    }
    float an0 = d0 * rsqrtf(v0*(1.0f/32.0f) + 1e-5f) * g2 + bb2;
    float an1 = d1 * rsqrtf(v1*(1.0f/32.0f) + 1e-5f) * g2 + bb2;

    __syncwarp();
    sB[w][0][lane] = h0;  sB[w][1][lane] = an0;
    sB[w][2][lane] = h1;  sB[w][3][lane] = an1;
    __syncwarp();

    // qemb = relu([h, after_ln] @ qs_w + qs_b)   (quad weights)
    u64 qe0a = 0ull, qe1a = 0ull;
    {
        const ulonglong2* ph0 = (const ulonglong2*)sB[w][0];
        const ulonglong2* pa0 = (const ulonglong2*)sB[w][1];
        const ulonglong2* ph1 = (const ulonglong2*)sB[w][2];
        const ulonglong2* pa1 = (const ulonglong2*)sB[w][3];
        const ulonglong2* wq  = (const ulonglong2*)g_qsw4 + lane;
        #pragma unroll
        for (int c = 0; c < 8; c++){
            ulonglong2 hh0 = ph0[c], aa0 = pa0[c], hh1 = ph1[c], aa1 = pa1[c];
            ulonglong2 wh = wq[c*32];          // rows 4c..4c+3 (h half)
            ulonglong2 wa = wq[(8+c)*32];      // rows 32+4c..  (an half)
            qe0a = f2fma(hh0.x, wh.x, f2fma(hh0.y, wh.y,
                    f2fma(aa0.x, wa.x, f2fma(aa0.y, wa.y, qe0a))));
            qe1a = f2fma(hh1.x, wh.x, f2fma(hh1.y, wh.y,
                    f2fma(aa1.x, wa.x, f2fma(aa1.y, wa.y, qe1a))));
        }
    }
    float qe0 = fmaxf(f2hsum(qe0a) + qs_b[lane], 0.f);
    float qe1 = fmaxf(f2hsum(qe1a) + qs_b[lane], 0.f);

    __syncwarp();
    sB[w][0][lane] = qe0;  sB[w][1][lane] = qe1;
    __syncwarp();

    // q = qemb @ ah_w[a] + ah_b[a]  (quad weights; lanes 0..15 = 16 actions)
    u64 qa0a = 0ull, qa1a = 0ull;
    {
        const ulonglong2* pq0 = (const ulonglong2*)sB[w][0];
        const ulonglong2* pq1 = (const ulonglong2*)sB[w][1];
        const ulonglong2* wa  = (const ulonglong2*)g_ahw4 + (size_t)a*8*16 + (lane & 15);
        #pragma unroll
        for (int c = 0; c < 8; c++){
            ulonglong2 qq0 = pq0[c], qq1 = pq1[c];
            ulonglong2 ww  = wa[c*16];
            qa0a = f2fma(qq0.x, ww.x, f2fma(qq0.y, ww.y, qa0a));
            qa1a = f2fma(qq1.x, ww.x, f2fma(qq1.y, ww.y, qa1a));
        }
    }
    if (lane < 16){
        out_q[(size_t)p0*AD + lane] = f2hsum(qa0a) + ah_b[a*16 + lane];
        out_q[(size_t)p1*AD + lane] = f2hsum(qa1a) + ah_b[a*16 + lane];
    }
}

// ---------------------------------------------------------------------------
extern "C" void kernel_launch(void* const* d_in, const int* in_sizes, int n_in,
                              void* d_out, int out_size)
{
    const float* states = (const float*)d_in[0];
    const float* hidden = (const float*)d_in[1];
    const float* ia_wq  = (const float*)d_in[2];
    const float* ia_bq  = (const float*)d_in[3];
    const float* ia_wkv = (const float*)d_in[4];
    const float* ia_bkv = (const float*)d_in[5];
    const float* ia_wo  = (const float*)d_in[6];
    const float* ia_bo  = (const float*)d_in[7];
    const float* ln1_g  = (const float*)d_in[8];
    const float* ln1_b  = (const float*)d_in[9];
    const float* il_w   = (const float*)d_in[10];
    const float* il_b   = (const float*)d_in[11];
    const float* gwih   = (const float*)d_in[12];
    const float* gwhh   = (const float*)d_in[13];
    const float* gbih   = (const float*)d_in[14];
    const float* gbhh   = (const float*)d_in[15];
    const float* ms_w   = (const float*)d_in[16];
    const float* ms_b   = (const float*)d_in[17];
    const float* mg_w   = (const float*)d_in[18];
    const float* mg_b   = (const float*)d_in[19];
    // d_in[20] = ma_wq, d_in[21] = ma_bq: eliminated (seqlen-1 softmax == 1)
    const float* ma_wkv = (const float*)d_in[22];
    const float* ma_bkv = (const float*)d_in[23];
    const float* ma_wo  = (const float*)d_in[24];
    const float* ma_bo  = (const float*)d_in[25];
    const float* ln2_g  = (const float*)d_in[26];
    const float* ln2_b  = (const float*)d_in[27];
    const float* qs_w   = (const float*)d_in[28];
    const float* qs_b   = (const float*)d_in[29];
    const float* ah_w   = (const float*)d_in[30];
    const float* ah_b   = (const float*)d_in[31];

    float* out    = (float*)d_out;
    float* out_q  = out;                                        // [NPAIR,16]
    float* out_h  = out + (size_t)NPAIR*AD;                     // [NPAIR,32]
    float* out_mm = out + (size_t)NPAIR*AD + (size_t)NPAIR*HD;  // [NPAIR,32]

    setup_kernel<<<64, 256>>>(il_w, gwih, gwhh, ms_w, mg_w,
                              qs_w, ma_wkv, ma_wo, ah_w);
    k1_kernel<<<NPAIR/4, 64>>>(states, hidden, ia_wq, ia_bq, ia_wkv, ia_bkv,
                               ia_wo, ia_bo, ln1_g, ln1_b, il_b,
                               gbih, gbhh, ms_b, mg_b, out_h);
    k2_kernel<<<BSZ, 32>>>(out_mm);
    k3_kernel<<<NPAIR/8, 128>>>(out_h, ma_bkv, ma_bo,
                                ln2_g, ln2_b, qs_b, ah_b, out_q);
}

// round 17
// speedup vs baseline: 2.2511x; 1.0318x over previous
#include <cuda_runtime.h>
#include <cuda_fp16.h>

#define BSZ 1024
#define NAG 64
#define NLK 32
#define NFE 16
#define HD  32
#define MD  32
#define AD  16
#define NPAIR (BSZ*NAG)   // 65536

typedef unsigned long long u64;

// Scratch (static device globals: allocation-free)
__device__ float g_msg[NPAIR*MD];   // per-pair messages
__device__ float g_mean[BSZ*MD];    // per-batch mean message
// Quad-packed weights, LANE-MAJOR: entry[q][lane] = float4(W[4q..4q+3][lane])
__device__ __align__(16) float4 g_ilw4[128*32];    // il_w  [512,32]
__device__ __align__(16) float4 g_gw4 [8*6*32];    // GRU   [kq][gate ir,iz,in,hr,hz,hn][j]
__device__ __align__(16) float4 g_msw4[8*32];      // ms_w
__device__ __align__(16) float4 g_mgw4[64*8*32];   // mg_w  [agent][kq][j]
__device__ __align__(16) float4 g_qsw4[16*32];     // qs_w  [64,32]
__device__ __align__(16) float4 g_mav4[8*32];      // ma_wkv V half [32,32]
__device__ __align__(16) float4 g_mao4[8*32];      // ma_wo [32,32]
__device__ __align__(16) float4 g_ahw4[64*8*16];   // ah_w  [agent][kq][j<16]

__device__ __forceinline__ float sigm(float x){ return 1.0f/(1.0f+__expf(-x)); }

// ---- packed f32x2 helpers (sm_103a FFMA2 path) ----
__device__ __forceinline__ u64 f2fma(u64 a, u64 b, u64 c){
    u64 d; asm("fma.rn.f32x2 %0, %1, %2, %3;" : "=l"(d) : "l"(a), "l"(b), "l"(c)); return d;
}
__device__ __forceinline__ u64 f2add(u64 a, u64 b){
    u64 d; asm("add.rn.f32x2 %0, %1, %2;" : "=l"(d) : "l"(a), "l"(b)); return d;
}
__device__ __forceinline__ u64 f2pack(float lo, float hi){
    u64 d; asm("mov.b64 %0, {%1, %2};" : "=l"(d) : "r"(__float_as_uint(lo)), "r"(__float_as_uint(hi)));
    return d;
}
__device__ __forceinline__ float2 f2unpack(u64 d){
    unsigned lo, hi; asm("mov.b64 {%0, %1}, %2;" : "=r"(lo), "=r"(hi) : "l"(d));
    return make_float2(__uint_as_float(lo), __uint_as_float(hi));
}
__device__ __forceinline__ float f2hsum(u64 d){ float2 u = f2unpack(d); return u.x + u.y; }
__device__ __forceinline__ __half2 u2h(unsigned u){ return *reinterpret_cast<__half2*>(&u); }
__device__ __forceinline__ unsigned h2u(__half2 h){ return *reinterpret_cast<unsigned*>(&h); }

// ---------------------------------------------------------------------------
// Setup: quad-pack weights lane-major (coalesced). ~4us.
// ---------------------------------------------------------------------------
__global__ void setup_kernel(const float* __restrict__ il_w,
                             const float* __restrict__ gwih,
                             const float* __restrict__ gwhh,
                             const float* __restrict__ ms_w,
                             const float* __restrict__ mg_w,
                             const float* __restrict__ qs_w,
                             const float* __restrict__ ma_wkv,
                             const float* __restrict__ ma_wo,
                             const float* __restrict__ ah_w)
{
    const int i = blockIdx.x * 256 + threadIdx.x;   // 0..16383
    {   // mg_w: all 16384 entries  [a][kq][j]
        int a = i >> 8, c = (i >> 5) & 7, j = i & 31;
        const float* s = mg_w + a*1024 + (4*c)*32 + j;
        g_mgw4[i] = make_float4(s[0], s[32], s[64], s[96]);
    }
    if (i < 8192){   // ah_w: [a][c][j<16]
        int a = i >> 7, c = (i >> 4) & 7, j = i & 15;
        const float* s = ah_w + a*512 + (4*c)*16 + j;
        g_ahw4[i] = make_float4(s[0], s[16], s[32], s[48]);
    }
    if (i < 4096){   // il_w: [fq][j]
        int fq = i >> 5, j = i & 31;
        const float* s = il_w + (4*fq)*32 + j;
        g_ilw4[i] = make_float4(s[0], s[32], s[64], s[96]);
    }
    if (i < 1536){   // GRU: [(c*6+g)*32 + j]
        int c = i / 192, r = i % 192, g = r >> 5, j = r & 31;
        const float* W = (g < 3) ? gwih : gwhh;
        const float* s = W + (4*c)*96 + (g % 3)*32 + j;
        g_gw4[i] = make_float4(s[0], s[96], s[192], s[288]);
    }
    if (i < 512){    // qs_w: [kq][j], kq 0..15
        int kq = i >> 5, j = i & 31;
        const float* s = qs_w + (4*kq)*32 + j;
        g_qsw4[i] = make_float4(s[0], s[32], s[64], s[96]);
    }
    if (i < 256){    // ms_w
        int c = i >> 5, j = i & 31;
        const float* s = ms_w + (4*c)*32 + j;
        g_msw4[i] = make_float4(s[0], s[32], s[64], s[96]);
    }
    if (i < 256){    // ma_wkv V half: col 32+j, stride 64
        int c = i >> 5, j = i & 31;
        const float* s = ma_wkv + (4*c)*64 + 32 + j;
        g_mav4[i] = make_float4(s[0], s[64], s[128], s[192]);
    }
    if (i < 256){    // ma_wo
        int c = i >> 5, j = i & 31;
        const float* s = ma_wo + (4*c)*32 + j;
        g_mao4[i] = make_float4(s[0], s[32], s[64], s[96]);
    }
}

// ---------------------------------------------------------------------------
// Kernel 1: 2 warps/block, 2 pairs/warp (p, p+32768; same agent).
// Attention identical to round-15. Tail: the block's two warps SPLIT the
// enc/GRU weight streams (each reads half) and compute partials for all 4
// block pairs, exchanging through the dead attention QKV smem (aliased fp32).
// ---------------------------------------------------------------------------
__global__ __launch_bounds__(64, 6) void k1_kernel(
    const float* __restrict__ states, const float* __restrict__ hprev,
    const float* __restrict__ ia_wq, const float* __restrict__ ia_bq,
    const float* __restrict__ ia_wkv, const float* __restrict__ ia_bkv,
    const float* __restrict__ ia_wo, const float* __restrict__ ia_bo,
    const float* __restrict__ ln1_g, const float* __restrict__ ln1_b,
    const float* __restrict__ il_b,
    const float* __restrict__ gbih, const float* __restrict__ gbhh,
    const float* __restrict__ ms_b, const float* __restrict__ mg_b,
    float* __restrict__ out_h)
{
    __shared__ __align__(16) __half s_woh[512];        // wo fp16 (1KB)
    __shared__ __align__(16) float  s_cst[48];         // bo[16], g1[16], b1[16]
    __shared__ __align__(16) __half SsH[2][2][32][16]; // states fp16 (4KB)
    __shared__ __align__(16) float  Sa[2][2][32][20];  // aft fp32 (10.25KB)
    __shared__ __align__(16) __half QKV[2][3][32][32]; // Q/K/V fp16 (12KB); tail: fp32 scratch

    // fp32 scratch overlay on QKV (used after attention, post-__syncthreads):
    //  E[0..255]    encP[2][4][32]  partial enc (then rows k*32 = FINAL enc)
    //  E[256..383]  hpX[4][32]
    //  E[384..767]  giX[12][32]   (pair k, gate g at row k*3+g)
    //  E[768..1151] ghX[12][32]
    //  E[1152..1407] per-warp ms/mg stash (64 floats each warp)
    float* E = (float*)QKV;

    const int tid = threadIdx.x;
    for (int i = tid; i < 512; i += 64) s_woh[i] = __float2half_rn(ia_wo[i]);
    if (tid < 16)      s_cst[tid] = ia_bo[tid];
    else if (tid < 32) s_cst[tid] = ln1_g[tid-16];
    else if (tid < 48) s_cst[tid] = ln1_b[tid-32];
    __syncthreads();

    const int w    = tid >> 5;
    const int lane = tid & 31;
    const int pA   = blockIdx.x * 2 + w;       // [0, 32768)
    const int pB   = pA + NPAIR/2;             // same agent
    const int a    = pA & (NAG - 1);

    // --- stage both pairs' rows: fp32 in regs (residual), fp16 to shared ---
    float sA[16], sB[16];
    {
        const float4* sa = (const float4*)(states + ((size_t)pA*NLK + lane)*NFE);
        const float4* sb = (const float4*)(states + ((size_t)pB*NLK + lane)*NFE);
        uint4* dA = (uint4*)SsH[w][0][lane];
        uint4* dB = (uint4*)SsH[w][1][lane];
        #pragma unroll
        for (int t = 0; t < 2; t++){
            float4 va0 = sa[2*t], va1 = sa[2*t+1];
            float4 vb0 = sb[2*t], vb1 = sb[2*t+1];
            sA[8*t+0]=va0.x; sA[8*t+1]=va0.y; sA[8*t+2]=va0.z; sA[8*t+3]=va0.w;
            sA[8*t+4]=va1.x; sA[8*t+5]=va1.y; sA[8*t+6]=va1.z; sA[8*t+7]=va1.w;
            sB[8*t+0]=vb0.x; sB[8*t+1]=vb0.y; sB[8*t+2]=vb0.z; sB[8*t+3]=vb0.w;
            sB[8*t+4]=vb1.x; sB[8*t+5]=vb1.y; sB[8*t+6]=vb1.z; sB[8*t+7]=vb1.w;
            dA[t] = make_uint4(h2u(__floats2half2_rn(va0.x,va0.y)),
                               h2u(__floats2half2_rn(va0.z,va0.w)),
                               h2u(__floats2half2_rn(va1.x,va1.y)),
                               h2u(__floats2half2_rn(va1.z,va1.w)));
            dB[t] = make_uint4(h2u(__floats2half2_rn(vb0.x,vb0.y)),
                               h2u(__floats2half2_rn(vb0.z,vb0.w)),
                               h2u(__floats2half2_rn(vb1.x,vb1.y)),
                               h2u(__floats2half2_rn(vb1.z,vb1.w)));
        }
    }

    // --- stationary half2 weight columns (lane = output channel) ---
    const float scale = 0.3535533905932738f;   // 1/sqrt(8)
    __half2 wqh[8], wkh[8], wvh[8];
    #pragma unroll
    for (int c = 0; c < 8; c++){
        wqh[c] = __floats2half2_rn(ia_wq [(2*c)*32 + lane]*scale, ia_wq [(2*c+1)*32 + lane]*scale);
        wkh[c] = __floats2half2_rn(ia_wkv[(2*c)*64 + lane],       ia_wkv[(2*c+1)*64 + lane]);
        wvh[c] = __floats2half2_rn(ia_wkv[(2*c)*64 + 32 + lane],  ia_wkv[(2*c+1)*64 + 32 + lane]);
    }
    const float bq = ia_bq[lane] * scale;
    const float bk = ia_bkv[lane];
    const float bv = ia_bkv[32 + lane];

    // ================= per-pair attention (full unroll: residual in regs) ==
    #pragma unroll
    for (int pp = 0; pp < 2; pp++){
        __syncwarp();
        // --- projection: 2 broadcast LDS.128/row, all HFMA2 ---
        #pragma unroll 4
        for (int t = 0; t < 32; t++){
            const uint4* rp = (const uint4*)SsH[w][pp][t];   // broadcast
            uint4 r0 = rp[0], r1 = rp[1];
            __half2 x0=u2h(r0.x), x1=u2h(r0.y), x2=u2h(r0.z), x3=u2h(r0.w);
            __half2 x4=u2h(r1.x), x5=u2h(r1.y), x6=u2h(r1.z), x7=u2h(r1.w);
            __half2 qa = __hmul2(x0,wqh[0]);
            qa=__hfma2(x1,wqh[1],qa); qa=__hfma2(x2,wqh[2],qa); qa=__hfma2(x3,wqh[3],qa);
            qa=__hfma2(x4,wqh[4],qa); qa=__hfma2(x5,wqh[5],qa); qa=__hfma2(x6,wqh[6],qa);
            qa=__hfma2(x7,wqh[7],qa);
            __half2 ka = __hmul2(x0,wkh[0]);
            ka=__hfma2(x1,wkh[1],ka); ka=__hfma2(x2,wkh[2],ka); ka=__hfma2(x3,wkh[3],ka);
            ka=__hfma2(x4,wkh[4],ka); ka=__hfma2(x5,wkh[5],ka); ka=__hfma2(x6,wkh[6],ka);
            ka=__hfma2(x7,wkh[7],ka);
            __half2 va = __hmul2(x0,wvh[0]);
            va=__hfma2(x1,wvh[1],va); va=__hfma2(x2,wvh[2],va); va=__hfma2(x3,wvh[3],va);
            va=__hfma2(x4,wvh[4],va); va=__hfma2(x5,wvh[5],va); va=__hfma2(x6,wvh[6],va);
            va=__hfma2(x7,wvh[7],va);
            QKV[w][0][t][lane] = __float2half_rn(__low2float(qa)+__high2float(qa)+bq);
            QKV[w][1][t][lane] = __float2half_rn(__low2float(ka)+__high2float(ka)+bk);
            QKV[w][2][t][lane] = __float2half_rn(__low2float(va)+__high2float(va)+bv);
        }
        __syncwarp();

        // --- 4-head attention (fp16), fp16 wo, half2 accumulation ---
        __half2 afth[8];
        #pragma unroll
        for (int j = 0; j < 8; j++) afth[j] = __float2half2_rn(0.f);

        #pragma unroll
        for (int n = 0; n < 4; n++){
            const uint4* qp = (const uint4*)&QKV[w][0][lane][n*8];
            uint4 qu = qp[0];
            __half2 q0 = u2h(qu.x), q1 = u2h(qu.y), q2 = u2h(qu.z), q3 = u2h(qu.w);
            __half2 o0 = __float2half2_rn(0.f), o1 = o0, o2 = o0, o3 = o0;
            float sum = 0.f;
            #pragma unroll 8
            for (int k = 0; k < 32; k++){
                uint4 ku = *(const uint4*)&QKV[w][1][k][n*8];   // broadcast, 1 wf
                __half2 sh = __hmul2(q0, u2h(ku.x));
                sh = __hfma2(q1, u2h(ku.y), sh);
                sh = __hfma2(q2, u2h(ku.z), sh);
                sh = __hfma2(q3, u2h(ku.w), sh);
                float s = __low2float(sh) + __high2float(sh);
                float e = __expf(s);        // no-max softmax: |score| << 1 here
                sum += e;
                __half2 e2 = __float2half2_rn(e);
                uint4 vu = *(const uint4*)&QKV[w][2][k][n*8];   // broadcast, 1 wf
                o0 = __hfma2(e2, u2h(vu.x), o0);
                o1 = __hfma2(e2, u2h(vu.y), o1);
                o2 = __hfma2(e2, u2h(vu.z), o2);
                o3 = __hfma2(e2, u2h(vu.w), o3);
            }
            const float inv = 1.0f / sum;
            float2 p0 = __half22float2(o0), p1 = __half22float2(o1);
            float2 p2 = __half22float2(o2), p3 = __half22float2(o3);
            float od[8] = {p0.x*inv, p0.y*inv, p1.x*inv, p1.y*inv,
                           p2.x*inv, p2.y*inv, p3.x*inv, p3.y*inv};
            #pragma unroll
            for (int d = 0; d < 8; d++){
                __half2 od2 = __float2half2_rn(od[d]);
                const uint4* wp = (const uint4*)(s_woh + (n*8+d)*16);  // 2 LDS.128
                uint4 wA = wp[0], wB = wp[1];
                afth[0] = __hfma2(od2, u2h(wA.x), afth[0]);
                afth[1] = __hfma2(od2, u2h(wA.y), afth[1]);
                afth[2] = __hfma2(od2, u2h(wA.z), afth[2]);
                afth[3] = __hfma2(od2, u2h(wA.w), afth[3]);
                afth[4] = __hfma2(od2, u2h(wB.x), afth[4]);
                afth[5] = __hfma2(od2, u2h(wB.y), afth[5]);
                afth[6] = __hfma2(od2, u2h(wB.z), afth[6]);
                afth[7] = __hfma2(od2, u2h(wB.w), afth[7]);
            }
        }

        // --- unpack (+bias), register-resident fp32 residual, LayerNorm ---
        float aft[16];
        #pragma unroll
        for (int j = 0; j < 8; j++){
            float2 u = __half22float2(afth[j]);
            aft[2*j]   = u.x + s_cst[2*j];
            aft[2*j+1] = u.y + s_cst[2*j+1];
        }
        #pragma unroll
        for (int f = 0; f < 16; f++) aft[f] += (pp ? sB[f] : sA[f]);

        float mean = 0.f;
        #pragma unroll
        for (int f = 0; f < 16; f++) mean += aft[f];
        mean *= 0.0625f;
        float var = 0.f;
        #pragma unroll
        for (int f = 0; f < 16; f++){ float d = aft[f]-mean; var = fmaf(d,d,var); }
        var *= 0.0625f;
        float rstd = rsqrtf(var + 1e-5f);
        #pragma unroll
        for (int f = 0; f < 16; f++)
            aft[f] = (aft[f]-mean)*rstd*s_cst[16+f] + s_cst[32+f];

        {
            float4* dst = (float4*)Sa[w][pp][lane];
            dst[0] = make_float4(aft[0],aft[1],aft[2],aft[3]);
            dst[1] = make_float4(aft[4],aft[5],aft[6],aft[7]);
            dst[2] = make_float4(aft[8],aft[9],aft[10],aft[11]);
            dst[3] = make_float4(aft[12],aft[13],aft[14],aft[15]);
        }
    }

    // Attention done for both warps; Sa complete; QKV becomes fp32 scratch E.
    __syncthreads();

    // ===== enc: warp w covers f-rows l in [16w, 16w+16) for ALL 4 pairs ====
    // (block pair k: warp k>>1, pp k&1)
    u64 acc0[4] = {0ull,0ull,0ull,0ull};
    u64 acc1[4] = {0ull,0ull,0ull,0ull};
    {
        const ulonglong2* iw = (const ulonglong2*)g_ilw4;
        #pragma unroll 4
        for (int ll = 0; ll < 16; ll++){
            const int l = (w<<4) + ll;
            const ulonglong2* wr = iw + (l*4)*32 + lane;      // coalesced LDG.128
            ulonglong2 w0 = wr[0], w1 = wr[32], w2 = wr[64], w3 = wr[96];
            #pragma unroll
            for (int k = 0; k < 4; k++){
                const ulonglong2* ap = (const ulonglong2*)Sa[k>>1][k&1][l];  // broadcast
                ulonglong2 a0=ap[0], a1=ap[1], a2=ap[2], a3=ap[3];
                acc0[k] = f2fma(a0.x,w0.x, f2fma(a0.y,w0.y, acc0[k]));
                acc1[k] = f2fma(a1.x,w1.x, f2fma(a1.y,w1.y, acc1[k]));
                acc0[k] = f2fma(a2.x,w2.x, f2fma(a2.y,w2.y, acc0[k]));
                acc1[k] = f2fma(a3.x,w3.x, f2fma(a3.y,w3.y, acc1[k]));
            }
        }
    }
    // partial enc -> encP[w][k], plus stash hprev for GRU
    float hpA = hprev[(size_t)pA*HD + lane];
    float hpB = hprev[(size_t)pB*HD + lane];
    #pragma unroll
    for (int k = 0; k < 4; k++)
        E[(w*4 + k)*32 + lane] = f2hsum(f2add(acc0[k], acc1[k]));
    E[256 + (2*w+0)*32 + lane] = hpA;
    E[256 + (2*w+1)*32 + lane] = hpB;
    __syncthreads();

    // finalize enc for own pairs (overwrite encP[0][k] slot with FINAL enc)
    {
        float bi = il_b[lane];
        float eA = E[(2*w+0)*32 + lane] + E[(4 + 2*w+0)*32 + lane] + bi;
        float eB = E[(2*w+1)*32 + lane] + E[(4 + 2*w+1)*32 + lane] + bi;
        __syncthreads();                       // partial reads done everywhere
        E[(2*w+0)*32 + lane] = eA;
        E[(2*w+1)*32 + lane] = eB;
    }
    __syncthreads();

    // ===== GRU: warp0 computes gi gates (enc side), warp1 gh gates (h side),
    //       each for ALL 4 pairs, reading only its half of the weights ======
    {
        u64 gacc[4][3];
        #pragma unroll
        for (int k = 0; k < 4; k++){ gacc[k][0]=0ull; gacc[k][1]=0ull; gacc[k][2]=0ull; }
        const float* abase = E + (w ? 256 : 0);       // enc rows or hp rows
        const ulonglong2* gw = (const ulonglong2*)g_gw4;
        #pragma unroll
        for (int c = 0; c < 8; c++){
            const ulonglong2* gbase = gw + (c*6 + w*3)*32 + lane;
            ulonglong2 wg0 = gbase[0], wg1 = gbase[32], wg2 = gbase[64];
            #pragma unroll
            for (int k = 0; k < 4; k++){
                ulonglong2 x = ((const ulonglong2*)(abase + k*32))[c];  // broadcast
                gacc[k][0] = f2fma(x.x, wg0.x, f2fma(x.y, wg0.y, gacc[k][0]));
                gacc[k][1] = f2fma(x.x, wg1.x, f2fma(x.y, wg1.y, gacc[k][1]));
                gacc[k][2] = f2fma(x.x, wg2.x, f2fma(x.y, wg2.y, gacc[k][2]));
            }
        }
        float* gout = E + (w ? 768 : 384);
        #pragma unroll
        for (int k = 0; k < 4; k++){
            gout[(k*3+0)*32 + lane] = f2hsum(gacc[k][0]);
            gout[(k*3+1)*32 + lane] = f2hsum(gacc[k][1]);
            gout[(k*3+2)*32 + lane] = f2hsum(gacc[k][2]);
        }
    }
    __syncthreads();

    // finalize GRU for own pairs
    float hnA, hnB;
    {
        float bir = gbih[lane], biz = gbih[32+lane], bin = gbih[64+lane];
        float bhr = gbhh[lane], bhz = gbhh[32+lane], bhn = gbhh[64+lane];
        #pragma unroll
        for (int pi = 0; pi < 2; pi++){
            const int k = 2*w + pi;
            float gi0 = E[384 + (k*3+0)*32 + lane];
            float gi1 = E[384 + (k*3+1)*32 + lane];
            float gi2 = E[384 + (k*3+2)*32 + lane];
            float gh0 = E[768 + (k*3+0)*32 + lane];
            float gh1 = E[768 + (k*3+1)*32 + lane];
            float gh2 = E[768 + (k*3+2)*32 + lane];
            float hp  = pi ? hpB : hpA;
            float r = sigm(gi0 + bir + gh0 + bhr);
            float z = sigm(gi1 + biz + gh1 + bhz);
            float n = tanhf(gi2 + bin + r*(gh2 + bhn));
            float hn = (1.0f - z)*n + z*hp;
            if (pi) hnB = hn; else hnA = hn;
        }
    }
    out_h[(size_t)pA*HD + lane] = hnA;
    out_h[(size_t)pB*HD + lane] = hnB;

    // ===== message embedding + generator (per-warp, quad weights) ==========
    float* st = E + 1152 + w*64;
    __syncwarp();
    st[lane] = hnA;  st[32+lane] = hnB;
    __syncwarp();
    u64 mA=0ull, mB=0ull;
    {
        const ulonglong2* p0 = (const ulonglong2*)st;
        const ulonglong2* p1 = (const ulonglong2*)(st+32);
        const ulonglong2* wm = (const ulonglong2*)g_msw4;
        #pragma unroll
        for (int c = 0; c < 8; c++){
            ulonglong2 hA = p0[c], hB = p1[c];       // broadcast
            ulonglong2 ww = wm[c*32 + lane];
            mA = f2fma(hA.x,ww.x, f2fma(hA.y,ww.y, mA));
            mB = f2fma(hB.x,ww.x, f2fma(hB.y,ww.y, mB));
        }
    }
    float mbA = fmaxf(f2hsum(mA) + ms_b[lane], 0.f);
    float mbB = fmaxf(f2hsum(mB) + ms_b[lane], 0.f);

    __syncwarp();
    st[lane] = mbA;  st[32+lane] = mbB;
    __syncwarp();
    u64 gA=0ull, gB=0ull;
    {
        const ulonglong2* p0 = (const ulonglong2*)st;
        const ulonglong2* p1 = (const ulonglong2*)(st+32);
        const ulonglong2* wg = (const ulonglong2*)g_mgw4 + (size_t)a*8*32 + lane;
        #pragma unroll
        for (int c = 0; c < 8; c++){
            ulonglong2 mAx = p0[c], mBx = p1[c];     // broadcast
            ulonglong2 ww = wg[c*32];
            gA = f2fma(mAx.x,ww.x, f2fma(mAx.y,ww.y, gA));
            gB = f2fma(mBx.x,ww.x, f2fma(mBx.y,ww.y, gB));
        }
    }
    g_msg[(size_t)pA*MD + lane] = f2hsum(gA) + mg_b[a*32 + lane];
    g_msg[(size_t)pB*MD + lane] = f2hsum(gB) + mg_b[a*32 + lane];
}

// ---------------------------------------------------------------------------
// Kernel 2: deterministic per-batch mean over agents; broadcast to out_mm.
// ---------------------------------------------------------------------------
__global__ void k2_kernel(float* __restrict__ out_mm)
{
    const int b = blockIdx.x;
    const int m = threadIdx.x;                    // 32 threads
    const float* base = g_msg + (size_t)b*NAG*MD + m;
    float sum = 0.f;
    #pragma unroll 8
    for (int a = 0; a < NAG; a++) sum += base[a*MD];
    float mean = sum * (1.0f/64.0f);
    g_mean[b*MD + m] = mean;
    float* ob = out_mm + (size_t)b*NAG*MD + m;
    #pragma unroll 8
    for (int a = 0; a < NAG; a++) ob[a*MD] = mean;
}

// ---------------------------------------------------------------------------
// Kernel 3: comm attention (seqlen-1 softmax == 1 -> only V path), LN2,
// q-head. 1 warp per TWO pairs (p, p+32768; same agent). Quad-packed
// weight LDG.128 + stash + packed broadcast f2fma.  (unchanged from r15)
// ---------------------------------------------------------------------------
__global__ __launch_bounds__(128) void k3_kernel(
    const float* __restrict__ hbuf,
    const float* __restrict__ ma_bkv, const float* __restrict__ ma_bo,
    const float* __restrict__ ln2_g,  const float* __restrict__ ln2_b,
    const float* __restrict__ qs_b,   const float* __restrict__ ah_b,
    float* __restrict__ out_q)
{
    __shared__ __align__(16) float sB[4][4][32];   // per-warp stash rows

    const int tid  = threadIdx.x;
    const int w    = tid >> 5;
    const int lane = tid & 31;
    const int idx  = blockIdx.x * 4 + w;          // 0..32767
    const int p0   = idx;
    const int p1   = idx + NPAIR/2;               // same agent
    const int b0   = p0 >> 6;
    const int b1   = p1 >> 6;
    const int a    = p0 & (NAG - 1);

    float h0 = hbuf[(size_t)p0*HD + lane];
    float h1 = hbuf[(size_t)p1*HD + lane];
    float m0 = g_mean[b0*MD + lane];
    float m1 = g_mean[b1*MD + lane];

    sB[w][0][lane] = m0;  sB[w][1][lane] = m1;
    __syncwarp();

    u64 V0a = 0ull, V1a = 0ull;
    {
        const ulonglong2* pm0 = (const ulonglong2*)sB[w][0];
        const ulonglong2* pm1 = (const ulonglong2*)sB[w][1];
        const ulonglong2* wv  = (const ulonglong2*)g_mav4 + lane;
        #pragma unroll
        for (int c = 0; c < 8; c++){
            ulonglong2 mm0 = pm0[c], mm1 = pm1[c];   // broadcast
            ulonglong2 ww  = wv[c*32];               // coalesced LDG.128
            V0a = f2fma(mm0.x, ww.x, f2fma(mm0.y, ww.y, V0a));
            V1a = f2fma(mm1.x, ww.x, f2fma(mm1.y, ww.y, V1a));
        }
    }
    float V0 = f2hsum(V0a) + ma_bkv[32 + lane];
    float V1 = f2hsum(V1a) + ma_bkv[32 + lane];

    __syncwarp();
    sB[w][0][lane] = V0;  sB[w][1][lane] = V1;
    __syncwarp();

    u64 A0a = 0ull, A1a = 0ull;
    {
        const ulonglong2* pv0 = (const ulonglong2*)sB[w][0];
        const ulonglong2* pv1 = (const ulonglong2*)sB[w][1];
        const ulonglong2* wo  = (const ulonglong2*)g_mao4 + lane;
        #pragma unroll
        for (int c = 0; c < 8; c++){
            ulonglong2 vv0 = pv0[c], vv1 = pv1[c];
            ulonglong2 ww  = wo[c*32];
            A0a = f2fma(vv0.x, ww.x, f2fma(vv0.y, ww.y, A0a));
            A1a = f2fma(vv1.x, ww.x, f2fma(vv1.y, ww.y, A1a));
        }
    }
    float af0 = f2hsum(A0a) + ma_bo[lane];
    float af1 = f2hsum(A1a) + ma_bo[lane];

    float g2 = ln2_g[lane], bb2 = ln2_b[lane];
    float x0 = h0 + af0, x1 = h1 + af1;
    float t0 = x0, t1 = x1;
    #pragma unroll
    for (int off = 16; off > 0; off >>= 1){
        t0 += __shfl_xor_sync(0xffffffffu, t0, off);
        t1 += __shfl_xor_sync(0xffffffffu, t1, off);
    }
    float mu0 = t0 * (1.0f/32.0f), mu1 = t1 * (1.0f/32.0f);
    float d0 = x0 - mu0, d1 = x1 - mu1;
    float v0 = d0*d0, v1 = d1*d1;
    #pragma unroll
    for (int off = 16; off > 0; off >>= 1){
        v0 += __shfl_xor_sync(0xffffffffu, v0, off);
        v1 += __shfl_xor_sync(0xffffffffu, v1, off);
    }
    float an0 = d0 * rsqrtf(v0*(1.0f/32.0f) + 1e-5f) * g2 + bb2;
    float an1 = d1 * rsqrtf(v1*(1.0f/32.0f) + 1e-5f) * g2 + bb2;

    __syncwarp();
    sB[w][0][lane] = h0;  sB[w][1][lane] = an0;
    sB[w][2][lane] = h1;  sB[w][3][lane] = an1;
    __syncwarp();

    u64 qe0a = 0ull, qe1a = 0ull;
    {
        const ulonglong2* ph0 = (const ulonglong2*)sB[w][0];
        const ulonglong2* pa0 = (const ulonglong2*)sB[w][1];
        const ulonglong2* ph1 = (const ulonglong2*)sB[w][2];
        const ulonglong2* pa1 = (const ulonglong2*)sB[w][3];
        const ulonglong2* wq  = (const ulonglong2*)g_qsw4 + lane;
        #pragma unroll
        for (int c = 0; c < 8; c++){
            ulonglong2 hh0 = ph0[c], aa0 = pa0[c], hh1 = ph1[c], aa1 = pa1[c];
            ulonglong2 wh = wq[c*32];          // rows 4c..4c+3 (h half)
            ulonglong2 wa = wq[(8+c)*32];      // rows 32+4c..  (an half)
            qe0a = f2fma(hh0.x, wh.x, f2fma(hh0.y, wh.y,
                    f2fma(aa0.x, wa.x, f2fma(aa0.y, wa.y, qe0a))));
            qe1a = f2fma(hh1.x, wh.x, f2fma(hh1.y, wh.y,
                    f2fma(aa1.x, wa.x, f2fma(aa1.y, wa.y, qe1a))));
        }
    }
    float qe0 = fmaxf(f2hsum(qe0a) + qs_b[lane], 0.f);
    float qe1 = fmaxf(f2hsum(qe1a) + qs_b[lane], 0.f);

    __syncwarp();
    sB[w][0][lane] = qe0;  sB[w][1][lane] = qe1;
    __syncwarp();

    u64 qa0a = 0ull, qa1a = 0ull;
    {
        const ulonglong2* pq0 = (const ulonglong2*)sB[w][0];
        const ulonglong2* pq1 = (const ulonglong2*)sB[w][1];
        const ulonglong2* wa  = (const ulonglong2*)g_ahw4 + (size_t)a*8*16 + (lane & 15);
        #pragma unroll
        for (int c = 0; c < 8; c++){
            ulonglong2 qq0 = pq0[c], qq1 = pq1[c];
            ulonglong2 ww  = wa[c*16];
            qa0a = f2fma(qq0.x, ww.x, f2fma(qq0.y, ww.y, qa0a));
            qa1a = f2fma(qq1.x, ww.x, f2fma(qq1.y, ww.y, qa1a));
        }
    }
    if (lane < 16){
        out_q[(size_t)p0*AD + lane] = f2hsum(qa0a) + ah_b[a*16 + lane];
        out_q[(size_t)p1*AD + lane] = f2hsum(qa1a) + ah_b[a*16 + lane];
    }
}

// ---------------------------------------------------------------------------
extern "C" void kernel_launch(void* const* d_in, const int* in_sizes, int n_in,
                              void* d_out, int out_size)
{
    const float* states = (const float*)d_in[0];
    const float* hidden = (const float*)d_in[1];
    const float* ia_wq  = (const float*)d_in[2];
    const float* ia_bq  = (const float*)d_in[3];
    const float* ia_wkv = (const float*)d_in[4];
    const float* ia_bkv = (const float*)d_in[5];
    const float* ia_wo  = (const float*)d_in[6];
    const float* ia_bo  = (const float*)d_in[7];
    const float* ln1_g  = (const float*)d_in[8];
    const float* ln1_b  = (const float*)d_in[9];
    const float* il_w   = (const float*)d_in[10];
    const float* il_b   = (const float*)d_in[11];
    const float* gwih   = (const float*)d_in[12];
    const float* gwhh   = (const float*)d_in[13];
    const float* gbih   = (const float*)d_in[14];
    const float* gbhh   = (const float*)d_in[15];
    const float* ms_w   = (const float*)d_in[16];
    const float* ms_b   = (const float*)d_in[17];
    const float* mg_w   = (const float*)d_in[18];
    const float* mg_b   = (const float*)d_in[19];
    // d_in[20] = ma_wq, d_in[21] = ma_bq: eliminated (seqlen-1 softmax == 1)
    const float* ma_wkv = (const float*)d_in[22];
    const float* ma_bkv = (const float*)d_in[23];
    const float* ma_wo  = (const float*)d_in[24];
    const float* ma_bo  = (const float*)d_in[25];
    const float* ln2_g  = (const float*)d_in[26];
    const float* ln2_b  = (const float*)d_in[27];
    const float* qs_w   = (const float*)d_in[28];
    const float* qs_b   = (const float*)d_in[29];
    const float* ah_w   = (const float*)d_in[30];
    const float* ah_b   = (const float*)d_in[31];

    float* out    = (float*)d_out;
    float* out_q  = out;                                        // [NPAIR,16]
    float* out_h  = out + (size_t)NPAIR*AD;                     // [NPAIR,32]
    float* out_mm = out + (size_t)NPAIR*AD + (size_t)NPAIR*HD;  // [NPAIR,32]

    setup_kernel<<<64, 256>>>(il_w, gwih, gwhh, ms_w, mg_w,
                              qs_w, ma_wkv, ma_wo, ah_w);
    k1_kernel<<<NPAIR/4, 64>>>(states, hidden, ia_wq, ia_bq, ia_wkv, ia_bkv,
                               ia_wo, ia_bo, ln1_g, ln1_b, il_b,
                               gbih, gbhh, ms_b, mg_b, out_h);
    k2_kernel<<<BSZ, 32>>>(out_mm);
    k3_kernel<<<NPAIR/8, 128>>>(out_h, ma_bkv, ma_bo,
                                ln2_g, ln2_b, qs_b, ah_b, out_q);
}